// round 1
// baseline (speedup 1.0000x reference)
#include <cuda_runtime.h>

#define N_BATCH 2
#define SEQ     2048
#define EMB     1024
#define NHEAD   16
#define HDIM    64
#define MTOT    (N_BATCH*SEQ)   // 4096

// Scratch (allocation-free rule: __device__ globals)
__device__ float g_q[(size_t)MTOT*EMB];
__device__ float g_k[(size_t)MTOT*EMB];
__device__ float g_v[(size_t)MTOT*EMB];
__device__ float g_ao[(size_t)MTOT*EMB];

// ---------------------------------------------------------------------------
// GEMM: C[M,N] = alpha * (A[M,K] @ B[N,K]^T + bias[N])
// BM=128, BN=64, BK=16, 256 threads, 8x4 micro-tile per thread.
// M,N,K assumed multiples of 128/64/16 respectively (true here: 4096/1024/1024)
// ---------------------------------------------------------------------------
__global__ __launch_bounds__(256) void gemm_nt_bias(
    const float* __restrict__ A, const float* __restrict__ B,
    const float* __restrict__ bias, float* __restrict__ C,
    int M, int N, int K, float alpha)
{
    __shared__ float As[16][132];   // [k][m], padded stride 132 (16B aligned)
    __shared__ float Bs[16][68];    // [k][n], padded stride 68

    const int tid = threadIdx.x;
    const int tx = tid & 15;        // n direction (16 * 4 = 64)
    const int ty = tid >> 4;        // m direction (16 * 8 = 128)
    const int m0 = blockIdx.y * 128;
    const int n0 = blockIdx.x * 64;

    float acc[8][4];
    #pragma unroll
    for (int i = 0; i < 8; i++)
        #pragma unroll
        for (int j = 0; j < 4; j++) acc[i][j] = 0.f;

    const int lrow = tid >> 2;      // 0..63
    const int lc4  = tid & 3;       // which float4 along K

    for (int k0 = 0; k0 < K; k0 += 16) {
        // Load A tile (128x16) transposed into As: 2 float4 per thread
        #pragma unroll
        for (int r = 0; r < 2; r++) {
            int row = lrow + r * 64;
            float4 va = *reinterpret_cast<const float4*>(
                &A[(size_t)(m0 + row) * K + k0 + lc4 * 4]);
            As[lc4*4+0][row] = va.x;
            As[lc4*4+1][row] = va.y;
            As[lc4*4+2][row] = va.z;
            As[lc4*4+3][row] = va.w;
        }
        // Load B tile (64x16) transposed into Bs: 1 float4 per thread
        {
            float4 vb = *reinterpret_cast<const float4*>(
                &B[(size_t)(n0 + lrow) * K + k0 + lc4 * 4]);
            Bs[lc4*4+0][lrow] = vb.x;
            Bs[lc4*4+1][lrow] = vb.y;
            Bs[lc4*4+2][lrow] = vb.z;
            Bs[lc4*4+3][lrow] = vb.w;
        }
        __syncthreads();

        #pragma unroll
        for (int kk = 0; kk < 16; kk++) {
            float4 a0 = *reinterpret_cast<const float4*>(&As[kk][ty*8]);
            float4 a1 = *reinterpret_cast<const float4*>(&As[kk][ty*8+4]);
            float4 b0 = *reinterpret_cast<const float4*>(&Bs[kk][tx*4]);
            float a[8] = {a0.x,a0.y,a0.z,a0.w,a1.x,a1.y,a1.z,a1.w};
            float b[4] = {b0.x,b0.y,b0.z,b0.w};
            #pragma unroll
            for (int i = 0; i < 8; i++)
                #pragma unroll
                for (int j = 0; j < 4; j++)
                    acc[i][j] = fmaf(a[i], b[j], acc[i][j]);
        }
        __syncthreads();
    }

    // Epilogue: bias + alpha, float4 stores
    float4 bb = *reinterpret_cast<const float4*>(&bias[n0 + tx*4]);
    #pragma unroll
    for (int i = 0; i < 8; i++) {
        float4 o;
        o.x = alpha * (acc[i][0] + bb.x);
        o.y = alpha * (acc[i][1] + bb.y);
        o.z = alpha * (acc[i][2] + bb.z);
        o.w = alpha * (acc[i][3] + bb.w);
        *reinterpret_cast<float4*>(&C[(size_t)(m0 + ty*8 + i) * N + n0 + tx*4]) = o;
    }
}

// ---------------------------------------------------------------------------
// Flash attention, causal, fp32. Per block: one (batch, head, 64-query tile).
// Key tiles of 32, only tiles touching/below the diagonal are processed.
// Q is pre-scaled by 1/sqrt(E) (folded into the Q projection GEMM's alpha).
// 256 threads: ty=tid/16 (q rows, 4 each), tx=tid%16 (2 S-cols / 4 O-cols).
// ---------------------------------------------------------------------------
#define BQ  64
#define BKT 32

__global__ __launch_bounds__(256) void attn_kernel(
    const float* __restrict__ Q, const float* __restrict__ K,
    const float* __restrict__ V, float* __restrict__ O)
{
    __shared__ float Qs[BQ][HDIM + 4];     // 64 x 68
    __shared__ float Kt[HDIM][BKT + 4];    // 64 x 36  (d-major, transposed)
    __shared__ float Vs[BKT][HDIM + 4];    // 32 x 68
    __shared__ float Ps[BQ][BKT + 1];      // 64 x 33

    const int tid = threadIdx.x;
    const int tx = tid & 15;
    const int ty = tid >> 4;
    const int q0 = blockIdx.x * BQ;
    const int h  = blockIdx.y;
    const int nb = blockIdx.z;

    const float* qbase = Q + (size_t)nb * SEQ * EMB + h * HDIM;
    const float* kbase = K + (size_t)nb * SEQ * EMB + h * HDIM;
    const float* vbase = V + (size_t)nb * SEQ * EMB + h * HDIM;

    // Load Q tile: 64 rows x 64 cols = 1024 float4, 4 per thread
    #pragma unroll
    for (int i = 0; i < 4; i++) {
        int idx = tid + i * 256;
        int r = idx >> 4, c4 = idx & 15;
        *reinterpret_cast<float4*>(&Qs[r][c4*4]) =
            *reinterpret_cast<const float4*>(&qbase[(size_t)(q0 + r) * EMB + c4*4]);
    }

    float m[4], l[4], acc[4][4];
    #pragma unroll
    for (int i = 0; i < 4; i++) {
        m[i] = -1e30f; l[i] = 0.f;
        #pragma unroll
        for (int j = 0; j < 4; j++) acc[i][j] = 0.f;
    }

    const int nkt = (q0 + BQ) / BKT;   // causal: only tiles with kb < q0+64
    for (int kt = 0; kt < nkt; kt++) {
        const int kb = kt * BKT;
        __syncthreads();   // protect Kt/Vs (prev stage-2) and Qs (first iter)

        // Load K tile transposed: 32x64 floats, 8 per thread
        #pragma unroll
        for (int i = 0; i < 8; i++) {
            int idx = tid + i * 256;
            int kr = idx >> 6, d = idx & 63;
            Kt[d][kr] = kbase[(size_t)(kb + kr) * EMB + d];
        }
        // Load V tile: 32x64 = 512 float4, 2 per thread
        #pragma unroll
        for (int i = 0; i < 2; i++) {
            int idx = tid + i * 256;
            int r = idx >> 4, c4 = idx & 15;
            *reinterpret_cast<float4*>(&Vs[r][c4*4]) =
                *reinterpret_cast<const float4*>(&vbase[(size_t)(kb + r) * EMB + c4*4]);
        }
        __syncthreads();

        // Stage 1: S[4][2] = Qs . Kt   (d unrolled by 4, Q reads as float4)
        float S[4][2];
        #pragma unroll
        for (int i = 0; i < 4; i++) { S[i][0] = 0.f; S[i][1] = 0.f; }
        #pragma unroll
        for (int dc = 0; dc < HDIM/4; dc++) {
            float4 qv[4];
            #pragma unroll
            for (int i = 0; i < 4; i++)
                qv[i] = *reinterpret_cast<const float4*>(&Qs[ty*4+i][dc*4]);
            #pragma unroll
            for (int e = 0; e < 4; e++) {
                float k0v = Kt[dc*4+e][tx*2+0];
                float k1v = Kt[dc*4+e][tx*2+1];
                #pragma unroll
                for (int i = 0; i < 4; i++) {
                    float qe = (e==0) ? qv[i].x : (e==1) ? qv[i].y : (e==2) ? qv[i].z : qv[i].w;
                    S[i][0] = fmaf(qe, k0v, S[i][0]);
                    S[i][1] = fmaf(qe, k1v, S[i][1]);
                }
            }
        }

        // Causal mask
        #pragma unroll
        for (int i = 0; i < 4; i++) {
            int gq = q0 + ty*4 + i;
            #pragma unroll
            for (int j = 0; j < 2; j++) {
                int gk = kb + tx*2 + j;
                if (gk > gq) S[i][j] = -1e30f;
            }
        }

        // Online softmax (row reductions over tx: low 4 lane bits)
        #pragma unroll
        for (int i = 0; i < 4; i++) {
            float mt = fmaxf(S[i][0], S[i][1]);
            #pragma unroll
            for (int off = 1; off < 16; off <<= 1)
                mt = fmaxf(mt, __shfl_xor_sync(0xffffffffu, mt, off));
            float mn = fmaxf(m[i], mt);
            float cor = __expf(m[i] - mn);
            m[i] = mn;
            float p0 = __expf(S[i][0] - mn);
            float p1 = __expf(S[i][1] - mn);
            float ls = p0 + p1;
            #pragma unroll
            for (int off = 1; off < 16; off <<= 1)
                ls += __shfl_xor_sync(0xffffffffu, ls, off);
            l[i] = l[i] * cor + ls;
            #pragma unroll
            for (int j = 0; j < 4; j++) acc[i][j] *= cor;
            Ps[ty*4+i][tx*2+0] = p0;
            Ps[ty*4+i][tx*2+1] = p1;
        }
        __syncthreads();

        // Stage 2: acc += Ps . Vs
        #pragma unroll
        for (int kk = 0; kk < BKT; kk++) {
            float p[4];
            #pragma unroll
            for (int i = 0; i < 4; i++) p[i] = Ps[ty*4+i][kk];
            float4 vv = *reinterpret_cast<const float4*>(&Vs[kk][tx*4]);
            #pragma unroll
            for (int i = 0; i < 4; i++) {
                acc[i][0] = fmaf(p[i], vv.x, acc[i][0]);
                acc[i][1] = fmaf(p[i], vv.y, acc[i][1]);
                acc[i][2] = fmaf(p[i], vv.z, acc[i][2]);
                acc[i][3] = fmaf(p[i], vv.w, acc[i][3]);
            }
        }
    }

    // Epilogue: normalize and write [n, q, h*64 + d]
    #pragma unroll
    for (int i = 0; i < 4; i++) {
        float inv = 1.f / l[i];
        float4 o;
        o.x = acc[i][0] * inv;
        o.y = acc[i][1] * inv;
        o.z = acc[i][2] * inv;
        o.w = acc[i][3] * inv;
        *reinterpret_cast<float4*>(
            &O[((size_t)nb * SEQ + q0 + ty*4 + i) * EMB + h * HDIM + tx*4]) = o;
    }
}

// ---------------------------------------------------------------------------
// Launch: 3 projection GEMMs -> attention -> output GEMM
// Inputs: 0 values, 1 keys, 2 query, 3 mask(unused), 4 Wv, 5 bv, 6 Wk, 7 bk,
//         8 Wq, 9 bq, 10 Wo, 11 bo
// ---------------------------------------------------------------------------
extern "C" void kernel_launch(void* const* d_in, const int* in_sizes, int n_in,
                              void* d_out, int out_size)
{
    const float* values = (const float*)d_in[0];
    const float* keys   = (const float*)d_in[1];
    const float* query  = (const float*)d_in[2];
    const float* Wv = (const float*)d_in[4];
    const float* bv = (const float*)d_in[5];
    const float* Wk = (const float*)d_in[6];
    const float* bk = (const float*)d_in[7];
    const float* Wq = (const float*)d_in[8];
    const float* bq = (const float*)d_in[9];
    const float* Wo = (const float*)d_in[10];
    const float* bo = (const float*)d_in[11];
    float* out = (float*)d_out;

    float *pq, *pk, *pv, *pa;
    cudaGetSymbolAddress((void**)&pq, g_q);
    cudaGetSymbolAddress((void**)&pk, g_k);
    cudaGetSymbolAddress((void**)&pv, g_v);
    cudaGetSymbolAddress((void**)&pa, g_ao);

    dim3 gproj(EMB / 64, MTOT / 128);   // 16 x 32 = 512 blocks
    // Q projection: fold softmax scale 1/sqrt(1024) = 1/32 into alpha
    gemm_nt_bias<<<gproj, 256>>>(query,  Wq, bq, pq, MTOT, EMB, EMB, 0.03125f);
    gemm_nt_bias<<<gproj, 256>>>(keys,   Wk, bk, pk, MTOT, EMB, EMB, 1.0f);
    gemm_nt_bias<<<gproj, 256>>>(values, Wv, bv, pv, MTOT, EMB, EMB, 1.0f);

    dim3 gattn(SEQ / BQ, NHEAD, N_BATCH);  // 32 x 16 x 2 = 1024 blocks
    attn_kernel<<<gattn, 256>>>(pq, pk, pv, pa);

    gemm_nt_bias<<<gproj, 256>>>(pa, Wo, bo, out, MTOT, EMB, EMB, 1.0f);
}

// round 2
// speedup vs baseline: 1.1200x; 1.1200x over previous
#include <cuda_runtime.h>

#define N_BATCH 2
#define SEQ     2048
#define EMB     1024
#define NHEAD   16
#define HDIM    64
#define MTOT    (N_BATCH*SEQ)   // 4096

// Scratch (allocation-free rule: __device__ globals)
__device__ float g_q[(size_t)MTOT*EMB];
__device__ float g_k[(size_t)MTOT*EMB];
__device__ float g_v[(size_t)MTOT*EMB];
__device__ float g_ao[(size_t)MTOT*EMB];

// ---------------------------------------------------------------------------
// GEMM: C[M,N] = alpha * (A[M,K] @ B[N,K]^T + bias[N])
// BM=128, BN=128, BK=16, 256 threads, 8x8 micro-tile, double-buffered smem.
// M,N multiples of 128; K multiple of 16. (4096 / 1024 / 1024 here.)
// ---------------------------------------------------------------------------
__global__ __launch_bounds__(256) void gemm_nt_bias(
    const float* __restrict__ A, const float* __restrict__ B,
    const float* __restrict__ bias, float* __restrict__ C,
    int M, int N, int K, float alpha)
{
    __shared__ float As[2][16][132];   // [buf][k][m]
    __shared__ float Bs[2][16][132];   // [buf][k][n]

    const int tid = threadIdx.x;
    const int tx = tid & 15;           // n: 16 * 8 = 128
    const int ty = tid >> 4;           // m: 16 * 8 = 128
    const int m0 = blockIdx.y * 128;
    const int n0 = blockIdx.x * 128;

    const int lr  = tid >> 2;          // 0..63
    const int lc4 = tid & 3;           // float4 index along K

    float acc[8][8];
    #pragma unroll
    for (int i = 0; i < 8; i++)
        #pragma unroll
        for (int j = 0; j < 8; j++) acc[i][j] = 0.f;

    const float* Abase = A + (size_t)m0 * K + lc4 * 4;
    const float* Bbase = B + (size_t)n0 * K + lc4 * 4;

    // preload chunk 0 into buffer 0
    {
        float4 a0 = *reinterpret_cast<const float4*>(&Abase[(size_t)lr * K]);
        float4 a1 = *reinterpret_cast<const float4*>(&Abase[(size_t)(lr + 64) * K]);
        float4 b0 = *reinterpret_cast<const float4*>(&Bbase[(size_t)lr * K]);
        float4 b1 = *reinterpret_cast<const float4*>(&Bbase[(size_t)(lr + 64) * K]);
        As[0][lc4*4+0][lr] = a0.x; As[0][lc4*4+1][lr] = a0.y;
        As[0][lc4*4+2][lr] = a0.z; As[0][lc4*4+3][lr] = a0.w;
        As[0][lc4*4+0][lr+64] = a1.x; As[0][lc4*4+1][lr+64] = a1.y;
        As[0][lc4*4+2][lr+64] = a1.z; As[0][lc4*4+3][lr+64] = a1.w;
        Bs[0][lc4*4+0][lr] = b0.x; Bs[0][lc4*4+1][lr] = b0.y;
        Bs[0][lc4*4+2][lr] = b0.z; Bs[0][lc4*4+3][lr] = b0.w;
        Bs[0][lc4*4+0][lr+64] = b1.x; Bs[0][lc4*4+1][lr+64] = b1.y;
        Bs[0][lc4*4+2][lr+64] = b1.z; Bs[0][lc4*4+3][lr+64] = b1.w;
    }
    __syncthreads();

    const int nk = K / 16;
    for (int kc = 0; kc < nk; kc++) {
        const int buf = kc & 1;
        float4 na0, na1, nb0, nb1;
        const bool more = (kc + 1 < nk);
        if (more) {
            int koff = (kc + 1) * 16;
            na0 = *reinterpret_cast<const float4*>(&Abase[(size_t)lr * K + koff]);
            na1 = *reinterpret_cast<const float4*>(&Abase[(size_t)(lr + 64) * K + koff]);
            nb0 = *reinterpret_cast<const float4*>(&Bbase[(size_t)lr * K + koff]);
            nb1 = *reinterpret_cast<const float4*>(&Bbase[(size_t)(lr + 64) * K + koff]);
        }

        #pragma unroll
        for (int kk = 0; kk < 16; kk++) {
            float4 av0 = *reinterpret_cast<const float4*>(&As[buf][kk][ty*8]);
            float4 av1 = *reinterpret_cast<const float4*>(&As[buf][kk][ty*8+4]);
            float4 bv0 = *reinterpret_cast<const float4*>(&Bs[buf][kk][tx*8]);
            float4 bv1 = *reinterpret_cast<const float4*>(&Bs[buf][kk][tx*8+4]);
            float a[8] = {av0.x,av0.y,av0.z,av0.w,av1.x,av1.y,av1.z,av1.w};
            float b[8] = {bv0.x,bv0.y,bv0.z,bv0.w,bv1.x,bv1.y,bv1.z,bv1.w};
            #pragma unroll
            for (int i = 0; i < 8; i++)
                #pragma unroll
                for (int j = 0; j < 8; j++)
                    acc[i][j] = fmaf(a[i], b[j], acc[i][j]);
        }

        if (more) {
            const int nb_ = buf ^ 1;
            As[nb_][lc4*4+0][lr] = na0.x; As[nb_][lc4*4+1][lr] = na0.y;
            As[nb_][lc4*4+2][lr] = na0.z; As[nb_][lc4*4+3][lr] = na0.w;
            As[nb_][lc4*4+0][lr+64] = na1.x; As[nb_][lc4*4+1][lr+64] = na1.y;
            As[nb_][lc4*4+2][lr+64] = na1.z; As[nb_][lc4*4+3][lr+64] = na1.w;
            Bs[nb_][lc4*4+0][lr] = nb0.x; Bs[nb_][lc4*4+1][lr] = nb0.y;
            Bs[nb_][lc4*4+2][lr] = nb0.z; Bs[nb_][lc4*4+3][lr] = nb0.w;
            Bs[nb_][lc4*4+0][lr+64] = nb1.x; Bs[nb_][lc4*4+1][lr+64] = nb1.y;
            Bs[nb_][lc4*4+2][lr+64] = nb1.z; Bs[nb_][lc4*4+3][lr+64] = nb1.w;
        }
        __syncthreads();
    }

    // Epilogue: bias + alpha
    float4 bb0 = *reinterpret_cast<const float4*>(&bias[n0 + tx*8]);
    float4 bb1 = *reinterpret_cast<const float4*>(&bias[n0 + tx*8 + 4]);
    float bv[8] = {bb0.x,bb0.y,bb0.z,bb0.w,bb1.x,bb1.y,bb1.z,bb1.w};
    #pragma unroll
    for (int i = 0; i < 8; i++) {
        float* crow = &C[(size_t)(m0 + ty*8 + i) * N + n0 + tx*8];
        float4 o0, o1;
        o0.x = alpha*(acc[i][0]+bv[0]); o0.y = alpha*(acc[i][1]+bv[1]);
        o0.z = alpha*(acc[i][2]+bv[2]); o0.w = alpha*(acc[i][3]+bv[3]);
        o1.x = alpha*(acc[i][4]+bv[4]); o1.y = alpha*(acc[i][5]+bv[5]);
        o1.z = alpha*(acc[i][6]+bv[6]); o1.w = alpha*(acc[i][7]+bv[7]);
        *reinterpret_cast<float4*>(crow)     = o0;
        *reinterpret_cast<float4*>(crow + 4) = o1;
    }
}

// ---------------------------------------------------------------------------
// Flash attention, causal, fp32. BQ=64, BKT=64.
// Q and K kept d-major in smem so QK^T reads are pure float4.
// P stored [q][k] (float4 writes, broadcast scalar reads), reusing K buffer.
// 256 threads: ty=tid/16 (4 q rows each), tx=tid%16 (4 k cols / 4 d cols).
// Dynamic smem: 3 * 64 * 68 * 4 = 52224 bytes.
// ---------------------------------------------------------------------------
#define BQ  64
#define BKT 64
#define ATTN_SMEM (3 * 64 * 68 * 4)

__global__ __launch_bounds__(256) void attn_kernel(
    const float* __restrict__ Q, const float* __restrict__ K,
    const float* __restrict__ V, float* __restrict__ O)
{
    extern __shared__ float sm[];
    float (*Qt)[68] = reinterpret_cast<float(*)[68]>(sm);              // [d][q]
    float (*KP)[68] = reinterpret_cast<float(*)[68]>(sm + 64*68);      // Kt [d][k] / Ps [q][k]
    float (*Vs)[68] = reinterpret_cast<float(*)[68]>(sm + 2*64*68);    // [k][d]

    const int tid = threadIdx.x;
    const int tx = tid & 15;
    const int ty = tid >> 4;
    const int q0 = blockIdx.x * BQ;
    const int h  = blockIdx.y;
    const int nb = blockIdx.z;

    const float* qbase = Q + (size_t)nb * SEQ * EMB + h * HDIM;
    const float* kbase = K + (size_t)nb * SEQ * EMB + h * HDIM;
    const float* vbase = V + (size_t)nb * SEQ * EMB + h * HDIM;

    // Load Q tile transposed into Qt[d][q]: lane-per-row so scatter stores are
    // conflict-free (consecutive lanes -> consecutive q at same d).
    {
        const int r = tid & 63;
        const int c4b = tid >> 6;  // 0..3
        #pragma unroll
        for (int i = 0; i < 4; i++) {
            int c4 = c4b + i * 4;
            float4 v = *reinterpret_cast<const float4*>(
                &qbase[(size_t)(q0 + r) * EMB + c4 * 4]);
            Qt[c4*4+0][r] = v.x; Qt[c4*4+1][r] = v.y;
            Qt[c4*4+2][r] = v.z; Qt[c4*4+3][r] = v.w;
        }
    }

    float m[4], l[4], acc[4][4];
    #pragma unroll
    for (int i = 0; i < 4; i++) {
        m[i] = -1e30f; l[i] = 0.f;
        #pragma unroll
        for (int j = 0; j < 4; j++) acc[i][j] = 0.f;
    }

    const int nkt = (q0 + BQ) / BKT;   // causal: tiles with kb <= q0
    for (int kt = 0; kt < nkt; kt++) {
        const int kb = kt * BKT;
        __syncthreads();   // Qt ready (first iter); prev Ps/Vs fully consumed

        // K tile transposed into KP[d][k]
        {
            const int r = tid & 63;
            const int c4b = tid >> 6;
            #pragma unroll
            for (int i = 0; i < 4; i++) {
                int c4 = c4b + i * 4;
                float4 v = *reinterpret_cast<const float4*>(
                    &kbase[(size_t)(kb + r) * EMB + c4 * 4]);
                KP[c4*4+0][r] = v.x; KP[c4*4+1][r] = v.y;
                KP[c4*4+2][r] = v.z; KP[c4*4+3][r] = v.w;
            }
        }
        // V tile natural layout Vs[k][d]
        #pragma unroll
        for (int i = 0; i < 4; i++) {
            int idx = tid + i * 256;
            int r = idx >> 4, c4 = idx & 15;
            *reinterpret_cast<float4*>(&Vs[r][c4*4]) =
                *reinterpret_cast<const float4*>(
                    &vbase[(size_t)(kb + r) * EMB + c4*4]);
        }
        __syncthreads();

        // Stage 1: S = Q . K^T  (both d-major: 2 x LDS.128 per d)
        float S[4][4];
        #pragma unroll
        for (int i = 0; i < 4; i++)
            #pragma unroll
            for (int j = 0; j < 4; j++) S[i][j] = 0.f;

        #pragma unroll 16
        for (int d = 0; d < HDIM; d++) {
            float4 qv = *reinterpret_cast<const float4*>(&Qt[d][ty*4]);
            float4 kv = *reinterpret_cast<const float4*>(&KP[d][tx*4]);
            float qa[4] = {qv.x, qv.y, qv.z, qv.w};
            float ka[4] = {kv.x, kv.y, kv.z, kv.w};
            #pragma unroll
            for (int i = 0; i < 4; i++)
                #pragma unroll
                for (int j = 0; j < 4; j++)
                    S[i][j] = fmaf(qa[i], ka[j], S[i][j]);
        }

        // Causal mask — only the diagonal tile needs it
        if (kb == q0) {
            #pragma unroll
            for (int i = 0; i < 4; i++) {
                int gq = ty*4 + i;
                #pragma unroll
                for (int j = 0; j < 4; j++)
                    if (tx*4 + j > gq) S[i][j] = -1e30f;
            }
        }

        // Online softmax; P values left in S
        #pragma unroll
        for (int i = 0; i < 4; i++) {
            float mt = fmaxf(fmaxf(S[i][0], S[i][1]), fmaxf(S[i][2], S[i][3]));
            #pragma unroll
            for (int off = 1; off < 16; off <<= 1)
                mt = fmaxf(mt, __shfl_xor_sync(0xffffffffu, mt, off));
            float mn = fmaxf(m[i], mt);
            float cor = __expf(m[i] - mn);
            m[i] = mn;
            float ls = 0.f;
            #pragma unroll
            for (int j = 0; j < 4; j++) {
                S[i][j] = __expf(S[i][j] - mn);
                ls += S[i][j];
            }
            #pragma unroll
            for (int off = 1; off < 16; off <<= 1)
                ls += __shfl_xor_sync(0xffffffffu, ls, off);
            l[i] = l[i] * cor + ls;
            #pragma unroll
            for (int j = 0; j < 4; j++) acc[i][j] *= cor;
        }

        __syncthreads();   // all stage-1 K reads done before overwriting KP with P
        #pragma unroll
        for (int i = 0; i < 4; i++)
            *reinterpret_cast<float4*>(&KP[ty*4+i][tx*4]) =
                make_float4(S[i][0], S[i][1], S[i][2], S[i][3]);
        __syncthreads();

        // Stage 2: acc += P . V
        #pragma unroll 8
        for (int kk = 0; kk < BKT; kk++) {
            float4 vv = *reinterpret_cast<const float4*>(&Vs[kk][tx*4]);
            #pragma unroll
            for (int i = 0; i < 4; i++) {
                float p = KP[ty*4+i][kk];
                acc[i][0] = fmaf(p, vv.x, acc[i][0]);
                acc[i][1] = fmaf(p, vv.y, acc[i][1]);
                acc[i][2] = fmaf(p, vv.z, acc[i][2]);
                acc[i][3] = fmaf(p, vv.w, acc[i][3]);
            }
        }
    }

    // Epilogue: normalize and write [n, q, h*64 + d]
    #pragma unroll
    for (int i = 0; i < 4; i++) {
        float inv = 1.f / l[i];
        float4 o;
        o.x = acc[i][0] * inv;
        o.y = acc[i][1] * inv;
        o.z = acc[i][2] * inv;
        o.w = acc[i][3] * inv;
        *reinterpret_cast<float4*>(
            &O[((size_t)nb * SEQ + q0 + ty*4 + i) * EMB + h * HDIM + tx*4]) = o;
    }
}

// ---------------------------------------------------------------------------
// Inputs: 0 values, 1 keys, 2 query, 3 mask(unused), 4 Wv, 5 bv, 6 Wk, 7 bk,
//         8 Wq, 9 bq, 10 Wo, 11 bo
// ---------------------------------------------------------------------------
extern "C" void kernel_launch(void* const* d_in, const int* in_sizes, int n_in,
                              void* d_out, int out_size)
{
    const float* values = (const float*)d_in[0];
    const float* keys   = (const float*)d_in[1];
    const float* query  = (const float*)d_in[2];
    const float* Wv = (const float*)d_in[4];
    const float* bv = (const float*)d_in[5];
    const float* Wk = (const float*)d_in[6];
    const float* bk = (const float*)d_in[7];
    const float* Wq = (const float*)d_in[8];
    const float* bq = (const float*)d_in[9];
    const float* Wo = (const float*)d_in[10];
    const float* bo = (const float*)d_in[11];
    float* out = (float*)d_out;

    float *pq, *pk, *pv, *pa;
    cudaGetSymbolAddress((void**)&pq, g_q);
    cudaGetSymbolAddress((void**)&pk, g_k);
    cudaGetSymbolAddress((void**)&pv, g_v);
    cudaGetSymbolAddress((void**)&pa, g_ao);

    cudaFuncSetAttribute(attn_kernel,
                         cudaFuncAttributeMaxDynamicSharedMemorySize, ATTN_SMEM);

    dim3 gproj(EMB / 128, MTOT / 128);   // 8 x 32 = 256 blocks
    // Q projection: fold softmax scale 1/sqrt(1024) = 1/32 into alpha
    gemm_nt_bias<<<gproj, 256>>>(query,  Wq, bq, pq, MTOT, EMB, EMB, 0.03125f);
    gemm_nt_bias<<<gproj, 256>>>(keys,   Wk, bk, pk, MTOT, EMB, EMB, 1.0f);
    gemm_nt_bias<<<gproj, 256>>>(values, Wv, bv, pv, MTOT, EMB, EMB, 1.0f);

    dim3 gattn(SEQ / BQ, NHEAD, N_BATCH);  // 32 x 16 x 2 = 1024 blocks
    attn_kernel<<<gattn, 256, ATTN_SMEM>>>(pq, pk, pv, pa);

    gemm_nt_bias<<<gproj, 256>>>(pa, Wo, bo, out, MTOT, EMB, EMB, 1.0f);
}

// round 4
// speedup vs baseline: 1.5776x; 1.4085x over previous
#include <cuda_runtime.h>
#include <cstdint>

#define N_BATCH 2
#define SEQ     2048
#define EMB     1024
#define NHEAD   16
#define HDIM    64
#define MTOT    (N_BATCH*SEQ)   // 4096

// Scratch (allocation-free rule: __device__ globals)
__device__ float g_q[(size_t)MTOT*EMB];
__device__ float g_k[(size_t)MTOT*EMB];
__device__ float g_v[(size_t)MTOT*EMB];
__device__ float g_ao[(size_t)MTOT*EMB];

__device__ __forceinline__ uint32_t f2tf32(float f) {
    uint32_t u;
    asm("cvt.rna.tf32.f32 %0, %1;" : "=r"(u) : "f"(f));
    return u;
}

__device__ __forceinline__ void mma_tf32(
    float c[4], const uint32_t a[4], const uint32_t b[2])
{
    asm volatile(
        "mma.sync.aligned.m16n8k8.row.col.f32.tf32.tf32.f32 "
        "{%0,%1,%2,%3}, {%4,%5,%6,%7}, {%8,%9}, {%0,%1,%2,%3};"
        : "+f"(c[0]), "+f"(c[1]), "+f"(c[2]), "+f"(c[3])
        : "r"(a[0]), "r"(a[1]), "r"(a[2]), "r"(a[3]), "r"(b[0]), "r"(b[1]));
}

// ===========================================================================
// tf32 mma.sync GEMM: C[M,N] = alpha * (A[M,K] @ B[N,K]^T + bias[N])
// CTA 128x128x16, 8 warps (64x32 each: 4x4 m16n8k8 tiles), double-buffered.
// Smem [k][m]/[k][n] with stride 136 -> conflict-free fragment loads.
// M,N mult of 128; K mult of 16.
// ===========================================================================
#define GSTR 136

__global__ __launch_bounds__(256) void gemm_mma(
    const float* __restrict__ A, const float* __restrict__ B,
    const float* __restrict__ bias, float* __restrict__ C,
    int M, int N, int K, float alpha)
{
    __shared__ uint32_t As[2][16][GSTR];
    __shared__ uint32_t Bs[2][16][GSTR];

    const int tid  = threadIdx.x;
    const int lane = tid & 31;
    const int wid  = tid >> 5;
    const int wm   = (wid & 1) * 64;    // warp m offset in tile
    const int wn   = (wid >> 1) * 32;   // warp n offset in tile
    const int m0 = blockIdx.y * 128;
    const int n0 = blockIdx.x * 128;

    const int lr = lane >> 2;           // 0..7
    const int lc = lane & 3;            // 0..3

    float acc[4][4][4];
    #pragma unroll
    for (int i = 0; i < 4; i++)
        #pragma unroll
        for (int j = 0; j < 4; j++)
            #pragma unroll
            for (int r = 0; r < 4; r++) acc[i][j][r] = 0.f;

    // global staging indices: idx = tid, tid+256 ; row = idx>>2, c4 = idx&3
    const int grow0 = tid >> 2,  gc4_0 = tid & 3;
    const int grow1 = (tid + 256) >> 2, gc4_1 = (tid + 256) & 3;

    // ---- preload chunk 0 into buffer 0 ----
    {
        float4 a0 = *reinterpret_cast<const float4*>(&A[(size_t)(m0+grow0)*K + gc4_0*4]);
        float4 a1 = *reinterpret_cast<const float4*>(&A[(size_t)(m0+grow1)*K + gc4_1*4]);
        float4 b0 = *reinterpret_cast<const float4*>(&B[(size_t)(n0+grow0)*K + gc4_0*4]);
        float4 b1 = *reinterpret_cast<const float4*>(&B[(size_t)(n0+grow1)*K + gc4_1*4]);
        As[0][gc4_0*4+0][grow0] = f2tf32(a0.x); As[0][gc4_0*4+1][grow0] = f2tf32(a0.y);
        As[0][gc4_0*4+2][grow0] = f2tf32(a0.z); As[0][gc4_0*4+3][grow0] = f2tf32(a0.w);
        As[0][gc4_1*4+0][grow1] = f2tf32(a1.x); As[0][gc4_1*4+1][grow1] = f2tf32(a1.y);
        As[0][gc4_1*4+2][grow1] = f2tf32(a1.z); As[0][gc4_1*4+3][grow1] = f2tf32(a1.w);
        Bs[0][gc4_0*4+0][grow0] = f2tf32(b0.x); Bs[0][gc4_0*4+1][grow0] = f2tf32(b0.y);
        Bs[0][gc4_0*4+2][grow0] = f2tf32(b0.z); Bs[0][gc4_0*4+3][grow0] = f2tf32(b0.w);
        Bs[0][gc4_1*4+0][grow1] = f2tf32(b1.x); Bs[0][gc4_1*4+1][grow1] = f2tf32(b1.y);
        Bs[0][gc4_1*4+2][grow1] = f2tf32(b1.z); Bs[0][gc4_1*4+3][grow1] = f2tf32(b1.w);
    }
    __syncthreads();

    const int nk = K / 16;
    for (int kc = 0; kc < nk; kc++) {
        const int buf = kc & 1;
        float4 na0, na1, nb0, nb1;
        const bool more = (kc + 1 < nk);
        if (more) {
            const int koff = (kc + 1) * 16;
            na0 = *reinterpret_cast<const float4*>(&A[(size_t)(m0+grow0)*K + koff + gc4_0*4]);
            na1 = *reinterpret_cast<const float4*>(&A[(size_t)(m0+grow1)*K + koff + gc4_1*4]);
            nb0 = *reinterpret_cast<const float4*>(&B[(size_t)(n0+grow0)*K + koff + gc4_0*4]);
            nb1 = *reinterpret_cast<const float4*>(&B[(size_t)(n0+grow1)*K + koff + gc4_1*4]);
        }

        // two k8 steps per chunk
        #pragma unroll
        for (int s = 0; s < 2; s++) {
            const int ks = s * 8;
            uint32_t af[4][4], bf[4][2];
            #pragma unroll
            for (int i = 0; i < 4; i++) {
                const int mr = wm + i * 16 + lr;
                af[i][0] = As[buf][ks + lc    ][mr];
                af[i][1] = As[buf][ks + lc    ][mr + 8];
                af[i][2] = As[buf][ks + lc + 4][mr];
                af[i][3] = As[buf][ks + lc + 4][mr + 8];
            }
            #pragma unroll
            for (int j = 0; j < 4; j++) {
                const int nc = wn + j * 8 + lr;
                bf[j][0] = Bs[buf][ks + lc    ][nc];
                bf[j][1] = Bs[buf][ks + lc + 4][nc];
            }
            #pragma unroll
            for (int i = 0; i < 4; i++)
                #pragma unroll
                for (int j = 0; j < 4; j++)
                    mma_tf32(acc[i][j], af[i], bf[j]);
        }

        if (more) {
            const int nb_ = buf ^ 1;
            As[nb_][gc4_0*4+0][grow0] = f2tf32(na0.x); As[nb_][gc4_0*4+1][grow0] = f2tf32(na0.y);
            As[nb_][gc4_0*4+2][grow0] = f2tf32(na0.z); As[nb_][gc4_0*4+3][grow0] = f2tf32(na0.w);
            As[nb_][gc4_1*4+0][grow1] = f2tf32(na1.x); As[nb_][gc4_1*4+1][grow1] = f2tf32(na1.y);
            As[nb_][gc4_1*4+2][grow1] = f2tf32(na1.z); As[nb_][gc4_1*4+3][grow1] = f2tf32(na1.w);
            Bs[nb_][gc4_0*4+0][grow0] = f2tf32(nb0.x); Bs[nb_][gc4_0*4+1][grow0] = f2tf32(nb0.y);
            Bs[nb_][gc4_0*4+2][grow0] = f2tf32(nb0.z); Bs[nb_][gc4_0*4+3][grow0] = f2tf32(nb0.w);
            Bs[nb_][gc4_1*4+0][grow1] = f2tf32(nb1.x); Bs[nb_][gc4_1*4+1][grow1] = f2tf32(nb1.y);
            Bs[nb_][gc4_1*4+2][grow1] = f2tf32(nb1.z); Bs[nb_][gc4_1*4+3][grow1] = f2tf32(nb1.w);
        }
        __syncthreads();
    }

    // Epilogue: c0/c1 at (row, col..col+1), c2/c3 at (row+8, ...)
    #pragma unroll
    for (int j = 0; j < 4; j++) {
        const int col = n0 + wn + j * 8 + lc * 2;
        const float b0 = bias[col], b1 = bias[col + 1];
        #pragma unroll
        for (int i = 0; i < 4; i++) {
            const int row = m0 + wm + i * 16 + lr;
            float2 o0, o1;
            o0.x = alpha * (acc[i][j][0] + b0);
            o0.y = alpha * (acc[i][j][1] + b1);
            o1.x = alpha * (acc[i][j][2] + b0);
            o1.y = alpha * (acc[i][j][3] + b1);
            *reinterpret_cast<float2*>(&C[(size_t)row * N + col])       = o0;
            *reinterpret_cast<float2*>(&C[(size_t)(row + 8) * N + col]) = o1;
        }
    }
}

// ---------------------------------------------------------------------------
// Flash attention, causal, fp32 (unchanged from R2 — known good, 629us).
// ---------------------------------------------------------------------------
#define BQ  64
#define BKT 64
#define ATTN_SMEM (3 * 64 * 68 * 4)

__global__ __launch_bounds__(256) void attn_kernel(
    const float* __restrict__ Q, const float* __restrict__ K,
    const float* __restrict__ V, float* __restrict__ O)
{
    extern __shared__ float sm[];
    float (*Qt)[68] = reinterpret_cast<float(*)[68]>(sm);              // [d][q]
    float (*KP)[68] = reinterpret_cast<float(*)[68]>(sm + 64*68);      // Kt [d][k] / Ps [q][k]
    float (*Vs)[68] = reinterpret_cast<float(*)[68]>(sm + 2*64*68);    // [k][d]

    const int tid = threadIdx.x;
    const int tx = tid & 15;
    const int ty = tid >> 4;
    const int q0 = blockIdx.x * BQ;
    const int h  = blockIdx.y;
    const int nb = blockIdx.z;

    const float* qbase = Q + (size_t)nb * SEQ * EMB + h * HDIM;
    const float* kbase = K + (size_t)nb * SEQ * EMB + h * HDIM;
    const float* vbase = V + (size_t)nb * SEQ * EMB + h * HDIM;

    {
        const int r = tid & 63;
        const int c4b = tid >> 6;
        #pragma unroll
        for (int i = 0; i < 4; i++) {
            int c4 = c4b + i * 4;
            float4 v = *reinterpret_cast<const float4*>(
                &qbase[(size_t)(q0 + r) * EMB + c4 * 4]);
            Qt[c4*4+0][r] = v.x; Qt[c4*4+1][r] = v.y;
            Qt[c4*4+2][r] = v.z; Qt[c4*4+3][r] = v.w;
        }
    }

    float m[4], l[4], acc[4][4];
    #pragma unroll
    for (int i = 0; i < 4; i++) {
        m[i] = -1e30f; l[i] = 0.f;
        #pragma unroll
        for (int j = 0; j < 4; j++) acc[i][j] = 0.f;
    }

    const int nkt = (q0 + BQ) / BKT;
    for (int kt = 0; kt < nkt; kt++) {
        const int kb = kt * BKT;
        __syncthreads();

        {
            const int r = tid & 63;
            const int c4b = tid >> 6;
            #pragma unroll
            for (int i = 0; i < 4; i++) {
                int c4 = c4b + i * 4;
                float4 v = *reinterpret_cast<const float4*>(
                    &kbase[(size_t)(kb + r) * EMB + c4 * 4]);
                KP[c4*4+0][r] = v.x; KP[c4*4+1][r] = v.y;
                KP[c4*4+2][r] = v.z; KP[c4*4+3][r] = v.w;
            }
        }
        #pragma unroll
        for (int i = 0; i < 4; i++) {
            int idx = tid + i * 256;
            int r = idx >> 4, c4 = idx & 15;
            *reinterpret_cast<float4*>(&Vs[r][c4*4]) =
                *reinterpret_cast<const float4*>(
                    &vbase[(size_t)(kb + r) * EMB + c4*4]);
        }
        __syncthreads();

        float S[4][4];
        #pragma unroll
        for (int i = 0; i < 4; i++)
            #pragma unroll
            for (int j = 0; j < 4; j++) S[i][j] = 0.f;

        #pragma unroll 16
        for (int d = 0; d < HDIM; d++) {
            float4 qv = *reinterpret_cast<const float4*>(&Qt[d][ty*4]);
            float4 kv = *reinterpret_cast<const float4*>(&KP[d][tx*4]);
            float qa[4] = {qv.x, qv.y, qv.z, qv.w};
            float ka[4] = {kv.x, kv.y, kv.z, kv.w};
            #pragma unroll
            for (int i = 0; i < 4; i++)
                #pragma unroll
                for (int j = 0; j < 4; j++)
                    S[i][j] = fmaf(qa[i], ka[j], S[i][j]);
        }

        if (kb == q0) {
            #pragma unroll
            for (int i = 0; i < 4; i++) {
                int gq = ty*4 + i;
                #pragma unroll
                for (int j = 0; j < 4; j++)
                    if (tx*4 + j > gq) S[i][j] = -1e30f;
            }
        }

        #pragma unroll
        for (int i = 0; i < 4; i++) {
            float mt = fmaxf(fmaxf(S[i][0], S[i][1]), fmaxf(S[i][2], S[i][3]));
            #pragma unroll
            for (int off = 1; off < 16; off <<= 1)
                mt = fmaxf(mt, __shfl_xor_sync(0xffffffffu, mt, off));
            float mn = fmaxf(m[i], mt);
            float cor = __expf(m[i] - mn);
            m[i] = mn;
            float ls = 0.f;
            #pragma unroll
            for (int j = 0; j < 4; j++) {
                S[i][j] = __expf(S[i][j] - mn);
                ls += S[i][j];
            }
            #pragma unroll
            for (int off = 1; off < 16; off <<= 1)
                ls += __shfl_xor_sync(0xffffffffu, ls, off);
            l[i] = l[i] * cor + ls;
            #pragma unroll
            for (int j = 0; j < 4; j++) acc[i][j] *= cor;
        }

        __syncthreads();
        #pragma unroll
        for (int i = 0; i < 4; i++)
            *reinterpret_cast<float4*>(&KP[ty*4+i][tx*4]) =
                make_float4(S[i][0], S[i][1], S[i][2], S[i][3]);
        __syncthreads();

        #pragma unroll 8
        for (int kk = 0; kk < BKT; kk++) {
            float4 vv = *reinterpret_cast<const float4*>(&Vs[kk][tx*4]);
            #pragma unroll
            for (int i = 0; i < 4; i++) {
                float p = KP[ty*4+i][kk];
                acc[i][0] = fmaf(p, vv.x, acc[i][0]);
                acc[i][1] = fmaf(p, vv.y, acc[i][1]);
                acc[i][2] = fmaf(p, vv.z, acc[i][2]);
                acc[i][3] = fmaf(p, vv.w, acc[i][3]);
            }
        }
    }

    #pragma unroll
    for (int i = 0; i < 4; i++) {
        float inv = 1.f / l[i];
        float4 o;
        o.x = acc[i][0] * inv;
        o.y = acc[i][1] * inv;
        o.z = acc[i][2] * inv;
        o.w = acc[i][3] * inv;
        *reinterpret_cast<float4*>(
            &O[((size_t)nb * SEQ + q0 + ty*4 + i) * EMB + h * HDIM + tx*4]) = o;
    }
}

// ---------------------------------------------------------------------------
// Inputs: 0 values, 1 keys, 2 query, 3 mask(unused), 4 Wv, 5 bv, 6 Wk, 7 bk,
//         8 Wq, 9 bq, 10 Wo, 11 bo
// ---------------------------------------------------------------------------
extern "C" void kernel_launch(void* const* d_in, const int* in_sizes, int n_in,
                              void* d_out, int out_size)
{
    const float* values = (const float*)d_in[0];
    const float* keys   = (const float*)d_in[1];
    const float* query  = (const float*)d_in[2];
    const float* Wv = (const float*)d_in[4];
    const float* bv = (const float*)d_in[5];
    const float* Wk = (const float*)d_in[6];
    const float* bk = (const float*)d_in[7];
    const float* Wq = (const float*)d_in[8];
    const float* bq = (const float*)d_in[9];
    const float* Wo = (const float*)d_in[10];
    const float* bo = (const float*)d_in[11];
    float* out = (float*)d_out;

    float *pq, *pk, *pv, *pa;
    cudaGetSymbolAddress((void**)&pq, g_q);
    cudaGetSymbolAddress((void**)&pk, g_k);
    cudaGetSymbolAddress((void**)&pv, g_v);
    cudaGetSymbolAddress((void**)&pa, g_ao);

    cudaFuncSetAttribute(attn_kernel,
                         cudaFuncAttributeMaxDynamicSharedMemorySize, ATTN_SMEM);

    dim3 gproj(EMB / 128, MTOT / 128);   // 8 x 32 = 256 CTAs
    // Q projection: fold softmax scale 1/sqrt(1024) = 1/32 into alpha
    gemm_mma<<<gproj, 256>>>(query,  Wq, bq, pq, MTOT, EMB, EMB, 0.03125f);
    gemm_mma<<<gproj, 256>>>(keys,   Wk, bk, pk, MTOT, EMB, EMB, 1.0f);
    gemm_mma<<<gproj, 256>>>(values, Wv, bv, pv, MTOT, EMB, EMB, 1.0f);

    dim3 gattn(SEQ / BQ, NHEAD, N_BATCH);  // 32 x 16 x 2 = 1024 blocks
    attn_kernel<<<gattn, 256, ATTN_SMEM>>>(pq, pk, pv, pa);

    gemm_mma<<<gproj, 256>>>(pa, Wo, bo, out, MTOT, EMB, EMB, 1.0f);
}

// round 5
// speedup vs baseline: 2.0054x; 1.2712x over previous
#include <cuda_runtime.h>
#include <cstdint>

#define N_BATCH 2
#define SEQ     2048
#define EMB     1024
#define NHEAD   16
#define HDIM    64
#define MTOT    (N_BATCH*SEQ)   // 4096

// Scratch (allocation-free rule: __device__ globals)
__device__ float g_q[(size_t)MTOT*EMB];
__device__ float g_k[(size_t)MTOT*EMB];
__device__ float g_v[(size_t)MTOT*EMB];
__device__ float g_ao[(size_t)MTOT*EMB];

__device__ __forceinline__ uint32_t f2tf32(float f) {
    uint32_t u;
    asm("cvt.rna.tf32.f32 %0, %1;" : "=r"(u) : "f"(f));
    return u;
}

__device__ __forceinline__ void mma_tf32(
    float c[4], const uint32_t a[4], const uint32_t b[2])
{
    asm volatile(
        "mma.sync.aligned.m16n8k8.row.col.f32.tf32.tf32.f32 "
        "{%0,%1,%2,%3}, {%4,%5,%6,%7}, {%8,%9}, {%0,%1,%2,%3};"
        : "+f"(c[0]), "+f"(c[1]), "+f"(c[2]), "+f"(c[3])
        : "r"(a[0]), "r"(a[1]), "r"(a[2]), "r"(a[3]), "r"(b[0]), "r"(b[1]));
}

// ===========================================================================
// tf32 mma.sync GEMM: C[M,N] = alpha * (A[M,K] @ B[N,K]^T + bias[N])
// (unchanged from R4 — 92us each)
// ===========================================================================
#define GSTR 136

__global__ __launch_bounds__(256) void gemm_mma(
    const float* __restrict__ A, const float* __restrict__ B,
    const float* __restrict__ bias, float* __restrict__ C,
    int M, int N, int K, float alpha)
{
    __shared__ uint32_t As[2][16][GSTR];
    __shared__ uint32_t Bs[2][16][GSTR];

    const int tid  = threadIdx.x;
    const int lane = tid & 31;
    const int wid  = tid >> 5;
    const int wm   = (wid & 1) * 64;
    const int wn   = (wid >> 1) * 32;
    const int m0 = blockIdx.y * 128;
    const int n0 = blockIdx.x * 128;

    const int lr = lane >> 2;
    const int lc = lane & 3;

    float acc[4][4][4];
    #pragma unroll
    for (int i = 0; i < 4; i++)
        #pragma unroll
        for (int j = 0; j < 4; j++)
            #pragma unroll
            for (int r = 0; r < 4; r++) acc[i][j][r] = 0.f;

    const int grow0 = tid >> 2,  gc4_0 = tid & 3;
    const int grow1 = (tid + 256) >> 2, gc4_1 = (tid + 256) & 3;

    {
        float4 a0 = *reinterpret_cast<const float4*>(&A[(size_t)(m0+grow0)*K + gc4_0*4]);
        float4 a1 = *reinterpret_cast<const float4*>(&A[(size_t)(m0+grow1)*K + gc4_1*4]);
        float4 b0 = *reinterpret_cast<const float4*>(&B[(size_t)(n0+grow0)*K + gc4_0*4]);
        float4 b1 = *reinterpret_cast<const float4*>(&B[(size_t)(n0+grow1)*K + gc4_1*4]);
        As[0][gc4_0*4+0][grow0] = f2tf32(a0.x); As[0][gc4_0*4+1][grow0] = f2tf32(a0.y);
        As[0][gc4_0*4+2][grow0] = f2tf32(a0.z); As[0][gc4_0*4+3][grow0] = f2tf32(a0.w);
        As[0][gc4_1*4+0][grow1] = f2tf32(a1.x); As[0][gc4_1*4+1][grow1] = f2tf32(a1.y);
        As[0][gc4_1*4+2][grow1] = f2tf32(a1.z); As[0][gc4_1*4+3][grow1] = f2tf32(a1.w);
        Bs[0][gc4_0*4+0][grow0] = f2tf32(b0.x); Bs[0][gc4_0*4+1][grow0] = f2tf32(b0.y);
        Bs[0][gc4_0*4+2][grow0] = f2tf32(b0.z); Bs[0][gc4_0*4+3][grow0] = f2tf32(b0.w);
        Bs[0][gc4_1*4+0][grow1] = f2tf32(b1.x); Bs[0][gc4_1*4+1][grow1] = f2tf32(b1.y);
        Bs[0][gc4_1*4+2][grow1] = f2tf32(b1.z); Bs[0][gc4_1*4+3][grow1] = f2tf32(b1.w);
    }
    __syncthreads();

    const int nk = K / 16;
    for (int kc = 0; kc < nk; kc++) {
        const int buf = kc & 1;
        float4 na0, na1, nb0, nb1;
        const bool more = (kc + 1 < nk);
        if (more) {
            const int koff = (kc + 1) * 16;
            na0 = *reinterpret_cast<const float4*>(&A[(size_t)(m0+grow0)*K + koff + gc4_0*4]);
            na1 = *reinterpret_cast<const float4*>(&A[(size_t)(m0+grow1)*K + koff + gc4_1*4]);
            nb0 = *reinterpret_cast<const float4*>(&B[(size_t)(n0+grow0)*K + koff + gc4_0*4]);
            nb1 = *reinterpret_cast<const float4*>(&B[(size_t)(n0+grow1)*K + koff + gc4_1*4]);
        }

        #pragma unroll
        for (int s = 0; s < 2; s++) {
            const int ks = s * 8;
            uint32_t af[4][4], bf[4][2];
            #pragma unroll
            for (int i = 0; i < 4; i++) {
                const int mr = wm + i * 16 + lr;
                af[i][0] = As[buf][ks + lc    ][mr];
                af[i][1] = As[buf][ks + lc    ][mr + 8];
                af[i][2] = As[buf][ks + lc + 4][mr];
                af[i][3] = As[buf][ks + lc + 4][mr + 8];
            }
            #pragma unroll
            for (int j = 0; j < 4; j++) {
                const int nc = wn + j * 8 + lr;
                bf[j][0] = Bs[buf][ks + lc    ][nc];
                bf[j][1] = Bs[buf][ks + lc + 4][nc];
            }
            #pragma unroll
            for (int i = 0; i < 4; i++)
                #pragma unroll
                for (int j = 0; j < 4; j++)
                    mma_tf32(acc[i][j], af[i], bf[j]);
        }

        if (more) {
            const int nb_ = buf ^ 1;
            As[nb_][gc4_0*4+0][grow0] = f2tf32(na0.x); As[nb_][gc4_0*4+1][grow0] = f2tf32(na0.y);
            As[nb_][gc4_0*4+2][grow0] = f2tf32(na0.z); As[nb_][gc4_0*4+3][grow0] = f2tf32(na0.w);
            As[nb_][gc4_1*4+0][grow1] = f2tf32(na1.x); As[nb_][gc4_1*4+1][grow1] = f2tf32(na1.y);
            As[nb_][gc4_1*4+2][grow1] = f2tf32(na1.z); As[nb_][gc4_1*4+3][grow1] = f2tf32(na1.w);
            Bs[nb_][gc4_0*4+0][grow0] = f2tf32(nb0.x); Bs[nb_][gc4_0*4+1][grow0] = f2tf32(nb0.y);
            Bs[nb_][gc4_0*4+2][grow0] = f2tf32(nb0.z); Bs[nb_][gc4_0*4+3][grow0] = f2tf32(nb0.w);
            Bs[nb_][gc4_1*4+0][grow1] = f2tf32(nb1.x); Bs[nb_][gc4_1*4+1][grow1] = f2tf32(nb1.y);
            Bs[nb_][gc4_1*4+2][grow1] = f2tf32(nb1.z); Bs[nb_][gc4_1*4+3][grow1] = f2tf32(nb1.w);
        }
        __syncthreads();
    }

    #pragma unroll
    for (int j = 0; j < 4; j++) {
        const int col = n0 + wn + j * 8 + lc * 2;
        const float b0 = bias[col], b1 = bias[col + 1];
        #pragma unroll
        for (int i = 0; i < 4; i++) {
            const int row = m0 + wm + i * 16 + lr;
            float2 o0, o1;
            o0.x = alpha * (acc[i][j][0] + b0);
            o0.y = alpha * (acc[i][j][1] + b1);
            o1.x = alpha * (acc[i][j][2] + b0);
            o1.y = alpha * (acc[i][j][3] + b1);
            *reinterpret_cast<float2*>(&C[(size_t)row * N + col])       = o0;
            *reinterpret_cast<float2*>(&C[(size_t)(row + 8) * N + col]) = o1;
        }
    }
}

// ===========================================================================
// Tensor-core flash attention (tf32 mma.sync), causal.
// 128 threads / 4 warps; BQ=64 (16 q-rows per warp), BKT=64.
// Qs/Ks row-major [row][d]; Vt transposed [d][key]; Ps per-warp [q][key].
// Stride 72 words: fragment banks (8*lr + lc) -> conflict-free.
// Q pre-scaled by 1/32 in projection.
// ===========================================================================
#define ASTR 72
#define ATTN_SMEM (4 * 64 * ASTR * 4)   // 73728 B

__global__ __launch_bounds__(128) void attn_mma(
    const float* __restrict__ Q, const float* __restrict__ K,
    const float* __restrict__ V, float* __restrict__ O)
{
    extern __shared__ uint32_t sm[];
    uint32_t (*Qs)[ASTR] = reinterpret_cast<uint32_t(*)[ASTR]>(sm);
    uint32_t (*Ks)[ASTR] = reinterpret_cast<uint32_t(*)[ASTR]>(sm + 64*ASTR);
    uint32_t (*Vt)[ASTR] = reinterpret_cast<uint32_t(*)[ASTR]>(sm + 2*64*ASTR);
    uint32_t (*Ps)[ASTR] = reinterpret_cast<uint32_t(*)[ASTR]>(sm + 3*64*ASTR);

    const int tid  = threadIdx.x;
    const int lane = tid & 31;
    const int wid  = tid >> 5;          // 0..3
    const int lr   = lane >> 2;         // 0..7
    const int lc   = lane & 3;          // 0..3
    const int wq   = wid * 16;          // warp's query-row base in tile

    const int q0 = blockIdx.x * 64;
    const int h  = blockIdx.y;
    const int nb = blockIdx.z;

    const float* qbase = Q + (size_t)nb * SEQ * EMB + h * HDIM;
    const float* kbase = K + (size_t)nb * SEQ * EMB + h * HDIM;
    const float* vbase = V + (size_t)nb * SEQ * EMB + h * HDIM;

    const int gr = tid & 63;            // row 0..63 for staging
    const int ch = tid >> 6;            // 0..1

    // ---- load Q tile (row-major, tf32) ----
    #pragma unroll
    for (int i = 0; i < 8; i++) {
        const int c4 = ch * 8 + i;
        float4 v = *reinterpret_cast<const float4*>(
            &qbase[(size_t)(q0 + gr) * EMB + c4 * 4]);
        *reinterpret_cast<uint4*>(&Qs[gr][c4 * 4]) =
            make_uint4(f2tf32(v.x), f2tf32(v.y), f2tf32(v.z), f2tf32(v.w));
    }

    // per-thread softmax state: rows (wq+lr) and (wq+lr+8)
    float m0 = -1e30f, m1 = -1e30f, l0 = 0.f, l1 = 0.f;
    float oacc[8][4];
    #pragma unroll
    for (int j = 0; j < 8; j++)
        #pragma unroll
        for (int r = 0; r < 4; r++) oacc[j][r] = 0.f;

    const int nkt = (q0 + 64) / 64;     // causal tile count
    for (int kt = 0; kt < nkt; kt++) {
        const int kb = kt * 64;
        __syncthreads();   // Qs ready (1st iter); prev tile's Ks/Vt consumed

        // K tile row-major [key][d]
        #pragma unroll
        for (int i = 0; i < 8; i++) {
            const int c4 = ch * 8 + i;
            float4 v = *reinterpret_cast<const float4*>(
                &kbase[(size_t)(kb + gr) * EMB + c4 * 4]);
            *reinterpret_cast<uint4*>(&Ks[gr][c4 * 4]) =
                make_uint4(f2tf32(v.x), f2tf32(v.y), f2tf32(v.z), f2tf32(v.w));
        }
        // V tile transposed [d][key]
        #pragma unroll
        for (int i = 0; i < 8; i++) {
            const int c4 = ch * 8 + i;
            float4 v = *reinterpret_cast<const float4*>(
                &vbase[(size_t)(kb + gr) * EMB + c4 * 4]);
            Vt[c4*4+0][gr] = f2tf32(v.x);
            Vt[c4*4+1][gr] = f2tf32(v.y);
            Vt[c4*4+2][gr] = f2tf32(v.z);
            Vt[c4*4+3][gr] = f2tf32(v.w);
        }
        __syncthreads();

        // ---- S = Q . K^T  (8 k-steps over d, 8 n-tiles over keys) ----
        float sacc[8][4];
        #pragma unroll
        for (int j = 0; j < 8; j++)
            #pragma unroll
            for (int r = 0; r < 4; r++) sacc[j][r] = 0.f;

        #pragma unroll
        for (int s = 0; s < 8; s++) {
            uint32_t af[4];
            af[0] = Qs[wq + lr    ][s*8 + lc    ];
            af[1] = Qs[wq + lr + 8][s*8 + lc    ];
            af[2] = Qs[wq + lr    ][s*8 + lc + 4];
            af[3] = Qs[wq + lr + 8][s*8 + lc + 4];
            #pragma unroll
            for (int j = 0; j < 8; j++) {
                uint32_t bf[2];
                bf[0] = Ks[j*8 + lr][s*8 + lc    ];
                bf[1] = Ks[j*8 + lr][s*8 + lc + 4];
                mma_tf32(sacc[j], af, bf);
            }
        }

        // ---- causal mask (diagonal tile only) ----
        if (kb == q0) {
            const int r0 = wq + lr, r1 = wq + lr + 8;
            #pragma unroll
            for (int j = 0; j < 8; j++) {
                const int c0 = j*8 + 2*lc, c1 = c0 + 1;
                if (c0 > r0) sacc[j][0] = -1e30f;
                if (c1 > r0) sacc[j][1] = -1e30f;
                if (c0 > r1) sacc[j][2] = -1e30f;
                if (c1 > r1) sacc[j][3] = -1e30f;
            }
        }

        // ---- online softmax (row groups = 4 lanes: lr*4 + lc) ----
        float mt0 = -1e30f, mt1 = -1e30f;
        #pragma unroll
        for (int j = 0; j < 8; j++) {
            mt0 = fmaxf(mt0, fmaxf(sacc[j][0], sacc[j][1]));
            mt1 = fmaxf(mt1, fmaxf(sacc[j][2], sacc[j][3]));
        }
        mt0 = fmaxf(mt0, __shfl_xor_sync(0xffffffffu, mt0, 1));
        mt0 = fmaxf(mt0, __shfl_xor_sync(0xffffffffu, mt0, 2));
        mt1 = fmaxf(mt1, __shfl_xor_sync(0xffffffffu, mt1, 1));
        mt1 = fmaxf(mt1, __shfl_xor_sync(0xffffffffu, mt1, 2));

        const float mn0 = fmaxf(m0, mt0);
        const float mn1 = fmaxf(m1, mt1);
        const float cor0 = __expf(m0 - mn0);
        const float cor1 = __expf(m1 - mn1);
        m0 = mn0; m1 = mn1;

        float ls0 = 0.f, ls1 = 0.f;
        #pragma unroll
        for (int j = 0; j < 8; j++) {
            sacc[j][0] = __expf(sacc[j][0] - mn0);
            sacc[j][1] = __expf(sacc[j][1] - mn0);
            sacc[j][2] = __expf(sacc[j][2] - mn1);
            sacc[j][3] = __expf(sacc[j][3] - mn1);
            ls0 += sacc[j][0] + sacc[j][1];
            ls1 += sacc[j][2] + sacc[j][3];
        }
        ls0 += __shfl_xor_sync(0xffffffffu, ls0, 1);
        ls0 += __shfl_xor_sync(0xffffffffu, ls0, 2);
        ls1 += __shfl_xor_sync(0xffffffffu, ls1, 1);
        ls1 += __shfl_xor_sync(0xffffffffu, ls1, 2);
        l0 = l0 * cor0 + ls0;
        l1 = l1 * cor1 + ls1;

        #pragma unroll
        for (int j = 0; j < 8; j++) {
            oacc[j][0] *= cor0; oacc[j][1] *= cor0;
            oacc[j][2] *= cor1; oacc[j][3] *= cor1;
        }

        // ---- stage P (per-warp rows, tf32) ----
        #pragma unroll
        for (int j = 0; j < 8; j++) {
            *reinterpret_cast<uint2*>(&Ps[wq + lr    ][j*8 + 2*lc]) =
                make_uint2(f2tf32(sacc[j][0]), f2tf32(sacc[j][1]));
            *reinterpret_cast<uint2*>(&Ps[wq + lr + 8][j*8 + 2*lc]) =
                make_uint2(f2tf32(sacc[j][2]), f2tf32(sacc[j][3]));
        }
        __syncwarp();

        // ---- O += P . V  (8 k-steps over keys, 8 n-tiles over d) ----
        #pragma unroll
        for (int s = 0; s < 8; s++) {
            uint32_t af[4];
            af[0] = Ps[wq + lr    ][s*8 + lc    ];
            af[1] = Ps[wq + lr + 8][s*8 + lc    ];
            af[2] = Ps[wq + lr    ][s*8 + lc + 4];
            af[3] = Ps[wq + lr + 8][s*8 + lc + 4];
            #pragma unroll
            for (int j = 0; j < 8; j++) {
                uint32_t bf[2];
                bf[0] = Vt[j*8 + lr][s*8 + lc    ];
                bf[1] = Vt[j*8 + lr][s*8 + lc + 4];
                mma_tf32(oacc[j], af, bf);
            }
        }
        __syncwarp();
    }

    // ---- epilogue: normalize, write [n, q, h*64 + d] ----
    const float inv0 = 1.f / l0;
    const float inv1 = 1.f / l1;
    const size_t row0 = (size_t)nb * SEQ + q0 + wq + lr;
    const size_t row1 = row0 + 8;
    #pragma unroll
    for (int j = 0; j < 8; j++) {
        const int col = h * HDIM + j*8 + 2*lc;
        *reinterpret_cast<float2*>(&O[row0 * EMB + col]) =
            make_float2(oacc[j][0] * inv0, oacc[j][1] * inv0);
        *reinterpret_cast<float2*>(&O[row1 * EMB + col]) =
            make_float2(oacc[j][2] * inv1, oacc[j][3] * inv1);
    }
}

// ---------------------------------------------------------------------------
// Inputs: 0 values, 1 keys, 2 query, 3 mask(unused), 4 Wv, 5 bv, 6 Wk, 7 bk,
//         8 Wq, 9 bq, 10 Wo, 11 bo
// ---------------------------------------------------------------------------
extern "C" void kernel_launch(void* const* d_in, const int* in_sizes, int n_in,
                              void* d_out, int out_size)
{
    const float* values = (const float*)d_in[0];
    const float* keys   = (const float*)d_in[1];
    const float* query  = (const float*)d_in[2];
    const float* Wv = (const float*)d_in[4];
    const float* bv = (const float*)d_in[5];
    const float* Wk = (const float*)d_in[6];
    const float* bk = (const float*)d_in[7];
    const float* Wq = (const float*)d_in[8];
    const float* bq = (const float*)d_in[9];
    const float* Wo = (const float*)d_in[10];
    const float* bo = (const float*)d_in[11];
    float* out = (float*)d_out;

    float *pq, *pk, *pv, *pa;
    cudaGetSymbolAddress((void**)&pq, g_q);
    cudaGetSymbolAddress((void**)&pk, g_k);
    cudaGetSymbolAddress((void**)&pv, g_v);
    cudaGetSymbolAddress((void**)&pa, g_ao);

    cudaFuncSetAttribute(attn_mma,
                         cudaFuncAttributeMaxDynamicSharedMemorySize, ATTN_SMEM);

    dim3 gproj(EMB / 128, MTOT / 128);   // 8 x 32 = 256 CTAs
    // Q projection: fold softmax scale 1/sqrt(1024) = 1/32 into alpha
    gemm_mma<<<gproj, 256>>>(query,  Wq, bq, pq, MTOT, EMB, EMB, 0.03125f);
    gemm_mma<<<gproj, 256>>>(keys,   Wk, bk, pk, MTOT, EMB, EMB, 1.0f);
    gemm_mma<<<gproj, 256>>>(values, Wv, bv, pv, MTOT, EMB, EMB, 1.0f);

    dim3 gattn(SEQ / 64, NHEAD, N_BATCH);  // 32 x 16 x 2 = 1024 blocks
    attn_mma<<<gattn, 128, ATTN_SMEM>>>(pq, pk, pv, pa);

    gemm_mma<<<gproj, 256>>>(pa, Wo, bo, out, MTOT, EMB, EMB, 1.0f);
}

// round 6
// speedup vs baseline: 2.1986x; 1.0964x over previous
#include <cuda_runtime.h>
#include <cstdint>

#define N_BATCH 2
#define SEQ     2048
#define EMB     1024
#define NHEAD   16
#define HDIM    64
#define MTOT    (N_BATCH*SEQ)   // 4096

// Scratch (allocation-free rule: __device__ globals)
__device__ float g_q[(size_t)MTOT*EMB];
__device__ float g_k[(size_t)MTOT*EMB];
__device__ float g_v[(size_t)MTOT*EMB];
__device__ float g_ao[(size_t)MTOT*EMB];

__device__ __forceinline__ uint32_t f2tf32(float f) {
    uint32_t u;
    asm("cvt.rna.tf32.f32 %0, %1;" : "=r"(u) : "f"(f));
    return u;
}

__device__ __forceinline__ void mma_tf32(
    float c[4], const uint32_t a[4], const uint32_t b[2])
{
    asm volatile(
        "mma.sync.aligned.m16n8k8.row.col.f32.tf32.tf32.f32 "
        "{%0,%1,%2,%3}, {%4,%5,%6,%7}, {%8,%9}, {%0,%1,%2,%3};"
        : "+f"(c[0]), "+f"(c[1]), "+f"(c[2]), "+f"(c[3])
        : "r"(a[0]), "r"(a[1]), "r"(a[2]), "r"(a[3]), "r"(b[0]), "r"(b[1]));
}

// ===========================================================================
// tf32 mma.sync GEMM: C[M,N] = alpha * (A[M,K] @ B[N,K]^T + bias[N])
// (unchanged from R4/R5 — ~92us each)
// ===========================================================================
#define GSTR 136

__global__ __launch_bounds__(256) void gemm_mma(
    const float* __restrict__ A, const float* __restrict__ B,
    const float* __restrict__ bias, float* __restrict__ C,
    int M, int N, int K, float alpha)
{
    __shared__ uint32_t As[2][16][GSTR];
    __shared__ uint32_t Bs[2][16][GSTR];

    const int tid  = threadIdx.x;
    const int lane = tid & 31;
    const int wid  = tid >> 5;
    const int wm   = (wid & 1) * 64;
    const int wn   = (wid >> 1) * 32;
    const int m0 = blockIdx.y * 128;
    const int n0 = blockIdx.x * 128;

    const int lr = lane >> 2;
    const int lc = lane & 3;

    float acc[4][4][4];
    #pragma unroll
    for (int i = 0; i < 4; i++)
        #pragma unroll
        for (int j = 0; j < 4; j++)
            #pragma unroll
            for (int r = 0; r < 4; r++) acc[i][j][r] = 0.f;

    const int grow0 = tid >> 2,  gc4_0 = tid & 3;
    const int grow1 = (tid + 256) >> 2, gc4_1 = (tid + 256) & 3;

    {
        float4 a0 = *reinterpret_cast<const float4*>(&A[(size_t)(m0+grow0)*K + gc4_0*4]);
        float4 a1 = *reinterpret_cast<const float4*>(&A[(size_t)(m0+grow1)*K + gc4_1*4]);
        float4 b0 = *reinterpret_cast<const float4*>(&B[(size_t)(n0+grow0)*K + gc4_0*4]);
        float4 b1 = *reinterpret_cast<const float4*>(&B[(size_t)(n0+grow1)*K + gc4_1*4]);
        As[0][gc4_0*4+0][grow0] = f2tf32(a0.x); As[0][gc4_0*4+1][grow0] = f2tf32(a0.y);
        As[0][gc4_0*4+2][grow0] = f2tf32(a0.z); As[0][gc4_0*4+3][grow0] = f2tf32(a0.w);
        As[0][gc4_1*4+0][grow1] = f2tf32(a1.x); As[0][gc4_1*4+1][grow1] = f2tf32(a1.y);
        As[0][gc4_1*4+2][grow1] = f2tf32(a1.z); As[0][gc4_1*4+3][grow1] = f2tf32(a1.w);
        Bs[0][gc4_0*4+0][grow0] = f2tf32(b0.x); Bs[0][gc4_0*4+1][grow0] = f2tf32(b0.y);
        Bs[0][gc4_0*4+2][grow0] = f2tf32(b0.z); Bs[0][gc4_0*4+3][grow0] = f2tf32(b0.w);
        Bs[0][gc4_1*4+0][grow1] = f2tf32(b1.x); Bs[0][gc4_1*4+1][grow1] = f2tf32(b1.y);
        Bs[0][gc4_1*4+2][grow1] = f2tf32(b1.z); Bs[0][gc4_1*4+3][grow1] = f2tf32(b1.w);
    }
    __syncthreads();

    const int nk = K / 16;
    for (int kc = 0; kc < nk; kc++) {
        const int buf = kc & 1;
        float4 na0, na1, nb0, nb1;
        const bool more = (kc + 1 < nk);
        if (more) {
            const int koff = (kc + 1) * 16;
            na0 = *reinterpret_cast<const float4*>(&A[(size_t)(m0+grow0)*K + koff + gc4_0*4]);
            na1 = *reinterpret_cast<const float4*>(&A[(size_t)(m0+grow1)*K + koff + gc4_1*4]);
            nb0 = *reinterpret_cast<const float4*>(&B[(size_t)(n0+grow0)*K + koff + gc4_0*4]);
            nb1 = *reinterpret_cast<const float4*>(&B[(size_t)(n0+grow1)*K + koff + gc4_1*4]);
        }

        #pragma unroll
        for (int s = 0; s < 2; s++) {
            const int ks = s * 8;
            uint32_t af[4][4], bf[4][2];
            #pragma unroll
            for (int i = 0; i < 4; i++) {
                const int mr = wm + i * 16 + lr;
                af[i][0] = As[buf][ks + lc    ][mr];
                af[i][1] = As[buf][ks + lc    ][mr + 8];
                af[i][2] = As[buf][ks + lc + 4][mr];
                af[i][3] = As[buf][ks + lc + 4][mr + 8];
            }
            #pragma unroll
            for (int j = 0; j < 4; j++) {
                const int nc = wn + j * 8 + lr;
                bf[j][0] = Bs[buf][ks + lc    ][nc];
                bf[j][1] = Bs[buf][ks + lc + 4][nc];
            }
            #pragma unroll
            for (int i = 0; i < 4; i++)
                #pragma unroll
                for (int j = 0; j < 4; j++)
                    mma_tf32(acc[i][j], af[i], bf[j]);
        }

        if (more) {
            const int nb_ = buf ^ 1;
            As[nb_][gc4_0*4+0][grow0] = f2tf32(na0.x); As[nb_][gc4_0*4+1][grow0] = f2tf32(na0.y);
            As[nb_][gc4_0*4+2][grow0] = f2tf32(na0.z); As[nb_][gc4_0*4+3][grow0] = f2tf32(na0.w);
            As[nb_][gc4_1*4+0][grow1] = f2tf32(na1.x); As[nb_][gc4_1*4+1][grow1] = f2tf32(na1.y);
            As[nb_][gc4_1*4+2][grow1] = f2tf32(na1.z); As[nb_][gc4_1*4+3][grow1] = f2tf32(na1.w);
            Bs[nb_][gc4_0*4+0][grow0] = f2tf32(nb0.x); Bs[nb_][gc4_0*4+1][grow0] = f2tf32(nb0.y);
            Bs[nb_][gc4_0*4+2][grow0] = f2tf32(nb0.z); Bs[nb_][gc4_0*4+3][grow0] = f2tf32(nb0.w);
            Bs[nb_][gc4_1*4+0][grow1] = f2tf32(nb1.x); Bs[nb_][gc4_1*4+1][grow1] = f2tf32(nb1.y);
            Bs[nb_][gc4_1*4+2][grow1] = f2tf32(nb1.z); Bs[nb_][gc4_1*4+3][grow1] = f2tf32(nb1.w);
        }
        __syncthreads();
    }

    #pragma unroll
    for (int j = 0; j < 4; j++) {
        const int col = n0 + wn + j * 8 + lc * 2;
        const float b0 = bias[col], b1 = bias[col + 1];
        #pragma unroll
        for (int i = 0; i < 4; i++) {
            const int row = m0 + wm + i * 16 + lr;
            float2 o0, o1;
            o0.x = alpha * (acc[i][j][0] + b0);
            o0.y = alpha * (acc[i][j][1] + b1);
            o1.x = alpha * (acc[i][j][2] + b0);
            o1.y = alpha * (acc[i][j][3] + b1);
            *reinterpret_cast<float2*>(&C[(size_t)row * N + col])       = o0;
            *reinterpret_cast<float2*>(&C[(size_t)(row + 8) * N + col]) = o1;
        }
    }
}

// ===========================================================================
// Tensor-core flash attention (tf32 mma.sync), causal.
// 128 threads / 4 warps; BQ=64 (16 q-rows per warp), BKT=64.
// R6: stride 72->68 (still conflict-free: banks 4*lr+lc distinct),
//     P overlays the K buffer (extra __syncthreads before P store)
//     => smem 73.7KB -> 51KB -> 4 CTAs/SM instead of 3.
// ===========================================================================
#define ASTR 68
#define ATTN_SMEM (3 * 64 * ASTR * 4)   // 52224 B

__global__ __launch_bounds__(128) void attn_mma(
    const float* __restrict__ Q, const float* __restrict__ K,
    const float* __restrict__ V, float* __restrict__ O)
{
    extern __shared__ uint32_t sm[];
    uint32_t (*Qs)[ASTR] = reinterpret_cast<uint32_t(*)[ASTR]>(sm);
    uint32_t (*Ks)[ASTR] = reinterpret_cast<uint32_t(*)[ASTR]>(sm + 64*ASTR);   // K, then P
    uint32_t (*Vt)[ASTR] = reinterpret_cast<uint32_t(*)[ASTR]>(sm + 2*64*ASTR);
    uint32_t (*Ps)[ASTR] = Ks;   // overlay

    const int tid  = threadIdx.x;
    const int lane = tid & 31;
    const int wid  = tid >> 5;          // 0..3
    const int lr   = lane >> 2;         // 0..7
    const int lc   = lane & 3;          // 0..3
    const int wq   = wid * 16;          // warp's query-row base in tile

    const int q0 = blockIdx.x * 64;
    const int h  = blockIdx.y;
    const int nb = blockIdx.z;

    const float* qbase = Q + (size_t)nb * SEQ * EMB + h * HDIM;
    const float* kbase = K + (size_t)nb * SEQ * EMB + h * HDIM;
    const float* vbase = V + (size_t)nb * SEQ * EMB + h * HDIM;

    const int gr = tid & 63;            // row 0..63 for staging
    const int ch = tid >> 6;            // 0..1

    // ---- load Q tile (row-major, tf32) ----
    #pragma unroll
    for (int i = 0; i < 8; i++) {
        const int c4 = ch * 8 + i;
        float4 v = *reinterpret_cast<const float4*>(
            &qbase[(size_t)(q0 + gr) * EMB + c4 * 4]);
        *reinterpret_cast<uint4*>(&Qs[gr][c4 * 4]) =
            make_uint4(f2tf32(v.x), f2tf32(v.y), f2tf32(v.z), f2tf32(v.w));
    }

    // per-thread softmax state: rows (wq+lr) and (wq+lr+8)
    float m0 = -1e30f, m1 = -1e30f, l0 = 0.f, l1 = 0.f;
    float oacc[8][4];
    #pragma unroll
    for (int j = 0; j < 8; j++)
        #pragma unroll
        for (int r = 0; r < 4; r++) oacc[j][r] = 0.f;

    const int nkt = (q0 + 64) / 64;     // causal tile count
    for (int kt = 0; kt < nkt; kt++) {
        const int kb = kt * 64;
        __syncthreads();   // Qs ready (1st iter); prev tile's Ps/Vt consumed

        // K tile row-major [key][d]
        #pragma unroll
        for (int i = 0; i < 8; i++) {
            const int c4 = ch * 8 + i;
            float4 v = *reinterpret_cast<const float4*>(
                &kbase[(size_t)(kb + gr) * EMB + c4 * 4]);
            *reinterpret_cast<uint4*>(&Ks[gr][c4 * 4]) =
                make_uint4(f2tf32(v.x), f2tf32(v.y), f2tf32(v.z), f2tf32(v.w));
        }
        // V tile transposed [d][key]
        #pragma unroll
        for (int i = 0; i < 8; i++) {
            const int c4 = ch * 8 + i;
            float4 v = *reinterpret_cast<const float4*>(
                &vbase[(size_t)(kb + gr) * EMB + c4 * 4]);
            Vt[c4*4+0][gr] = f2tf32(v.x);
            Vt[c4*4+1][gr] = f2tf32(v.y);
            Vt[c4*4+2][gr] = f2tf32(v.z);
            Vt[c4*4+3][gr] = f2tf32(v.w);
        }
        __syncthreads();

        // ---- S = Q . K^T  (8 k-steps over d, 8 n-tiles over keys) ----
        float sacc[8][4];
        #pragma unroll
        for (int j = 0; j < 8; j++)
            #pragma unroll
            for (int r = 0; r < 4; r++) sacc[j][r] = 0.f;

        #pragma unroll
        for (int s = 0; s < 8; s++) {
            uint32_t af[4];
            af[0] = Qs[wq + lr    ][s*8 + lc    ];
            af[1] = Qs[wq + lr + 8][s*8 + lc    ];
            af[2] = Qs[wq + lr    ][s*8 + lc + 4];
            af[3] = Qs[wq + lr + 8][s*8 + lc + 4];
            #pragma unroll
            for (int j = 0; j < 8; j++) {
                uint32_t bf[2];
                bf[0] = Ks[j*8 + lr][s*8 + lc    ];
                bf[1] = Ks[j*8 + lr][s*8 + lc + 4];
                mma_tf32(sacc[j], af, bf);
            }
        }

        // ---- causal mask (diagonal tile only) ----
        if (kb == q0) {
            const int r0 = wq + lr, r1 = wq + lr + 8;
            #pragma unroll
            for (int j = 0; j < 8; j++) {
                const int c0 = j*8 + 2*lc, c1 = c0 + 1;
                if (c0 > r0) sacc[j][0] = -1e30f;
                if (c1 > r0) sacc[j][1] = -1e30f;
                if (c0 > r1) sacc[j][2] = -1e30f;
                if (c1 > r1) sacc[j][3] = -1e30f;
            }
        }

        // ---- online softmax (row groups = 4 lanes: lr*4 + lc) ----
        float mt0 = -1e30f, mt1 = -1e30f;
        #pragma unroll
        for (int j = 0; j < 8; j++) {
            mt0 = fmaxf(mt0, fmaxf(sacc[j][0], sacc[j][1]));
            mt1 = fmaxf(mt1, fmaxf(sacc[j][2], sacc[j][3]));
        }
        mt0 = fmaxf(mt0, __shfl_xor_sync(0xffffffffu, mt0, 1));
        mt0 = fmaxf(mt0, __shfl_xor_sync(0xffffffffu, mt0, 2));
        mt1 = fmaxf(mt1, __shfl_xor_sync(0xffffffffu, mt1, 1));
        mt1 = fmaxf(mt1, __shfl_xor_sync(0xffffffffu, mt1, 2));

        const float mn0 = fmaxf(m0, mt0);
        const float mn1 = fmaxf(m1, mt1);
        const float cor0 = __expf(m0 - mn0);
        const float cor1 = __expf(m1 - mn1);
        m0 = mn0; m1 = mn1;

        float ls0 = 0.f, ls1 = 0.f;
        #pragma unroll
        for (int j = 0; j < 8; j++) {
            sacc[j][0] = __expf(sacc[j][0] - mn0);
            sacc[j][1] = __expf(sacc[j][1] - mn0);
            sacc[j][2] = __expf(sacc[j][2] - mn1);
            sacc[j][3] = __expf(sacc[j][3] - mn1);
            ls0 += sacc[j][0] + sacc[j][1];
            ls1 += sacc[j][2] + sacc[j][3];
        }
        ls0 += __shfl_xor_sync(0xffffffffu, ls0, 1);
        ls0 += __shfl_xor_sync(0xffffffffu, ls0, 2);
        ls1 += __shfl_xor_sync(0xffffffffu, ls1, 1);
        ls1 += __shfl_xor_sync(0xffffffffu, ls1, 2);
        l0 = l0 * cor0 + ls0;
        l1 = l1 * cor1 + ls1;

        #pragma unroll
        for (int j = 0; j < 8; j++) {
            oacc[j][0] *= cor0; oacc[j][1] *= cor0;
            oacc[j][2] *= cor1; oacc[j][3] *= cor1;
        }

        // ---- P overlays K: wait until ALL warps finished stage-1 K reads ----
        __syncthreads();

        // ---- stage P (per-warp rows, tf32) ----
        #pragma unroll
        for (int j = 0; j < 8; j++) {
            *reinterpret_cast<uint2*>(&Ps[wq + lr    ][j*8 + 2*lc]) =
                make_uint2(f2tf32(sacc[j][0]), f2tf32(sacc[j][1]));
            *reinterpret_cast<uint2*>(&Ps[wq + lr + 8][j*8 + 2*lc]) =
                make_uint2(f2tf32(sacc[j][2]), f2tf32(sacc[j][3]));
        }
        __syncwarp();

        // ---- O += P . V  (8 k-steps over keys, 8 n-tiles over d) ----
        #pragma unroll
        for (int s = 0; s < 8; s++) {
            uint32_t af[4];
            af[0] = Ps[wq + lr    ][s*8 + lc    ];
            af[1] = Ps[wq + lr + 8][s*8 + lc    ];
            af[2] = Ps[wq + lr    ][s*8 + lc + 4];
            af[3] = Ps[wq + lr + 8][s*8 + lc + 4];
            #pragma unroll
            for (int j = 0; j < 8; j++) {
                uint32_t bf[2];
                bf[0] = Vt[j*8 + lr][s*8 + lc    ];
                bf[1] = Vt[j*8 + lr][s*8 + lc + 4];
                mma_tf32(oacc[j], af, bf);
            }
        }
        __syncwarp();
    }

    // ---- epilogue: normalize, write [n, q, h*64 + d] ----
    const float inv0 = 1.f / l0;
    const float inv1 = 1.f / l1;
    const size_t row0 = (size_t)nb * SEQ + q0 + wq + lr;
    const size_t row1 = row0 + 8;
    #pragma unroll
    for (int j = 0; j < 8; j++) {
        const int col = h * HDIM + j*8 + 2*lc;
        *reinterpret_cast<float2*>(&O[row0 * EMB + col]) =
            make_float2(oacc[j][0] * inv0, oacc[j][1] * inv0);
        *reinterpret_cast<float2*>(&O[row1 * EMB + col]) =
            make_float2(oacc[j][2] * inv1, oacc[j][3] * inv1);
    }
}

// ---------------------------------------------------------------------------
// Inputs: 0 values, 1 keys, 2 query, 3 mask(unused), 4 Wv, 5 bv, 6 Wk, 7 bk,
//         8 Wq, 9 bq, 10 Wo, 11 bo
// ---------------------------------------------------------------------------
extern "C" void kernel_launch(void* const* d_in, const int* in_sizes, int n_in,
                              void* d_out, int out_size)
{
    const float* values = (const float*)d_in[0];
    const float* keys   = (const float*)d_in[1];
    const float* query  = (const float*)d_in[2];
    const float* Wv = (const float*)d_in[4];
    const float* bv = (const float*)d_in[5];
    const float* Wk = (const float*)d_in[6];
    const float* bk = (const float*)d_in[7];
    const float* Wq = (const float*)d_in[8];
    const float* bq = (const float*)d_in[9];
    const float* Wo = (const float*)d_in[10];
    const float* bo = (const float*)d_in[11];
    float* out = (float*)d_out;

    float *pq, *pk, *pv, *pa;
    cudaGetSymbolAddress((void**)&pq, g_q);
    cudaGetSymbolAddress((void**)&pk, g_k);
    cudaGetSymbolAddress((void**)&pv, g_v);
    cudaGetSymbolAddress((void**)&pa, g_ao);

    cudaFuncSetAttribute(attn_mma,
                         cudaFuncAttributeMaxDynamicSharedMemorySize, ATTN_SMEM);

    dim3 gproj(EMB / 128, MTOT / 128);   // 8 x 32 = 256 CTAs
    // Q projection: fold softmax scale 1/sqrt(1024) = 1/32 into alpha
    gemm_mma<<<gproj, 256>>>(query,  Wq, bq, pq, MTOT, EMB, EMB, 0.03125f);
    gemm_mma<<<gproj, 256>>>(keys,   Wk, bk, pk, MTOT, EMB, EMB, 1.0f);
    gemm_mma<<<gproj, 256>>>(values, Wv, bv, pv, MTOT, EMB, EMB, 1.0f);

    dim3 gattn(SEQ / 64, NHEAD, N_BATCH);  // 32 x 16 x 2 = 1024 blocks
    attn_mma<<<gattn, 128, ATTN_SMEM>>>(pq, pk, pv, pa);

    gemm_mma<<<gproj, 256>>>(pa, Wo, bo, out, MTOT, EMB, EMB, 1.0f);
}

// round 7
// speedup vs baseline: 2.7873x; 1.2677x over previous
#include <cuda_runtime.h>
#include <cstdint>

#define N_BATCH 2
#define SEQ     2048
#define EMB     1024
#define NHEAD   16
#define HDIM    64
#define MTOT    (N_BATCH*SEQ)   // 4096

// Scratch (allocation-free rule: __device__ globals)
__device__ float g_q[(size_t)MTOT*EMB];
__device__ float g_k[(size_t)MTOT*EMB];
__device__ float g_v[(size_t)MTOT*EMB];
__device__ float g_ao[(size_t)MTOT*EMB];

__device__ __forceinline__ uint32_t f2tf32(float f) {
    uint32_t u;
    asm("cvt.rna.tf32.f32 %0, %1;" : "=r"(u) : "f"(f));
    return u;
}

__device__ __forceinline__ void mma_tf32(
    float c[4], const uint32_t a[4], const uint32_t b[2])
{
    asm volatile(
        "mma.sync.aligned.m16n8k8.row.col.f32.tf32.tf32.f32 "
        "{%0,%1,%2,%3}, {%4,%5,%6,%7}, {%8,%9}, {%0,%1,%2,%3};"
        : "+f"(c[0]), "+f"(c[1]), "+f"(c[2]), "+f"(c[3])
        : "r"(a[0]), "r"(a[1]), "r"(a[2]), "r"(a[3]), "r"(b[0]), "r"(b[1]));
}

// ===========================================================================
// tf32 mma.sync GEMM: C[M,N] = alpha * (A[M,K] @ B[N,K]^T + bias[N])
// (unchanged from R4/R5/R6 — ~92us each)
// ===========================================================================
#define GSTR 136

__global__ __launch_bounds__(256) void gemm_mma(
    const float* __restrict__ A, const float* __restrict__ B,
    const float* __restrict__ bias, float* __restrict__ C,
    int M, int N, int K, float alpha)
{
    __shared__ uint32_t As[2][16][GSTR];
    __shared__ uint32_t Bs[2][16][GSTR];

    const int tid  = threadIdx.x;
    const int lane = tid & 31;
    const int wid  = tid >> 5;
    const int wm   = (wid & 1) * 64;
    const int wn   = (wid >> 1) * 32;
    const int m0 = blockIdx.y * 128;
    const int n0 = blockIdx.x * 128;

    const int lr = lane >> 2;
    const int lc = lane & 3;

    float acc[4][4][4];
    #pragma unroll
    for (int i = 0; i < 4; i++)
        #pragma unroll
        for (int j = 0; j < 4; j++)
            #pragma unroll
            for (int r = 0; r < 4; r++) acc[i][j][r] = 0.f;

    const int grow0 = tid >> 2,  gc4_0 = tid & 3;
    const int grow1 = (tid + 256) >> 2, gc4_1 = (tid + 256) & 3;

    {
        float4 a0 = *reinterpret_cast<const float4*>(&A[(size_t)(m0+grow0)*K + gc4_0*4]);
        float4 a1 = *reinterpret_cast<const float4*>(&A[(size_t)(m0+grow1)*K + gc4_1*4]);
        float4 b0 = *reinterpret_cast<const float4*>(&B[(size_t)(n0+grow0)*K + gc4_0*4]);
        float4 b1 = *reinterpret_cast<const float4*>(&B[(size_t)(n0+grow1)*K + gc4_1*4]);
        As[0][gc4_0*4+0][grow0] = f2tf32(a0.x); As[0][gc4_0*4+1][grow0] = f2tf32(a0.y);
        As[0][gc4_0*4+2][grow0] = f2tf32(a0.z); As[0][gc4_0*4+3][grow0] = f2tf32(a0.w);
        As[0][gc4_1*4+0][grow1] = f2tf32(a1.x); As[0][gc4_1*4+1][grow1] = f2tf32(a1.y);
        As[0][gc4_1*4+2][grow1] = f2tf32(a1.z); As[0][gc4_1*4+3][grow1] = f2tf32(a1.w);
        Bs[0][gc4_0*4+0][grow0] = f2tf32(b0.x); Bs[0][gc4_0*4+1][grow0] = f2tf32(b0.y);
        Bs[0][gc4_0*4+2][grow0] = f2tf32(b0.z); Bs[0][gc4_0*4+3][grow0] = f2tf32(b0.w);
        Bs[0][gc4_1*4+0][grow1] = f2tf32(b1.x); Bs[0][gc4_1*4+1][grow1] = f2tf32(b1.y);
        Bs[0][gc4_1*4+2][grow1] = f2tf32(b1.z); Bs[0][gc4_1*4+3][grow1] = f2tf32(b1.w);
    }
    __syncthreads();

    const int nk = K / 16;
    for (int kc = 0; kc < nk; kc++) {
        const int buf = kc & 1;
        float4 na0, na1, nb0, nb1;
        const bool more = (kc + 1 < nk);
        if (more) {
            const int koff = (kc + 1) * 16;
            na0 = *reinterpret_cast<const float4*>(&A[(size_t)(m0+grow0)*K + koff + gc4_0*4]);
            na1 = *reinterpret_cast<const float4*>(&A[(size_t)(m0+grow1)*K + koff + gc4_1*4]);
            nb0 = *reinterpret_cast<const float4*>(&B[(size_t)(n0+grow0)*K + koff + gc4_0*4]);
            nb1 = *reinterpret_cast<const float4*>(&B[(size_t)(n0+grow1)*K + koff + gc4_1*4]);
        }

        #pragma unroll
        for (int s = 0; s < 2; s++) {
            const int ks = s * 8;
            uint32_t af[4][4], bf[4][2];
            #pragma unroll
            for (int i = 0; i < 4; i++) {
                const int mr = wm + i * 16 + lr;
                af[i][0] = As[buf][ks + lc    ][mr];
                af[i][1] = As[buf][ks + lc    ][mr + 8];
                af[i][2] = As[buf][ks + lc + 4][mr];
                af[i][3] = As[buf][ks + lc + 4][mr + 8];
            }
            #pragma unroll
            for (int j = 0; j < 4; j++) {
                const int nc = wn + j * 8 + lr;
                bf[j][0] = Bs[buf][ks + lc    ][nc];
                bf[j][1] = Bs[buf][ks + lc + 4][nc];
            }
            #pragma unroll
            for (int i = 0; i < 4; i++)
                #pragma unroll
                for (int j = 0; j < 4; j++)
                    mma_tf32(acc[i][j], af[i], bf[j]);
        }

        if (more) {
            const int nb_ = buf ^ 1;
            As[nb_][gc4_0*4+0][grow0] = f2tf32(na0.x); As[nb_][gc4_0*4+1][grow0] = f2tf32(na0.y);
            As[nb_][gc4_0*4+2][grow0] = f2tf32(na0.z); As[nb_][gc4_0*4+3][grow0] = f2tf32(na0.w);
            As[nb_][gc4_1*4+0][grow1] = f2tf32(na1.x); As[nb_][gc4_1*4+1][grow1] = f2tf32(na1.y);
            As[nb_][gc4_1*4+2][grow1] = f2tf32(na1.z); As[nb_][gc4_1*4+3][grow1] = f2tf32(na1.w);
            Bs[nb_][gc4_0*4+0][grow0] = f2tf32(nb0.x); Bs[nb_][gc4_0*4+1][grow0] = f2tf32(nb0.y);
            Bs[nb_][gc4_0*4+2][grow0] = f2tf32(nb0.z); Bs[nb_][gc4_0*4+3][grow0] = f2tf32(nb0.w);
            Bs[nb_][gc4_1*4+0][grow1] = f2tf32(nb1.x); Bs[nb_][gc4_1*4+1][grow1] = f2tf32(nb1.y);
            Bs[nb_][gc4_1*4+2][grow1] = f2tf32(nb1.z); Bs[nb_][gc4_1*4+3][grow1] = f2tf32(nb1.w);
        }
        __syncthreads();
    }

    #pragma unroll
    for (int j = 0; j < 4; j++) {
        const int col = n0 + wn + j * 8 + lc * 2;
        const float b0 = bias[col], b1 = bias[col + 1];
        #pragma unroll
        for (int i = 0; i < 4; i++) {
            const int row = m0 + wm + i * 16 + lr;
            float2 o0, o1;
            o0.x = alpha * (acc[i][j][0] + b0);
            o0.y = alpha * (acc[i][j][1] + b1);
            o1.x = alpha * (acc[i][j][2] + b0);
            o1.y = alpha * (acc[i][j][3] + b1);
            *reinterpret_cast<float2*>(&C[(size_t)row * N + col])       = o0;
            *reinterpret_cast<float2*>(&C[(size_t)(row + 8) * N + col]) = o1;
        }
    }
}

// ===========================================================================
// Tensor-core flash attention (tf32 mma.sync), causal.
// 128 threads / 4 warps; BQ=64 (16 q-rows per warp), BKT=64.
// R7: coalesced staging (lane<->column), V kept row-major (stride 72,
//     fragment banks 8*lc+lr conflict-free), heavy q-tiles launched first.
// Smem: Qs 64x68 + Ks 64x68 (P overlays) + Vs 64x72 = 53248 B -> 4 CTAs/SM.
// ===========================================================================
#define ASTR 68
#define VSTR 72
#define ATTN_SMEM ((2 * 64 * ASTR + 64 * VSTR) * 4)   // 53248 B

__global__ __launch_bounds__(128) void attn_mma(
    const float* __restrict__ Q, const float* __restrict__ K,
    const float* __restrict__ V, float* __restrict__ O)
{
    extern __shared__ uint32_t sm[];
    uint32_t (*Qs)[ASTR] = reinterpret_cast<uint32_t(*)[ASTR]>(sm);
    uint32_t (*Ks)[ASTR] = reinterpret_cast<uint32_t(*)[ASTR]>(sm + 64*ASTR);   // K, then P
    uint32_t (*Vs)[VSTR] = reinterpret_cast<uint32_t(*)[VSTR]>(sm + 2*64*ASTR); // row-major [key][d]
    uint32_t (*Ps)[ASTR] = Ks;   // overlay

    const int tid  = threadIdx.x;
    const int lane = tid & 31;
    const int wid  = tid >> 5;          // 0..3
    const int lr   = lane >> 2;         // 0..7
    const int lc   = lane & 3;          // 0..3
    const int wq   = wid * 16;          // warp's query-row base in tile

    // Heavy q-tiles (most key tiles) first: better wave scheduling.
    const int q0 = (gridDim.x - 1 - blockIdx.x) * 64;
    const int h  = blockIdx.y;
    const int nb = blockIdx.z;

    const float* qbase = Q + (size_t)nb * SEQ * EMB + h * HDIM;
    const float* kbase = K + (size_t)nb * SEQ * EMB + h * HDIM;
    const float* vbase = V + (size_t)nb * SEQ * EMB + h * HDIM;

    // ---- load Q tile, coalesced: lane <-> column chunk ----
    #pragma unroll
    for (int i = 0; i < 8; i++) {
        const int idx = tid + i * 128;
        const int row = idx >> 4, c4 = idx & 15;
        float4 v = *reinterpret_cast<const float4*>(
            &qbase[(size_t)(q0 + row) * EMB + c4 * 4]);
        *reinterpret_cast<uint4*>(&Qs[row][c4 * 4]) =
            make_uint4(f2tf32(v.x), f2tf32(v.y), f2tf32(v.z), f2tf32(v.w));
    }

    // per-thread softmax state: rows (wq+lr) and (wq+lr+8)
    float m0 = -1e30f, m1 = -1e30f, l0 = 0.f, l1 = 0.f;
    float oacc[8][4];
    #pragma unroll
    for (int j = 0; j < 8; j++)
        #pragma unroll
        for (int r = 0; r < 4; r++) oacc[j][r] = 0.f;

    const int nkt = (q0 + 64) / 64;     // causal tile count
    for (int kt = 0; kt < nkt; kt++) {
        const int kb = kt * 64;
        __syncthreads();   // Qs ready (1st iter); prev tile's Ps/Vs consumed

        // K tile row-major [key][d], coalesced
        #pragma unroll
        for (int i = 0; i < 8; i++) {
            const int idx = tid + i * 128;
            const int row = idx >> 4, c4 = idx & 15;
            float4 v = *reinterpret_cast<const float4*>(
                &kbase[(size_t)(kb + row) * EMB + c4 * 4]);
            *reinterpret_cast<uint4*>(&Ks[row][c4 * 4]) =
                make_uint4(f2tf32(v.x), f2tf32(v.y), f2tf32(v.z), f2tf32(v.w));
        }
        // V tile row-major [key][d], coalesced
        #pragma unroll
        for (int i = 0; i < 8; i++) {
            const int idx = tid + i * 128;
            const int row = idx >> 4, c4 = idx & 15;
            float4 v = *reinterpret_cast<const float4*>(
                &vbase[(size_t)(kb + row) * EMB + c4 * 4]);
            *reinterpret_cast<uint4*>(&Vs[row][c4 * 4]) =
                make_uint4(f2tf32(v.x), f2tf32(v.y), f2tf32(v.z), f2tf32(v.w));
        }
        __syncthreads();

        // ---- S = Q . K^T  (8 k-steps over d, 8 n-tiles over keys) ----
        float sacc[8][4];
        #pragma unroll
        for (int j = 0; j < 8; j++)
            #pragma unroll
            for (int r = 0; r < 4; r++) sacc[j][r] = 0.f;

        #pragma unroll
        for (int s = 0; s < 8; s++) {
            uint32_t af[4];
            af[0] = Qs[wq + lr    ][s*8 + lc    ];
            af[1] = Qs[wq + lr + 8][s*8 + lc    ];
            af[2] = Qs[wq + lr    ][s*8 + lc + 4];
            af[3] = Qs[wq + lr + 8][s*8 + lc + 4];
            #pragma unroll
            for (int j = 0; j < 8; j++) {
                uint32_t bf[2];
                bf[0] = Ks[j*8 + lr][s*8 + lc    ];
                bf[1] = Ks[j*8 + lr][s*8 + lc + 4];
                mma_tf32(sacc[j], af, bf);
            }
        }

        // ---- causal mask (diagonal tile only) ----
        if (kb == q0) {
            const int r0 = wq + lr, r1 = wq + lr + 8;
            #pragma unroll
            for (int j = 0; j < 8; j++) {
                const int c0 = j*8 + 2*lc, c1 = c0 + 1;
                if (c0 > r0) sacc[j][0] = -1e30f;
                if (c1 > r0) sacc[j][1] = -1e30f;
                if (c0 > r1) sacc[j][2] = -1e30f;
                if (c1 > r1) sacc[j][3] = -1e30f;
            }
        }

        // ---- online softmax (row groups = 4 lanes) ----
        float mt0 = -1e30f, mt1 = -1e30f;
        #pragma unroll
        for (int j = 0; j < 8; j++) {
            mt0 = fmaxf(mt0, fmaxf(sacc[j][0], sacc[j][1]));
            mt1 = fmaxf(mt1, fmaxf(sacc[j][2], sacc[j][3]));
        }
        mt0 = fmaxf(mt0, __shfl_xor_sync(0xffffffffu, mt0, 1));
        mt0 = fmaxf(mt0, __shfl_xor_sync(0xffffffffu, mt0, 2));
        mt1 = fmaxf(mt1, __shfl_xor_sync(0xffffffffu, mt1, 1));
        mt1 = fmaxf(mt1, __shfl_xor_sync(0xffffffffu, mt1, 2));

        const float mn0 = fmaxf(m0, mt0);
        const float mn1 = fmaxf(m1, mt1);
        const float cor0 = __expf(m0 - mn0);
        const float cor1 = __expf(m1 - mn1);
        m0 = mn0; m1 = mn1;

        float ls0 = 0.f, ls1 = 0.f;
        #pragma unroll
        for (int j = 0; j < 8; j++) {
            sacc[j][0] = __expf(sacc[j][0] - mn0);
            sacc[j][1] = __expf(sacc[j][1] - mn0);
            sacc[j][2] = __expf(sacc[j][2] - mn1);
            sacc[j][3] = __expf(sacc[j][3] - mn1);
            ls0 += sacc[j][0] + sacc[j][1];
            ls1 += sacc[j][2] + sacc[j][3];
        }
        ls0 += __shfl_xor_sync(0xffffffffu, ls0, 1);
        ls0 += __shfl_xor_sync(0xffffffffu, ls0, 2);
        ls1 += __shfl_xor_sync(0xffffffffu, ls1, 1);
        ls1 += __shfl_xor_sync(0xffffffffu, ls1, 2);
        l0 = l0 * cor0 + ls0;
        l1 = l1 * cor1 + ls1;

        #pragma unroll
        for (int j = 0; j < 8; j++) {
            oacc[j][0] *= cor0; oacc[j][1] *= cor0;
            oacc[j][2] *= cor1; oacc[j][3] *= cor1;
        }

        // ---- P overlays K: wait until ALL warps finished stage-1 K reads ----
        __syncthreads();

        // ---- stage P (per-warp rows, tf32) ----
        #pragma unroll
        for (int j = 0; j < 8; j++) {
            *reinterpret_cast<uint2*>(&Ps[wq + lr    ][j*8 + 2*lc]) =
                make_uint2(f2tf32(sacc[j][0]), f2tf32(sacc[j][1]));
            *reinterpret_cast<uint2*>(&Ps[wq + lr + 8][j*8 + 2*lc]) =
                make_uint2(f2tf32(sacc[j][2]), f2tf32(sacc[j][3]));
        }
        __syncwarp();

        // ---- O += P . V  (8 k-steps over keys, 8 n-tiles over d) ----
        // V row-major: bf from Vs[key][d]; banks (8*lc + lr) conflict-free.
        #pragma unroll
        for (int s = 0; s < 8; s++) {
            uint32_t af[4];
            af[0] = Ps[wq + lr    ][s*8 + lc    ];
            af[1] = Ps[wq + lr + 8][s*8 + lc    ];
            af[2] = Ps[wq + lr    ][s*8 + lc + 4];
            af[3] = Ps[wq + lr + 8][s*8 + lc + 4];
            #pragma unroll
            for (int j = 0; j < 8; j++) {
                uint32_t bf[2];
                bf[0] = Vs[s*8 + lc    ][j*8 + lr];
                bf[1] = Vs[s*8 + lc + 4][j*8 + lr];
                mma_tf32(oacc[j], af, bf);
            }
        }
        __syncwarp();
    }

    // ---- epilogue: normalize, write [n, q, h*64 + d] ----
    const float inv0 = 1.f / l0;
    const float inv1 = 1.f / l1;
    const size_t row0 = (size_t)nb * SEQ + q0 + wq + lr;
    const size_t row1 = row0 + 8;
    #pragma unroll
    for (int j = 0; j < 8; j++) {
        const int col = h * HDIM + j*8 + 2*lc;
        *reinterpret_cast<float2*>(&O[row0 * EMB + col]) =
            make_float2(oacc[j][0] * inv0, oacc[j][1] * inv0);
        *reinterpret_cast<float2*>(&O[row1 * EMB + col]) =
            make_float2(oacc[j][2] * inv1, oacc[j][3] * inv1);
    }
}

// ---------------------------------------------------------------------------
// Inputs: 0 values, 1 keys, 2 query, 3 mask(unused), 4 Wv, 5 bv, 6 Wk, 7 bk,
//         8 Wq, 9 bq, 10 Wo, 11 bo
// ---------------------------------------------------------------------------
extern "C" void kernel_launch(void* const* d_in, const int* in_sizes, int n_in,
                              void* d_out, int out_size)
{
    const float* values = (const float*)d_in[0];
    const float* keys   = (const float*)d_in[1];
    const float* query  = (const float*)d_in[2];
    const float* Wv = (const float*)d_in[4];
    const float* bv = (const float*)d_in[5];
    const float* Wk = (const float*)d_in[6];
    const float* bk = (const float*)d_in[7];
    const float* Wq = (const float*)d_in[8];
    const float* bq = (const float*)d_in[9];
    const float* Wo = (const float*)d_in[10];
    const float* bo = (const float*)d_in[11];
    float* out = (float*)d_out;

    float *pq, *pk, *pv, *pa;
    cudaGetSymbolAddress((void**)&pq, g_q);
    cudaGetSymbolAddress((void**)&pk, g_k);
    cudaGetSymbolAddress((void**)&pv, g_v);
    cudaGetSymbolAddress((void**)&pa, g_ao);

    cudaFuncSetAttribute(attn_mma,
                         cudaFuncAttributeMaxDynamicSharedMemorySize, ATTN_SMEM);

    dim3 gproj(EMB / 128, MTOT / 128);   // 8 x 32 = 256 CTAs
    // Q projection: fold softmax scale 1/sqrt(1024) = 1/32 into alpha
    gemm_mma<<<gproj, 256>>>(query,  Wq, bq, pq, MTOT, EMB, EMB, 0.03125f);
    gemm_mma<<<gproj, 256>>>(keys,   Wk, bk, pk, MTOT, EMB, EMB, 1.0f);
    gemm_mma<<<gproj, 256>>>(values, Wv, bv, pv, MTOT, EMB, EMB, 1.0f);

    dim3 gattn(SEQ / 64, NHEAD, N_BATCH);  // 32 x 16 x 2 = 1024 blocks
    attn_mma<<<gattn, 128, ATTN_SMEM>>>(pq, pk, pv, pa);

    gemm_mma<<<gproj, 256>>>(pa, Wo, bo, out, MTOT, EMB, EMB, 1.0f);
}

// round 8
// speedup vs baseline: 2.9417x; 1.0554x over previous
#include <cuda_runtime.h>
#include <cstdint>

#define N_BATCH 2
#define SEQ     2048
#define EMB     1024
#define NHEAD   16
#define HDIM    64
#define MTOT    (N_BATCH*SEQ)   // 4096

// Scratch (allocation-free rule: __device__ globals)
__device__ float g_q[(size_t)MTOT*EMB];
__device__ float g_k[(size_t)MTOT*EMB];
__device__ float g_v[(size_t)MTOT*EMB];
__device__ float g_ao[(size_t)MTOT*EMB];

__device__ __forceinline__ uint32_t f2tf32(float f) {
    uint32_t u;
    asm("cvt.rna.tf32.f32 %0, %1;" : "=r"(u) : "f"(f));
    return u;
}

__device__ __forceinline__ void mma_tf32(
    float c[4], const uint32_t a[4], const uint32_t b[2])
{
    asm volatile(
        "mma.sync.aligned.m16n8k8.row.col.f32.tf32.tf32.f32 "
        "{%0,%1,%2,%3}, {%4,%5,%6,%7}, {%8,%9}, {%0,%1,%2,%3};"
        : "+f"(c[0]), "+f"(c[1]), "+f"(c[2]), "+f"(c[3])
        : "r"(a[0]), "r"(a[1]), "r"(a[2]), "r"(a[3]), "r"(b[0]), "r"(b[1]));
}

// ===========================================================================
// tf32 mma.sync GEMM body: C = alpha * (A[M,K] @ B[N,K]^T + bias[N])
// CTA 128x128x16, 8 warps (64x32), double-buffered. (R4 body, unchanged.)
// ===========================================================================
#define GSTR 136

__device__ __forceinline__ void gemm_body(
    const float* __restrict__ A, const float* __restrict__ B,
    const float* __restrict__ bias, float* __restrict__ C,
    int M, int N, int K, float alpha)
{
    __shared__ uint32_t As[2][16][GSTR];
    __shared__ uint32_t Bs[2][16][GSTR];

    const int tid  = threadIdx.x;
    const int lane = tid & 31;
    const int wid  = tid >> 5;
    const int wm   = (wid & 1) * 64;
    const int wn   = (wid >> 1) * 32;
    const int m0 = blockIdx.y * 128;
    const int n0 = blockIdx.x * 128;

    const int lr = lane >> 2;
    const int lc = lane & 3;

    float acc[4][4][4];
    #pragma unroll
    for (int i = 0; i < 4; i++)
        #pragma unroll
        for (int j = 0; j < 4; j++)
            #pragma unroll
            for (int r = 0; r < 4; r++) acc[i][j][r] = 0.f;

    const int grow0 = tid >> 2,  gc4_0 = tid & 3;
    const int grow1 = (tid + 256) >> 2, gc4_1 = (tid + 256) & 3;

    {
        float4 a0 = *reinterpret_cast<const float4*>(&A[(size_t)(m0+grow0)*K + gc4_0*4]);
        float4 a1 = *reinterpret_cast<const float4*>(&A[(size_t)(m0+grow1)*K + gc4_1*4]);
        float4 b0 = *reinterpret_cast<const float4*>(&B[(size_t)(n0+grow0)*K + gc4_0*4]);
        float4 b1 = *reinterpret_cast<const float4*>(&B[(size_t)(n0+grow1)*K + gc4_1*4]);
        As[0][gc4_0*4+0][grow0] = f2tf32(a0.x); As[0][gc4_0*4+1][grow0] = f2tf32(a0.y);
        As[0][gc4_0*4+2][grow0] = f2tf32(a0.z); As[0][gc4_0*4+3][grow0] = f2tf32(a0.w);
        As[0][gc4_1*4+0][grow1] = f2tf32(a1.x); As[0][gc4_1*4+1][grow1] = f2tf32(a1.y);
        As[0][gc4_1*4+2][grow1] = f2tf32(a1.z); As[0][gc4_1*4+3][grow1] = f2tf32(a1.w);
        Bs[0][gc4_0*4+0][grow0] = f2tf32(b0.x); Bs[0][gc4_0*4+1][grow0] = f2tf32(b0.y);
        Bs[0][gc4_0*4+2][grow0] = f2tf32(b0.z); Bs[0][gc4_0*4+3][grow0] = f2tf32(b0.w);
        Bs[0][gc4_1*4+0][grow1] = f2tf32(b1.x); Bs[0][gc4_1*4+1][grow1] = f2tf32(b1.y);
        Bs[0][gc4_1*4+2][grow1] = f2tf32(b1.z); Bs[0][gc4_1*4+3][grow1] = f2tf32(b1.w);
    }
    __syncthreads();

    const int nk = K / 16;
    for (int kc = 0; kc < nk; kc++) {
        const int buf = kc & 1;
        float4 na0, na1, nb0, nb1;
        const bool more = (kc + 1 < nk);
        if (more) {
            const int koff = (kc + 1) * 16;
            na0 = *reinterpret_cast<const float4*>(&A[(size_t)(m0+grow0)*K + koff + gc4_0*4]);
            na1 = *reinterpret_cast<const float4*>(&A[(size_t)(m0+grow1)*K + koff + gc4_1*4]);
            nb0 = *reinterpret_cast<const float4*>(&B[(size_t)(n0+grow0)*K + koff + gc4_0*4]);
            nb1 = *reinterpret_cast<const float4*>(&B[(size_t)(n0+grow1)*K + koff + gc4_1*4]);
        }

        #pragma unroll
        for (int s = 0; s < 2; s++) {
            const int ks = s * 8;
            uint32_t af[4][4], bf[4][2];
            #pragma unroll
            for (int i = 0; i < 4; i++) {
                const int mr = wm + i * 16 + lr;
                af[i][0] = As[buf][ks + lc    ][mr];
                af[i][1] = As[buf][ks + lc    ][mr + 8];
                af[i][2] = As[buf][ks + lc + 4][mr];
                af[i][3] = As[buf][ks + lc + 4][mr + 8];
            }
            #pragma unroll
            for (int j = 0; j < 4; j++) {
                const int nc = wn + j * 8 + lr;
                bf[j][0] = Bs[buf][ks + lc    ][nc];
                bf[j][1] = Bs[buf][ks + lc + 4][nc];
            }
            #pragma unroll
            for (int i = 0; i < 4; i++)
                #pragma unroll
                for (int j = 0; j < 4; j++)
                    mma_tf32(acc[i][j], af[i], bf[j]);
        }

        if (more) {
            const int nb_ = buf ^ 1;
            As[nb_][gc4_0*4+0][grow0] = f2tf32(na0.x); As[nb_][gc4_0*4+1][grow0] = f2tf32(na0.y);
            As[nb_][gc4_0*4+2][grow0] = f2tf32(na0.z); As[nb_][gc4_0*4+3][grow0] = f2tf32(na0.w);
            As[nb_][gc4_1*4+0][grow1] = f2tf32(na1.x); As[nb_][gc4_1*4+1][grow1] = f2tf32(na1.y);
            As[nb_][gc4_1*4+2][grow1] = f2tf32(na1.z); As[nb_][gc4_1*4+3][grow1] = f2tf32(na1.w);
            Bs[nb_][gc4_0*4+0][grow0] = f2tf32(nb0.x); Bs[nb_][gc4_0*4+1][grow0] = f2tf32(nb0.y);
            Bs[nb_][gc4_0*4+2][grow0] = f2tf32(nb0.z); Bs[nb_][gc4_0*4+3][grow0] = f2tf32(nb0.w);
            Bs[nb_][gc4_1*4+0][grow1] = f2tf32(nb1.x); Bs[nb_][gc4_1*4+1][grow1] = f2tf32(nb1.y);
            Bs[nb_][gc4_1*4+2][grow1] = f2tf32(nb1.z); Bs[nb_][gc4_1*4+3][grow1] = f2tf32(nb1.w);
        }
        __syncthreads();
    }

    #pragma unroll
    for (int j = 0; j < 4; j++) {
        const int col = n0 + wn + j * 8 + lc * 2;
        const float b0 = bias[col], b1 = bias[col + 1];
        #pragma unroll
        for (int i = 0; i < 4; i++) {
            const int row = m0 + wm + i * 16 + lr;
            float2 o0, o1;
            o0.x = alpha * (acc[i][j][0] + b0);
            o0.y = alpha * (acc[i][j][1] + b1);
            o1.x = alpha * (acc[i][j][2] + b0);
            o1.y = alpha * (acc[i][j][3] + b1);
            *reinterpret_cast<float2*>(&C[(size_t)row * N + col])       = o0;
            *reinterpret_cast<float2*>(&C[(size_t)(row + 8) * N + col]) = o1;
        }
    }
}

__global__ __launch_bounds__(256) void gemm_mma(
    const float* __restrict__ A, const float* __restrict__ B,
    const float* __restrict__ bias, float* __restrict__ C,
    int M, int N, int K, float alpha)
{
    gemm_body(A, B, bias, C, M, N, K, alpha);
}

// Fused QKV: one launch, blockIdx.z selects the projection.
__global__ __launch_bounds__(256) void gemm_qkv(
    const float* __restrict__ Aq, const float* __restrict__ Ak, const float* __restrict__ Av,
    const float* __restrict__ Wq, const float* __restrict__ Wk, const float* __restrict__ Wv,
    const float* __restrict__ bq, const float* __restrict__ bk, const float* __restrict__ bv,
    float* __restrict__ Cq, float* __restrict__ Ck, float* __restrict__ Cv)
{
    const int z = blockIdx.z;
    const float* A = (z == 0) ? Aq : (z == 1) ? Ak : Av;
    const float* W = (z == 0) ? Wq : (z == 1) ? Wk : Wv;
    const float* b = (z == 0) ? bq : (z == 1) ? bk : bv;
    float*       C = (z == 0) ? Cq : (z == 1) ? Ck : Cv;
    const float alpha = (z == 0) ? 0.03125f : 1.0f;  // softmax scale folded into Q
    gemm_body(A, W, b, C, MTOT, EMB, EMB, alpha);
}

// ===========================================================================
// Tensor-core flash attention (tf32 mma.sync), causal.
// R8: BQ=128, 4 warps, 32 q-rows per warp (2 m16 tiles) -> B-fragment reuse,
//     LDS/MMA 2.5 -> 1.5. BKT=64. P in its own buffer (no K overlay barrier).
//     Fully-masked k-tiles skipped per-warp.
// Smem: Qs 128x68 + Ks 64x68 + Vs 64x72 + Ps 128x68 = 105472 B -> 2 CTA/SM.
// ===========================================================================
#define ASTR 68
#define VSTR 72
#define ATTN_SMEM ((128*ASTR + 64*ASTR + 64*VSTR + 128*ASTR) * 4)

__global__ __launch_bounds__(128, 2) void attn_mma(
    const float* __restrict__ Q, const float* __restrict__ K,
    const float* __restrict__ V, float* __restrict__ O)
{
    extern __shared__ uint32_t sm[];
    uint32_t (*Qs)[ASTR] = reinterpret_cast<uint32_t(*)[ASTR]>(sm);
    uint32_t (*Ks)[ASTR] = reinterpret_cast<uint32_t(*)[ASTR]>(sm + 128*ASTR);
    uint32_t (*Vs)[VSTR] = reinterpret_cast<uint32_t(*)[VSTR]>(sm + 192*ASTR);
    uint32_t (*Ps)[ASTR] = reinterpret_cast<uint32_t(*)[ASTR]>(sm + 192*ASTR + 64*VSTR);

    const int tid  = threadIdx.x;
    const int lane = tid & 31;
    const int wid  = tid >> 5;          // 0..3
    const int lr   = lane >> 2;         // 0..7
    const int lc   = lane & 3;          // 0..3
    const int wq   = wid * 32;          // warp's query-row base (32 rows/warp)

    // Heavy q-tiles first
    const int q0 = (gridDim.x - 1 - blockIdx.x) * 128;
    const int h  = blockIdx.y;
    const int nb = blockIdx.z;

    const float* qbase = Q + (size_t)nb * SEQ * EMB + h * HDIM;
    const float* kbase = K + (size_t)nb * SEQ * EMB + h * HDIM;
    const float* vbase = V + (size_t)nb * SEQ * EMB + h * HDIM;

    // ---- load Q tile (128 x 64), coalesced ----
    #pragma unroll
    for (int i = 0; i < 16; i++) {
        const int idx = tid + i * 128;
        const int row = idx >> 4, c4 = idx & 15;
        float4 v = *reinterpret_cast<const float4*>(
            &qbase[(size_t)(q0 + row) * EMB + c4 * 4]);
        *reinterpret_cast<uint4*>(&Qs[row][c4 * 4]) =
            make_uint4(f2tf32(v.x), f2tf32(v.y), f2tf32(v.z), f2tf32(v.w));
    }

    // softmax state per m-tile t (rows wq+t*16+lr, +8)
    float mrow[2][2], lsum[2][2];
    #pragma unroll
    for (int t = 0; t < 2; t++) {
        mrow[t][0] = -1e30f; mrow[t][1] = -1e30f;
        lsum[t][0] = 0.f;    lsum[t][1] = 0.f;
    }
    float oacc[2][8][4];
    #pragma unroll
    for (int t = 0; t < 2; t++)
        #pragma unroll
        for (int j = 0; j < 8; j++)
            #pragma unroll
            for (int r = 0; r < 4; r++) oacc[t][j][r] = 0.f;

    const int nkt = (q0 + 128) / 64;
    for (int kt = 0; kt < nkt; kt++) {
        const int kb = kt * 64;
        __syncthreads();   // Qs ready (1st); prev Ks/Vs consumed by all warps

        // stage K (64x64) and V (64x64), coalesced
        #pragma unroll
        for (int i = 0; i < 8; i++) {
            const int idx = tid + i * 128;
            const int row = idx >> 4, c4 = idx & 15;
            float4 kv = *reinterpret_cast<const float4*>(
                &kbase[(size_t)(kb + row) * EMB + c4 * 4]);
            *reinterpret_cast<uint4*>(&Ks[row][c4 * 4]) =
                make_uint4(f2tf32(kv.x), f2tf32(kv.y), f2tf32(kv.z), f2tf32(kv.w));
            float4 vv = *reinterpret_cast<const float4*>(
                &vbase[(size_t)(kb + row) * EMB + c4 * 4]);
            *reinterpret_cast<uint4*>(&Vs[row][c4 * 4]) =
                make_uint4(f2tf32(vv.x), f2tf32(vv.y), f2tf32(vv.z), f2tf32(vv.w));
        }
        __syncthreads();

        // skip k-tiles entirely above this warp's rows
        if (kb > q0 + wq + 31) continue;

        // ---- S = Q . K^T : 2 m-tiles x 8 j-tiles, 8 k-steps ----
        float sacc[2][8][4];
        #pragma unroll
        for (int t = 0; t < 2; t++)
            #pragma unroll
            for (int j = 0; j < 8; j++)
                #pragma unroll
                for (int r = 0; r < 4; r++) sacc[t][j][r] = 0.f;

        #pragma unroll
        for (int s = 0; s < 8; s++) {
            uint32_t af[2][4];
            #pragma unroll
            for (int t = 0; t < 2; t++) {
                const int mr = wq + t * 16 + lr;
                af[t][0] = Qs[mr    ][s*8 + lc    ];
                af[t][1] = Qs[mr + 8][s*8 + lc    ];
                af[t][2] = Qs[mr    ][s*8 + lc + 4];
                af[t][3] = Qs[mr + 8][s*8 + lc + 4];
            }
            #pragma unroll
            for (int j = 0; j < 8; j++) {
                uint32_t bf[2];
                bf[0] = Ks[j*8 + lr][s*8 + lc    ];
                bf[1] = Ks[j*8 + lr][s*8 + lc + 4];
                mma_tf32(sacc[0][j], af[0], bf);
                mma_tf32(sacc[1][j], af[1], bf);
            }
        }

        // ---- causal mask (only when tile crosses this warp's diagonal) ----
        if (kb + 63 > q0 + wq) {
            #pragma unroll
            for (int t = 0; t < 2; t++) {
                const int r0 = q0 + wq + t*16 + lr, r1 = r0 + 8;
                #pragma unroll
                for (int j = 0; j < 8; j++) {
                    const int c0 = kb + j*8 + 2*lc, c1 = c0 + 1;
                    if (c0 > r0) sacc[t][j][0] = -1e30f;
                    if (c1 > r0) sacc[t][j][1] = -1e30f;
                    if (c0 > r1) sacc[t][j][2] = -1e30f;
                    if (c1 > r1) sacc[t][j][3] = -1e30f;
                }
            }
        }

        // ---- online softmax per m-tile ----
        #pragma unroll
        for (int t = 0; t < 2; t++) {
            float mt0 = -1e30f, mt1 = -1e30f;
            #pragma unroll
            for (int j = 0; j < 8; j++) {
                mt0 = fmaxf(mt0, fmaxf(sacc[t][j][0], sacc[t][j][1]));
                mt1 = fmaxf(mt1, fmaxf(sacc[t][j][2], sacc[t][j][3]));
            }
            mt0 = fmaxf(mt0, __shfl_xor_sync(0xffffffffu, mt0, 1));
            mt0 = fmaxf(mt0, __shfl_xor_sync(0xffffffffu, mt0, 2));
            mt1 = fmaxf(mt1, __shfl_xor_sync(0xffffffffu, mt1, 1));
            mt1 = fmaxf(mt1, __shfl_xor_sync(0xffffffffu, mt1, 2));

            const float mn0 = fmaxf(mrow[t][0], mt0);
            const float mn1 = fmaxf(mrow[t][1], mt1);
            const float cor0 = __expf(mrow[t][0] - mn0);
            const float cor1 = __expf(mrow[t][1] - mn1);
            mrow[t][0] = mn0; mrow[t][1] = mn1;

            float ls0 = 0.f, ls1 = 0.f;
            #pragma unroll
            for (int j = 0; j < 8; j++) {
                sacc[t][j][0] = __expf(sacc[t][j][0] - mn0);
                sacc[t][j][1] = __expf(sacc[t][j][1] - mn0);
                sacc[t][j][2] = __expf(sacc[t][j][2] - mn1);
                sacc[t][j][3] = __expf(sacc[t][j][3] - mn1);
                ls0 += sacc[t][j][0] + sacc[t][j][1];
                ls1 += sacc[t][j][2] + sacc[t][j][3];
            }
            ls0 += __shfl_xor_sync(0xffffffffu, ls0, 1);
            ls0 += __shfl_xor_sync(0xffffffffu, ls0, 2);
            ls1 += __shfl_xor_sync(0xffffffffu, ls1, 1);
            ls1 += __shfl_xor_sync(0xffffffffu, ls1, 2);
            lsum[t][0] = lsum[t][0] * cor0 + ls0;
            lsum[t][1] = lsum[t][1] * cor1 + ls1;

            #pragma unroll
            for (int j = 0; j < 8; j++) {
                oacc[t][j][0] *= cor0; oacc[t][j][1] *= cor0;
                oacc[t][j][2] *= cor1; oacc[t][j][3] *= cor1;
            }
        }

        // ---- stage P (per-warp private rows) ----
        #pragma unroll
        for (int t = 0; t < 2; t++) {
            const int mr = wq + t * 16 + lr;
            #pragma unroll
            for (int j = 0; j < 8; j++) {
                *reinterpret_cast<uint2*>(&Ps[mr    ][j*8 + 2*lc]) =
                    make_uint2(f2tf32(sacc[t][j][0]), f2tf32(sacc[t][j][1]));
                *reinterpret_cast<uint2*>(&Ps[mr + 8][j*8 + 2*lc]) =
                    make_uint2(f2tf32(sacc[t][j][2]), f2tf32(sacc[t][j][3]));
            }
        }
        __syncwarp();

        // ---- O += P . V ----
        #pragma unroll
        for (int s = 0; s < 8; s++) {
            uint32_t af[2][4];
            #pragma unroll
            for (int t = 0; t < 2; t++) {
                const int mr = wq + t * 16 + lr;
                af[t][0] = Ps[mr    ][s*8 + lc    ];
                af[t][1] = Ps[mr + 8][s*8 + lc    ];
                af[t][2] = Ps[mr    ][s*8 + lc + 4];
                af[t][3] = Ps[mr + 8][s*8 + lc + 4];
            }
            #pragma unroll
            for (int j = 0; j < 8; j++) {
                uint32_t bf[2];
                bf[0] = Vs[s*8 + lc    ][j*8 + lr];
                bf[1] = Vs[s*8 + lc + 4][j*8 + lr];
                mma_tf32(oacc[0][j], af[0], bf);
                mma_tf32(oacc[1][j], af[1], bf);
            }
        }
        __syncwarp();
    }

    // ---- epilogue ----
    #pragma unroll
    for (int t = 0; t < 2; t++) {
        const float inv0 = 1.f / lsum[t][0];
        const float inv1 = 1.f / lsum[t][1];
        const size_t row0 = (size_t)nb * SEQ + q0 + wq + t*16 + lr;
        const size_t row1 = row0 + 8;
        #pragma unroll
        for (int j = 0; j < 8; j++) {
            const int col = h * HDIM + j*8 + 2*lc;
            *reinterpret_cast<float2*>(&O[row0 * EMB + col]) =
                make_float2(oacc[t][j][0] * inv0, oacc[t][j][1] * inv0);
            *reinterpret_cast<float2*>(&O[row1 * EMB + col]) =
                make_float2(oacc[t][j][2] * inv1, oacc[t][j][3] * inv1);
        }
    }
}

// ---------------------------------------------------------------------------
// Inputs: 0 values, 1 keys, 2 query, 3 mask(unused), 4 Wv, 5 bv, 6 Wk, 7 bk,
//         8 Wq, 9 bq, 10 Wo, 11 bo
// ---------------------------------------------------------------------------
extern "C" void kernel_launch(void* const* d_in, const int* in_sizes, int n_in,
                              void* d_out, int out_size)
{
    const float* values = (const float*)d_in[0];
    const float* keys   = (const float*)d_in[1];
    const float* query  = (const float*)d_in[2];
    const float* Wv = (const float*)d_in[4];
    const float* bv = (const float*)d_in[5];
    const float* Wk = (const float*)d_in[6];
    const float* bk = (const float*)d_in[7];
    const float* Wq = (const float*)d_in[8];
    const float* bq = (const float*)d_in[9];
    const float* Wo = (const float*)d_in[10];
    const float* bo = (const float*)d_in[11];
    float* out = (float*)d_out;

    float *pq, *pk, *pv, *pa;
    cudaGetSymbolAddress((void**)&pq, g_q);
    cudaGetSymbolAddress((void**)&pk, g_k);
    cudaGetSymbolAddress((void**)&pv, g_v);
    cudaGetSymbolAddress((void**)&pa, g_ao);

    cudaFuncSetAttribute(attn_mma,
                         cudaFuncAttributeMaxDynamicSharedMemorySize, ATTN_SMEM);

    // Fused Q/K/V projections: 8 x 32 x 3 = 768 CTAs in one launch
    dim3 gqkv(EMB / 128, MTOT / 128, 3);
    gemm_qkv<<<gqkv, 256>>>(query, keys, values,
                            Wq, Wk, Wv, bq, bk, bv,
                            pq, pk, pv);

    dim3 gattn(SEQ / 128, NHEAD, N_BATCH);  // 16 x 16 x 2 = 512 blocks
    attn_mma<<<gattn, 128, ATTN_SMEM>>>(pq, pk, pv, pa);

    dim3 gproj(EMB / 128, MTOT / 128);
    gemm_mma<<<gproj, 256>>>(pa, Wo, bo, out, MTOT, EMB, EMB, 1.0f);
}

// round 9
// speedup vs baseline: 3.4949x; 1.1881x over previous
#include <cuda_runtime.h>
#include <cstdint>

#define N_BATCH 2
#define SEQ     2048
#define EMB     1024
#define NHEAD   16
#define HDIM    64
#define MTOT    (N_BATCH*SEQ)   // 4096

// Scratch (allocation-free rule: __device__ globals)
__device__ float g_q[(size_t)MTOT*EMB];
__device__ float g_k[(size_t)MTOT*EMB];
__device__ float g_v[(size_t)MTOT*EMB];
__device__ float g_ao[(size_t)MTOT*EMB];

__device__ __forceinline__ uint32_t f2tf32(float f) {
    uint32_t u;
    asm("cvt.rna.tf32.f32 %0, %1;" : "=r"(u) : "f"(f));
    return u;
}

__device__ __forceinline__ void mma_tf32(
    float c[4], const uint32_t a[4], const uint32_t b[2])
{
    asm volatile(
        "mma.sync.aligned.m16n8k8.row.col.f32.tf32.tf32.f32 "
        "{%0,%1,%2,%3}, {%4,%5,%6,%7}, {%8,%9}, {%0,%1,%2,%3};"
        : "+f"(c[0]), "+f"(c[1]), "+f"(c[2]), "+f"(c[3])
        : "r"(a[0]), "r"(a[1]), "r"(a[2]), "r"(a[3]), "r"(b[0]), "r"(b[1]));
}

// ===========================================================================
// tf32 mma.sync GEMM: C = alpha * (A[M,K] @ B[N,K]^T + bias[N])
// R9: XOR-swizzled [row][32] smem (BK=32, zero padding):
//   word (row,k) at row*32 + ((k>>2 ^ (row&7))<<2) + (k&3)
//   -> STS.128 staging conflict-free AND scalar fragment LDS conflict-free.
// CTA 128x128, 8 warps (64x32), double-buffered, dynamic smem 64KB.
// ===========================================================================
#define GEMM_SMEM (2 * 2 * 4096 * 4)   // 65536 B

__device__ __forceinline__ void gemm_body(
    const float* __restrict__ A, const float* __restrict__ B,
    const float* __restrict__ bias, float* __restrict__ C,
    int M, int N, int K, float alpha)
{
    extern __shared__ uint32_t gsm[];
    uint32_t* Asm = gsm;             // [2][4096]
    uint32_t* Bsm = gsm + 2 * 4096;  // [2][4096]

    const int tid  = threadIdx.x;
    const int lane = tid & 31;
    const int wid  = tid >> 5;
    const int wm   = (wid & 1) * 64;
    const int wn   = (wid >> 1) * 32;
    const int m0 = blockIdx.y * 128;
    const int n0 = blockIdx.x * 128;

    const int lr = lane >> 2;
    const int lc = lane & 3;

    // staging: thread -> (row = tid>>3 + i*32, c4 = tid&7), 4 rows each for A and B
    const int srow = tid >> 3;
    const int sc4  = tid & 7;

    float acc[4][4][4];
    #pragma unroll
    for (int i = 0; i < 4; i++)
        #pragma unroll
        for (int j = 0; j < 4; j++)
            #pragma unroll
            for (int r = 0; r < 4; r++) acc[i][j][r] = 0.f;

    // ---- preload chunk 0 into buffer 0 ----
    #pragma unroll
    for (int i = 0; i < 4; i++) {
        const int row = srow + i * 32;
        const uint32_t soff = row * 32 + (((uint32_t)(sc4 ^ (row & 7))) << 2);
        float4 a = *reinterpret_cast<const float4*>(&A[(size_t)(m0 + row) * K + sc4 * 4]);
        *reinterpret_cast<uint4*>(&Asm[soff]) =
            make_uint4(f2tf32(a.x), f2tf32(a.y), f2tf32(a.z), f2tf32(a.w));
        float4 b = *reinterpret_cast<const float4*>(&B[(size_t)(n0 + row) * K + sc4 * 4]);
        *reinterpret_cast<uint4*>(&Bsm[soff]) =
            make_uint4(f2tf32(b.x), f2tf32(b.y), f2tf32(b.z), f2tf32(b.w));
    }
    __syncthreads();

    const int nk = K / 32;
    for (int kc = 0; kc < nk; kc++) {
        const int buf = kc & 1;
        const uint32_t* Ab = Asm + buf * 4096;
        const uint32_t* Bb = Bsm + buf * 4096;

        float4 na[4], nb[4];
        const bool more = (kc + 1 < nk);
        if (more) {
            const int koff = (kc + 1) * 32 + sc4 * 4;
            #pragma unroll
            for (int i = 0; i < 4; i++) {
                const int row = srow + i * 32;
                na[i] = *reinterpret_cast<const float4*>(&A[(size_t)(m0 + row) * K + koff]);
                nb[i] = *reinterpret_cast<const float4*>(&B[(size_t)(n0 + row) * K + koff]);
            }
        }

        // 4 k8-steps
        #pragma unroll
        for (int s = 0; s < 4; s++) {
            const uint32_t x0 = ((uint32_t)((2*s)     ^ lr)) << 2;
            const uint32_t x1 = ((uint32_t)((2*s + 1) ^ lr)) << 2;
            uint32_t af[4][4], bf[4][2];
            #pragma unroll
            for (int i = 0; i < 4; i++) {
                const uint32_t ra = (wm + i * 16 + lr) * 32;
                af[i][0] = Ab[ra       + x0 + lc];
                af[i][1] = Ab[ra + 256 + x0 + lc];   // (+8 rows)*32
                af[i][2] = Ab[ra       + x1 + lc];
                af[i][3] = Ab[ra + 256 + x1 + lc];
            }
            #pragma unroll
            for (int j = 0; j < 4; j++) {
                const uint32_t rb = (wn + j * 8 + lr) * 32;
                bf[j][0] = Bb[rb + x0 + lc];
                bf[j][1] = Bb[rb + x1 + lc];
            }
            #pragma unroll
            for (int i = 0; i < 4; i++)
                #pragma unroll
                for (int j = 0; j < 4; j++)
                    mma_tf32(acc[i][j], af[i], bf[j]);
        }

        if (more) {
            uint32_t* An = Asm + (buf ^ 1) * 4096;
            uint32_t* Bn = Bsm + (buf ^ 1) * 4096;
            #pragma unroll
            for (int i = 0; i < 4; i++) {
                const int row = srow + i * 32;
                const uint32_t soff = row * 32 + (((uint32_t)(sc4 ^ (row & 7))) << 2);
                *reinterpret_cast<uint4*>(&An[soff]) =
                    make_uint4(f2tf32(na[i].x), f2tf32(na[i].y), f2tf32(na[i].z), f2tf32(na[i].w));
                *reinterpret_cast<uint4*>(&Bn[soff]) =
                    make_uint4(f2tf32(nb[i].x), f2tf32(nb[i].y), f2tf32(nb[i].z), f2tf32(nb[i].w));
            }
        }
        __syncthreads();
    }

    #pragma unroll
    for (int j = 0; j < 4; j++) {
        const int col = n0 + wn + j * 8 + lc * 2;
        const float b0 = bias[col], b1 = bias[col + 1];
        #pragma unroll
        for (int i = 0; i < 4; i++) {
            const int row = m0 + wm + i * 16 + lr;
            float2 o0, o1;
            o0.x = alpha * (acc[i][j][0] + b0);
            o0.y = alpha * (acc[i][j][1] + b1);
            o1.x = alpha * (acc[i][j][2] + b0);
            o1.y = alpha * (acc[i][j][3] + b1);
            *reinterpret_cast<float2*>(&C[(size_t)row * N + col])       = o0;
            *reinterpret_cast<float2*>(&C[(size_t)(row + 8) * N + col]) = o1;
        }
    }
}

__global__ __launch_bounds__(256, 2) void gemm_mma(
    const float* __restrict__ A, const float* __restrict__ B,
    const float* __restrict__ bias, float* __restrict__ C,
    int M, int N, int K, float alpha)
{
    gemm_body(A, B, bias, C, M, N, K, alpha);
}

// Fused QKV: one launch, blockIdx.z selects the projection.
__global__ __launch_bounds__(256, 2) void gemm_qkv(
    const float* __restrict__ Aq, const float* __restrict__ Ak, const float* __restrict__ Av,
    const float* __restrict__ Wq, const float* __restrict__ Wk, const float* __restrict__ Wv,
    const float* __restrict__ bq, const float* __restrict__ bk, const float* __restrict__ bv,
    float* __restrict__ Cq, float* __restrict__ Ck, float* __restrict__ Cv)
{
    const int z = blockIdx.z;
    const float* A = (z == 0) ? Aq : (z == 1) ? Ak : Av;
    const float* W = (z == 0) ? Wq : (z == 1) ? Wk : Wv;
    const float* b = (z == 0) ? bq : (z == 1) ? bk : bv;
    float*       C = (z == 0) ? Cq : (z == 1) ? Ck : Cv;
    const float alpha = (z == 0) ? 0.03125f : 1.0f;  // softmax scale folded into Q
    gemm_body(A, W, b, C, MTOT, EMB, EMB, alpha);
}

// ===========================================================================
// Tensor-core flash attention (tf32 mma.sync), causal. (unchanged from R8)
// BQ=128, 4 warps, 32 q-rows per warp; BKT=64.
// ===========================================================================
#define ASTR 68
#define VSTR 72
#define ATTN_SMEM ((128*ASTR + 64*ASTR + 64*VSTR + 128*ASTR) * 4)

__global__ __launch_bounds__(128, 2) void attn_mma(
    const float* __restrict__ Q, const float* __restrict__ K,
    const float* __restrict__ V, float* __restrict__ O)
{
    extern __shared__ uint32_t sm[];
    uint32_t (*Qs)[ASTR] = reinterpret_cast<uint32_t(*)[ASTR]>(sm);
    uint32_t (*Ks)[ASTR] = reinterpret_cast<uint32_t(*)[ASTR]>(sm + 128*ASTR);
    uint32_t (*Vs)[VSTR] = reinterpret_cast<uint32_t(*)[VSTR]>(sm + 192*ASTR);
    uint32_t (*Ps)[ASTR] = reinterpret_cast<uint32_t(*)[ASTR]>(sm + 192*ASTR + 64*VSTR);

    const int tid  = threadIdx.x;
    const int lane = tid & 31;
    const int wid  = tid >> 5;
    const int lr   = lane >> 2;
    const int lc   = lane & 3;
    const int wq   = wid * 32;

    const int q0 = (gridDim.x - 1 - blockIdx.x) * 128;
    const int h  = blockIdx.y;
    const int nb = blockIdx.z;

    const float* qbase = Q + (size_t)nb * SEQ * EMB + h * HDIM;
    const float* kbase = K + (size_t)nb * SEQ * EMB + h * HDIM;
    const float* vbase = V + (size_t)nb * SEQ * EMB + h * HDIM;

    #pragma unroll
    for (int i = 0; i < 16; i++) {
        const int idx = tid + i * 128;
        const int row = idx >> 4, c4 = idx & 15;
        float4 v = *reinterpret_cast<const float4*>(
            &qbase[(size_t)(q0 + row) * EMB + c4 * 4]);
        *reinterpret_cast<uint4*>(&Qs[row][c4 * 4]) =
            make_uint4(f2tf32(v.x), f2tf32(v.y), f2tf32(v.z), f2tf32(v.w));
    }

    float mrow[2][2], lsum[2][2];
    #pragma unroll
    for (int t = 0; t < 2; t++) {
        mrow[t][0] = -1e30f; mrow[t][1] = -1e30f;
        lsum[t][0] = 0.f;    lsum[t][1] = 0.f;
    }
    float oacc[2][8][4];
    #pragma unroll
    for (int t = 0; t < 2; t++)
        #pragma unroll
        for (int j = 0; j < 8; j++)
            #pragma unroll
            for (int r = 0; r < 4; r++) oacc[t][j][r] = 0.f;

    const int nkt = (q0 + 128) / 64;
    for (int kt = 0; kt < nkt; kt++) {
        const int kb = kt * 64;
        __syncthreads();

        #pragma unroll
        for (int i = 0; i < 8; i++) {
            const int idx = tid + i * 128;
            const int row = idx >> 4, c4 = idx & 15;
            float4 kv = *reinterpret_cast<const float4*>(
                &kbase[(size_t)(kb + row) * EMB + c4 * 4]);
            *reinterpret_cast<uint4*>(&Ks[row][c4 * 4]) =
                make_uint4(f2tf32(kv.x), f2tf32(kv.y), f2tf32(kv.z), f2tf32(kv.w));
            float4 vv = *reinterpret_cast<const float4*>(
                &vbase[(size_t)(kb + row) * EMB + c4 * 4]);
            *reinterpret_cast<uint4*>(&Vs[row][c4 * 4]) =
                make_uint4(f2tf32(vv.x), f2tf32(vv.y), f2tf32(vv.z), f2tf32(vv.w));
        }
        __syncthreads();

        if (kb > q0 + wq + 31) continue;

        float sacc[2][8][4];
        #pragma unroll
        for (int t = 0; t < 2; t++)
            #pragma unroll
            for (int j = 0; j < 8; j++)
                #pragma unroll
                for (int r = 0; r < 4; r++) sacc[t][j][r] = 0.f;

        #pragma unroll
        for (int s = 0; s < 8; s++) {
            uint32_t af[2][4];
            #pragma unroll
            for (int t = 0; t < 2; t++) {
                const int mr = wq + t * 16 + lr;
                af[t][0] = Qs[mr    ][s*8 + lc    ];
                af[t][1] = Qs[mr + 8][s*8 + lc    ];
                af[t][2] = Qs[mr    ][s*8 + lc + 4];
                af[t][3] = Qs[mr + 8][s*8 + lc + 4];
            }
            #pragma unroll
            for (int j = 0; j < 8; j++) {
                uint32_t bf[2];
                bf[0] = Ks[j*8 + lr][s*8 + lc    ];
                bf[1] = Ks[j*8 + lr][s*8 + lc + 4];
                mma_tf32(sacc[0][j], af[0], bf);
                mma_tf32(sacc[1][j], af[1], bf);
            }
        }

        if (kb + 63 > q0 + wq) {
            #pragma unroll
            for (int t = 0; t < 2; t++) {
                const int r0 = q0 + wq + t*16 + lr, r1 = r0 + 8;
                #pragma unroll
                for (int j = 0; j < 8; j++) {
                    const int c0 = kb + j*8 + 2*lc, c1 = c0 + 1;
                    if (c0 > r0) sacc[t][j][0] = -1e30f;
                    if (c1 > r0) sacc[t][j][1] = -1e30f;
                    if (c0 > r1) sacc[t][j][2] = -1e30f;
                    if (c1 > r1) sacc[t][j][3] = -1e30f;
                }
            }
        }

        #pragma unroll
        for (int t = 0; t < 2; t++) {
            float mt0 = -1e30f, mt1 = -1e30f;
            #pragma unroll
            for (int j = 0; j < 8; j++) {
                mt0 = fmaxf(mt0, fmaxf(sacc[t][j][0], sacc[t][j][1]));
                mt1 = fmaxf(mt1, fmaxf(sacc[t][j][2], sacc[t][j][3]));
            }
            mt0 = fmaxf(mt0, __shfl_xor_sync(0xffffffffu, mt0, 1));
            mt0 = fmaxf(mt0, __shfl_xor_sync(0xffffffffu, mt0, 2));
            mt1 = fmaxf(mt1, __shfl_xor_sync(0xffffffffu, mt1, 1));
            mt1 = fmaxf(mt1, __shfl_xor_sync(0xffffffffu, mt1, 2));

            const float mn0 = fmaxf(mrow[t][0], mt0);
            const float mn1 = fmaxf(mrow[t][1], mt1);
            const float cor0 = __expf(mrow[t][0] - mn0);
            const float cor1 = __expf(mrow[t][1] - mn1);
            mrow[t][0] = mn0; mrow[t][1] = mn1;

            float ls0 = 0.f, ls1 = 0.f;
            #pragma unroll
            for (int j = 0; j < 8; j++) {
                sacc[t][j][0] = __expf(sacc[t][j][0] - mn0);
                sacc[t][j][1] = __expf(sacc[t][j][1] - mn0);
                sacc[t][j][2] = __expf(sacc[t][j][2] - mn1);
                sacc[t][j][3] = __expf(sacc[t][j][3] - mn1);
                ls0 += sacc[t][j][0] + sacc[t][j][1];
                ls1 += sacc[t][j][2] + sacc[t][j][3];
            }
            ls0 += __shfl_xor_sync(0xffffffffu, ls0, 1);
            ls0 += __shfl_xor_sync(0xffffffffu, ls0, 2);
            ls1 += __shfl_xor_sync(0xffffffffu, ls1, 1);
            ls1 += __shfl_xor_sync(0xffffffffu, ls1, 2);
            lsum[t][0] = lsum[t][0] * cor0 + ls0;
            lsum[t][1] = lsum[t][1] * cor1 + ls1;

            #pragma unroll
            for (int j = 0; j < 8; j++) {
                oacc[t][j][0] *= cor0; oacc[t][j][1] *= cor0;
                oacc[t][j][2] *= cor1; oacc[t][j][3] *= cor1;
            }
        }

        #pragma unroll
        for (int t = 0; t < 2; t++) {
            const int mr = wq + t * 16 + lr;
            #pragma unroll
            for (int j = 0; j < 8; j++) {
                *reinterpret_cast<uint2*>(&Ps[mr    ][j*8 + 2*lc]) =
                    make_uint2(f2tf32(sacc[t][j][0]), f2tf32(sacc[t][j][1]));
                *reinterpret_cast<uint2*>(&Ps[mr + 8][j*8 + 2*lc]) =
                    make_uint2(f2tf32(sacc[t][j][2]), f2tf32(sacc[t][j][3]));
            }
        }
        __syncwarp();

        #pragma unroll
        for (int s = 0; s < 8; s++) {
            uint32_t af[2][4];
            #pragma unroll
            for (int t = 0; t < 2; t++) {
                const int mr = wq + t * 16 + lr;
                af[t][0] = Ps[mr    ][s*8 + lc    ];
                af[t][1] = Ps[mr + 8][s*8 + lc    ];
                af[t][2] = Ps[mr    ][s*8 + lc + 4];
                af[t][3] = Ps[mr + 8][s*8 + lc + 4];
            }
            #pragma unroll
            for (int j = 0; j < 8; j++) {
                uint32_t bf[2];
                bf[0] = Vs[s*8 + lc    ][j*8 + lr];
                bf[1] = Vs[s*8 + lc + 4][j*8 + lr];
                mma_tf32(oacc[0][j], af[0], bf);
                mma_tf32(oacc[1][j], af[1], bf);
            }
        }
        __syncwarp();
    }

    #pragma unroll
    for (int t = 0; t < 2; t++) {
        const float inv0 = 1.f / lsum[t][0];
        const float inv1 = 1.f / lsum[t][1];
        const size_t row0 = (size_t)nb * SEQ + q0 + wq + t*16 + lr;
        const size_t row1 = row0 + 8;
        #pragma unroll
        for (int j = 0; j < 8; j++) {
            const int col = h * HDIM + j*8 + 2*lc;
            *reinterpret_cast<float2*>(&O[row0 * EMB + col]) =
                make_float2(oacc[t][j][0] * inv0, oacc[t][j][1] * inv0);
            *reinterpret_cast<float2*>(&O[row1 * EMB + col]) =
                make_float2(oacc[t][j][2] * inv1, oacc[t][j][3] * inv1);
        }
    }
}

// ---------------------------------------------------------------------------
// Inputs: 0 values, 1 keys, 2 query, 3 mask(unused), 4 Wv, 5 bv, 6 Wk, 7 bk,
//         8 Wq, 9 bq, 10 Wo, 11 bo
// ---------------------------------------------------------------------------
extern "C" void kernel_launch(void* const* d_in, const int* in_sizes, int n_in,
                              void* d_out, int out_size)
{
    const float* values = (const float*)d_in[0];
    const float* keys   = (const float*)d_in[1];
    const float* query  = (const float*)d_in[2];
    const float* Wv = (const float*)d_in[4];
    const float* bv = (const float*)d_in[5];
    const float* Wk = (const float*)d_in[6];
    const float* bk = (const float*)d_in[7];
    const float* Wq = (const float*)d_in[8];
    const float* bq = (const float*)d_in[9];
    const float* Wo = (const float*)d_in[10];
    const float* bo = (const float*)d_in[11];
    float* out = (float*)d_out;

    float *pq, *pk, *pv, *pa;
    cudaGetSymbolAddress((void**)&pq, g_q);
    cudaGetSymbolAddress((void**)&pk, g_k);
    cudaGetSymbolAddress((void**)&pv, g_v);
    cudaGetSymbolAddress((void**)&pa, g_ao);

    cudaFuncSetAttribute(attn_mma,
                         cudaFuncAttributeMaxDynamicSharedMemorySize, ATTN_SMEM);
    cudaFuncSetAttribute(gemm_qkv,
                         cudaFuncAttributeMaxDynamicSharedMemorySize, GEMM_SMEM);
    cudaFuncSetAttribute(gemm_mma,
                         cudaFuncAttributeMaxDynamicSharedMemorySize, GEMM_SMEM);

    // Fused Q/K/V projections: 8 x 32 x 3 = 768 CTAs
    dim3 gqkv(EMB / 128, MTOT / 128, 3);
    gemm_qkv<<<gqkv, 256, GEMM_SMEM>>>(query, keys, values,
                                       Wq, Wk, Wv, bq, bk, bv,
                                       pq, pk, pv);

    dim3 gattn(SEQ / 128, NHEAD, N_BATCH);  // 16 x 16 x 2 = 512 blocks
    attn_mma<<<gattn, 128, ATTN_SMEM>>>(pq, pk, pv, pa);

    dim3 gproj(EMB / 128, MTOT / 128);
    gemm_mma<<<gproj, 256, GEMM_SMEM>>>(pa, Wo, bo, out, MTOT, EMB, EMB, 1.0f);
}

// round 10
// speedup vs baseline: 3.6258x; 1.0375x over previous
#include <cuda_runtime.h>
#include <cstdint>

#define N_BATCH 2
#define SEQ     2048
#define EMB     1024
#define NHEAD   16
#define HDIM    64
#define MTOT    (N_BATCH*SEQ)   // 4096

// Scratch (allocation-free rule: __device__ globals)
__device__ float g_q[(size_t)MTOT*EMB];
__device__ float g_k[(size_t)MTOT*EMB];
__device__ float g_v[(size_t)MTOT*EMB];
__device__ float g_ao[(size_t)MTOT*EMB];

__device__ __forceinline__ uint32_t f2tf32(float f) {
    uint32_t u;
    asm("cvt.rna.tf32.f32 %0, %1;" : "=r"(u) : "f"(f));
    return u;
}

__device__ __forceinline__ void mma_tf32(
    float c[4], const uint32_t a[4], const uint32_t b[2])
{
    asm volatile(
        "mma.sync.aligned.m16n8k8.row.col.f32.tf32.tf32.f32 "
        "{%0,%1,%2,%3}, {%4,%5,%6,%7}, {%8,%9}, {%0,%1,%2,%3};"
        : "+f"(c[0]), "+f"(c[1]), "+f"(c[2]), "+f"(c[3])
        : "r"(a[0]), "r"(a[1]), "r"(a[2]), "r"(a[3]), "r"(b[0]), "r"(b[1]));
}

// ===========================================================================
// tf32 mma.sync GEMM: C = alpha * (A[M,K] @ B[N,K]^T + bias[N])
// R10: 128 threads / 4 warps, CTA 128x128, warp tile 64x64, BK=16,
//      double-buffered. Swizzled [row][16] layout:
//        word (row,k) at row*16 + ((k>>2 ^ ((row>>1)&3))<<2) + (k&3)
//      STS.128 staging and all fragment LDS conflict-free.
//      1.0 crossbar-wavefront per MMA (was 1.5).
// ===========================================================================
#define GEMM_SMEM (2 * 2 * 2048 * 4)   // 32768 B

__device__ __forceinline__ void gemm_body(
    const float* __restrict__ A, const float* __restrict__ B,
    const float* __restrict__ bias, float* __restrict__ C,
    int M, int N, int K, float alpha)
{
    extern __shared__ uint32_t gsm[];
    uint32_t* Asm = gsm;             // [2][2048]
    uint32_t* Bsm = gsm + 2 * 2048;  // [2][2048]

    const int tid  = threadIdx.x;
    const int lane = tid & 31;
    const int wid  = tid >> 5;          // 0..3
    const int wm   = (wid & 1) * 64;
    const int wn   = (wid >> 1) * 64;
    const int m0 = blockIdx.y * 128;
    const int n0 = blockIdx.x * 128;

    const int lr = lane >> 2;
    const int lc = lane & 3;

    // staging: thread -> rows (tid>>2) + 32*i, chunk c4 = tid&3
    const int srow = tid >> 2;          // 0..31
    const int sc4  = tid & 3;

    float acc[4][8][4];
    #pragma unroll
    for (int i = 0; i < 4; i++)
        #pragma unroll
        for (int j = 0; j < 8; j++)
            #pragma unroll
            for (int r = 0; r < 4; r++) acc[i][j][r] = 0.f;

    // swizzled word offset for (row, c4-chunk)
    auto swoff = [](int row, int c4) -> uint32_t {
        return (uint32_t)(row * 16 + (((c4 ^ ((row >> 1) & 3)) & 3) << 2));
    };

    // ---- preload chunk 0 into buffer 0 ----
    #pragma unroll
    for (int i = 0; i < 4; i++) {
        const int row = srow + i * 32;
        const uint32_t so = swoff(row, sc4);
        float4 a = *reinterpret_cast<const float4*>(&A[(size_t)(m0 + row) * K + sc4 * 4]);
        *reinterpret_cast<uint4*>(&Asm[so]) =
            make_uint4(f2tf32(a.x), f2tf32(a.y), f2tf32(a.z), f2tf32(a.w));
        float4 b = *reinterpret_cast<const float4*>(&B[(size_t)(n0 + row) * K + sc4 * 4]);
        *reinterpret_cast<uint4*>(&Bsm[so]) =
            make_uint4(f2tf32(b.x), f2tf32(b.y), f2tf32(b.z), f2tf32(b.w));
    }
    __syncthreads();

    const int nk = K / 16;
    for (int kc = 0; kc < nk; kc++) {
        const int buf = kc & 1;
        const uint32_t* Ab = Asm + buf * 2048;
        const uint32_t* Bb = Bsm + buf * 2048;

        float4 na[4], nb[4];
        const bool more = (kc + 1 < nk);
        if (more) {
            const int koff = (kc + 1) * 16 + sc4 * 4;
            #pragma unroll
            for (int i = 0; i < 4; i++) {
                const int row = srow + i * 32;
                na[i] = *reinterpret_cast<const float4*>(&A[(size_t)(m0 + row) * K + koff]);
                nb[i] = *reinterpret_cast<const float4*>(&B[(size_t)(n0 + row) * K + koff]);
            }
        }

        // 2 k8-steps per chunk
        #pragma unroll
        for (int s = 0; s < 2; s++) {
            uint32_t af[4][4], bf[8][2];
            #pragma unroll
            for (int i = 0; i < 4; i++) {
                const int row = wm + i * 16 + lr;       // rows row, row+8 share swizzle
                const uint32_t g = (uint32_t)((row >> 1) & 3);
                const uint32_t x0 = (((uint32_t)(2*s)     ^ g) & 3) << 2;
                const uint32_t x1 = (((uint32_t)(2*s + 1) ^ g) & 3) << 2;
                const uint32_t ra = (uint32_t)row * 16;
                af[i][0] = Ab[ra       + x0 + lc];
                af[i][1] = Ab[ra + 128 + x0 + lc];      // +8 rows = +128 words
                af[i][2] = Ab[ra       + x1 + lc];
                af[i][3] = Ab[ra + 128 + x1 + lc];
            }
            #pragma unroll
            for (int j = 0; j < 8; j++) {
                const int row = wn + j * 8 + lr;
                const uint32_t g = (uint32_t)((row >> 1) & 3);
                const uint32_t x0 = (((uint32_t)(2*s)     ^ g) & 3) << 2;
                const uint32_t x1 = (((uint32_t)(2*s + 1) ^ g) & 3) << 2;
                const uint32_t rb = (uint32_t)row * 16;
                bf[j][0] = Bb[rb + x0 + lc];
                bf[j][1] = Bb[rb + x1 + lc];
            }
            #pragma unroll
            for (int i = 0; i < 4; i++)
                #pragma unroll
                for (int j = 0; j < 8; j++)
                    mma_tf32(acc[i][j], af[i], bf[j]);
        }

        if (more) {
            uint32_t* An = Asm + (buf ^ 1) * 2048;
            uint32_t* Bn = Bsm + (buf ^ 1) * 2048;
            #pragma unroll
            for (int i = 0; i < 4; i++) {
                const int row = srow + i * 32;
                const uint32_t so = swoff(row, sc4);
                *reinterpret_cast<uint4*>(&An[so]) =
                    make_uint4(f2tf32(na[i].x), f2tf32(na[i].y), f2tf32(na[i].z), f2tf32(na[i].w));
                *reinterpret_cast<uint4*>(&Bn[so]) =
                    make_uint4(f2tf32(nb[i].x), f2tf32(nb[i].y), f2tf32(nb[i].z), f2tf32(nb[i].w));
            }
        }
        __syncthreads();
    }

    // ---- epilogue ----
    #pragma unroll
    for (int j = 0; j < 8; j++) {
        const int col = n0 + wn + j * 8 + lc * 2;
        const float b0 = bias[col], b1 = bias[col + 1];
        #pragma unroll
        for (int i = 0; i < 4; i++) {
            const int row = m0 + wm + i * 16 + lr;
            float2 o0, o1;
            o0.x = alpha * (acc[i][j][0] + b0);
            o0.y = alpha * (acc[i][j][1] + b1);
            o1.x = alpha * (acc[i][j][2] + b0);
            o1.y = alpha * (acc[i][j][3] + b1);
            *reinterpret_cast<float2*>(&C[(size_t)row * N + col])       = o0;
            *reinterpret_cast<float2*>(&C[(size_t)(row + 8) * N + col]) = o1;
        }
    }
}

__global__ __launch_bounds__(128, 2) void gemm_mma(
    const float* __restrict__ A, const float* __restrict__ B,
    const float* __restrict__ bias, float* __restrict__ C,
    int M, int N, int K, float alpha)
{
    gemm_body(A, B, bias, C, M, N, K, alpha);
}

// Fused QKV: one launch, blockIdx.z selects the projection.
__global__ __launch_bounds__(128, 2) void gemm_qkv(
    const float* __restrict__ Aq, const float* __restrict__ Ak, const float* __restrict__ Av,
    const float* __restrict__ Wq, const float* __restrict__ Wk, const float* __restrict__ Wv,
    const float* __restrict__ bq, const float* __restrict__ bk, const float* __restrict__ bv,
    float* __restrict__ Cq, float* __restrict__ Ck, float* __restrict__ Cv)
{
    const int z = blockIdx.z;
    const float* A = (z == 0) ? Aq : (z == 1) ? Ak : Av;
    const float* W = (z == 0) ? Wq : (z == 1) ? Wk : Wv;
    const float* b = (z == 0) ? bq : (z == 1) ? bk : bv;
    float*       C = (z == 0) ? Cq : (z == 1) ? Ck : Cv;
    const float alpha = (z == 0) ? 0.03125f : 1.0f;  // softmax scale folded into Q
    gemm_body(A, W, b, C, MTOT, EMB, EMB, alpha);
}

// ===========================================================================
// Tensor-core flash attention (tf32 mma.sync), causal. (unchanged from R8/R9)
// BQ=128, 4 warps, 32 q-rows per warp; BKT=64.
// ===========================================================================
#define ASTR 68
#define VSTR 72
#define ATTN_SMEM ((128*ASTR + 64*ASTR + 64*VSTR + 128*ASTR) * 4)

__global__ __launch_bounds__(128, 2) void attn_mma(
    const float* __restrict__ Q, const float* __restrict__ K,
    const float* __restrict__ V, float* __restrict__ O)
{
    extern __shared__ uint32_t sm[];
    uint32_t (*Qs)[ASTR] = reinterpret_cast<uint32_t(*)[ASTR]>(sm);
    uint32_t (*Ks)[ASTR] = reinterpret_cast<uint32_t(*)[ASTR]>(sm + 128*ASTR);
    uint32_t (*Vs)[VSTR] = reinterpret_cast<uint32_t(*)[VSTR]>(sm + 192*ASTR);
    uint32_t (*Ps)[ASTR] = reinterpret_cast<uint32_t(*)[ASTR]>(sm + 192*ASTR + 64*VSTR);

    const int tid  = threadIdx.x;
    const int lane = tid & 31;
    const int wid  = tid >> 5;
    const int lr   = lane >> 2;
    const int lc   = lane & 3;
    const int wq   = wid * 32;

    const int q0 = (gridDim.x - 1 - blockIdx.x) * 128;
    const int h  = blockIdx.y;
    const int nb = blockIdx.z;

    const float* qbase = Q + (size_t)nb * SEQ * EMB + h * HDIM;
    const float* kbase = K + (size_t)nb * SEQ * EMB + h * HDIM;
    const float* vbase = V + (size_t)nb * SEQ * EMB + h * HDIM;

    #pragma unroll
    for (int i = 0; i < 16; i++) {
        const int idx = tid + i * 128;
        const int row = idx >> 4, c4 = idx & 15;
        float4 v = *reinterpret_cast<const float4*>(
            &qbase[(size_t)(q0 + row) * EMB + c4 * 4]);
        *reinterpret_cast<uint4*>(&Qs[row][c4 * 4]) =
            make_uint4(f2tf32(v.x), f2tf32(v.y), f2tf32(v.z), f2tf32(v.w));
    }

    float mrow[2][2], lsum[2][2];
    #pragma unroll
    for (int t = 0; t < 2; t++) {
        mrow[t][0] = -1e30f; mrow[t][1] = -1e30f;
        lsum[t][0] = 0.f;    lsum[t][1] = 0.f;
    }
    float oacc[2][8][4];
    #pragma unroll
    for (int t = 0; t < 2; t++)
        #pragma unroll
        for (int j = 0; j < 8; j++)
            #pragma unroll
            for (int r = 0; r < 4; r++) oacc[t][j][r] = 0.f;

    const int nkt = (q0 + 128) / 64;
    for (int kt = 0; kt < nkt; kt++) {
        const int kb = kt * 64;
        __syncthreads();

        #pragma unroll
        for (int i = 0; i < 8; i++) {
            const int idx = tid + i * 128;
            const int row = idx >> 4, c4 = idx & 15;
            float4 kv = *reinterpret_cast<const float4*>(
                &kbase[(size_t)(kb + row) * EMB + c4 * 4]);
            *reinterpret_cast<uint4*>(&Ks[row][c4 * 4]) =
                make_uint4(f2tf32(kv.x), f2tf32(kv.y), f2tf32(kv.z), f2tf32(kv.w));
            float4 vv = *reinterpret_cast<const float4*>(
                &vbase[(size_t)(kb + row) * EMB + c4 * 4]);
            *reinterpret_cast<uint4*>(&Vs[row][c4 * 4]) =
                make_uint4(f2tf32(vv.x), f2tf32(vv.y), f2tf32(vv.z), f2tf32(vv.w));
        }
        __syncthreads();

        if (kb > q0 + wq + 31) continue;

        float sacc[2][8][4];
        #pragma unroll
        for (int t = 0; t < 2; t++)
            #pragma unroll
            for (int j = 0; j < 8; j++)
                #pragma unroll
                for (int r = 0; r < 4; r++) sacc[t][j][r] = 0.f;

        #pragma unroll
        for (int s = 0; s < 8; s++) {
            uint32_t af[2][4];
            #pragma unroll
            for (int t = 0; t < 2; t++) {
                const int mr = wq + t * 16 + lr;
                af[t][0] = Qs[mr    ][s*8 + lc    ];
                af[t][1] = Qs[mr + 8][s*8 + lc    ];
                af[t][2] = Qs[mr    ][s*8 + lc + 4];
                af[t][3] = Qs[mr + 8][s*8 + lc + 4];
            }
            #pragma unroll
            for (int j = 0; j < 8; j++) {
                uint32_t bf[2];
                bf[0] = Ks[j*8 + lr][s*8 + lc    ];
                bf[1] = Ks[j*8 + lr][s*8 + lc + 4];
                mma_tf32(sacc[0][j], af[0], bf);
                mma_tf32(sacc[1][j], af[1], bf);
            }
        }

        if (kb + 63 > q0 + wq) {
            #pragma unroll
            for (int t = 0; t < 2; t++) {
                const int r0 = q0 + wq + t*16 + lr, r1 = r0 + 8;
                #pragma unroll
                for (int j = 0; j < 8; j++) {
                    const int c0 = kb + j*8 + 2*lc, c1 = c0 + 1;
                    if (c0 > r0) sacc[t][j][0] = -1e30f;
                    if (c1 > r0) sacc[t][j][1] = -1e30f;
                    if (c0 > r1) sacc[t][j][2] = -1e30f;
                    if (c1 > r1) sacc[t][j][3] = -1e30f;
                }
            }
        }

        #pragma unroll
        for (int t = 0; t < 2; t++) {
            float mt0 = -1e30f, mt1 = -1e30f;
            #pragma unroll
            for (int j = 0; j < 8; j++) {
                mt0 = fmaxf(mt0, fmaxf(sacc[t][j][0], sacc[t][j][1]));
                mt1 = fmaxf(mt1, fmaxf(sacc[t][j][2], sacc[t][j][3]));
            }
            mt0 = fmaxf(mt0, __shfl_xor_sync(0xffffffffu, mt0, 1));
            mt0 = fmaxf(mt0, __shfl_xor_sync(0xffffffffu, mt0, 2));
            mt1 = fmaxf(mt1, __shfl_xor_sync(0xffffffffu, mt1, 1));
            mt1 = fmaxf(mt1, __shfl_xor_sync(0xffffffffu, mt1, 2));

            const float mn0 = fmaxf(mrow[t][0], mt0);
            const float mn1 = fmaxf(mrow[t][1], mt1);
            const float cor0 = __expf(mrow[t][0] - mn0);
            const float cor1 = __expf(mrow[t][1] - mn1);
            mrow[t][0] = mn0; mrow[t][1] = mn1;

            float ls0 = 0.f, ls1 = 0.f;
            #pragma unroll
            for (int j = 0; j < 8; j++) {
                sacc[t][j][0] = __expf(sacc[t][j][0] - mn0);
                sacc[t][j][1] = __expf(sacc[t][j][1] - mn0);
                sacc[t][j][2] = __expf(sacc[t][j][2] - mn1);
                sacc[t][j][3] = __expf(sacc[t][j][3] - mn1);
                ls0 += sacc[t][j][0] + sacc[t][j][1];
                ls1 += sacc[t][j][2] + sacc[t][j][3];
            }
            ls0 += __shfl_xor_sync(0xffffffffu, ls0, 1);
            ls0 += __shfl_xor_sync(0xffffffffu, ls0, 2);
            ls1 += __shfl_xor_sync(0xffffffffu, ls1, 1);
            ls1 += __shfl_xor_sync(0xffffffffu, ls1, 2);
            lsum[t][0] = lsum[t][0] * cor0 + ls0;
            lsum[t][1] = lsum[t][1] * cor1 + ls1;

            #pragma unroll
            for (int j = 0; j < 8; j++) {
                oacc[t][j][0] *= cor0; oacc[t][j][1] *= cor0;
                oacc[t][j][2] *= cor1; oacc[t][j][3] *= cor1;
            }
        }

        #pragma unroll
        for (int t = 0; t < 2; t++) {
            const int mr = wq + t * 16 + lr;
            #pragma unroll
            for (int j = 0; j < 8; j++) {
                *reinterpret_cast<uint2*>(&Ps[mr    ][j*8 + 2*lc]) =
                    make_uint2(f2tf32(sacc[t][j][0]), f2tf32(sacc[t][j][1]));
                *reinterpret_cast<uint2*>(&Ps[mr + 8][j*8 + 2*lc]) =
                    make_uint2(f2tf32(sacc[t][j][2]), f2tf32(sacc[t][j][3]));
            }
        }
        __syncwarp();

        #pragma unroll
        for (int s = 0; s < 8; s++) {
            uint32_t af[2][4];
            #pragma unroll
            for (int t = 0; t < 2; t++) {
                const int mr = wq + t * 16 + lr;
                af[t][0] = Ps[mr    ][s*8 + lc    ];
                af[t][1] = Ps[mr + 8][s*8 + lc    ];
                af[t][2] = Ps[mr    ][s*8 + lc + 4];
                af[t][3] = Ps[mr + 8][s*8 + lc + 4];
            }
            #pragma unroll
            for (int j = 0; j < 8; j++) {
                uint32_t bf[2];
                bf[0] = Vs[s*8 + lc    ][j*8 + lr];
                bf[1] = Vs[s*8 + lc + 4][j*8 + lr];
                mma_tf32(oacc[0][j], af[0], bf);
                mma_tf32(oacc[1][j], af[1], bf);
            }
        }
        __syncwarp();
    }

    #pragma unroll
    for (int t = 0; t < 2; t++) {
        const float inv0 = 1.f / lsum[t][0];
        const float inv1 = 1.f / lsum[t][1];
        const size_t row0 = (size_t)nb * SEQ + q0 + wq + t*16 + lr;
        const size_t row1 = row0 + 8;
        #pragma unroll
        for (int j = 0; j < 8; j++) {
            const int col = h * HDIM + j*8 + 2*lc;
            *reinterpret_cast<float2*>(&O[row0 * EMB + col]) =
                make_float2(oacc[t][j][0] * inv0, oacc[t][j][1] * inv0);
            *reinterpret_cast<float2*>(&O[row1 * EMB + col]) =
                make_float2(oacc[t][j][2] * inv1, oacc[t][j][3] * inv1);
        }
    }
}

// ---------------------------------------------------------------------------
// Inputs: 0 values, 1 keys, 2 query, 3 mask(unused), 4 Wv, 5 bv, 6 Wk, 7 bk,
//         8 Wq, 9 bq, 10 Wo, 11 bo
// ---------------------------------------------------------------------------
extern "C" void kernel_launch(void* const* d_in, const int* in_sizes, int n_in,
                              void* d_out, int out_size)
{
    const float* values = (const float*)d_in[0];
    const float* keys   = (const float*)d_in[1];
    const float* query  = (const float*)d_in[2];
    const float* Wv = (const float*)d_in[4];
    const float* bv = (const float*)d_in[5];
    const float* Wk = (const float*)d_in[6];
    const float* bk = (const float*)d_in[7];
    const float* Wq = (const float*)d_in[8];
    const float* bq = (const float*)d_in[9];
    const float* Wo = (const float*)d_in[10];
    const float* bo = (const float*)d_in[11];
    float* out = (float*)d_out;

    float *pq, *pk, *pv, *pa;
    cudaGetSymbolAddress((void**)&pq, g_q);
    cudaGetSymbolAddress((void**)&pk, g_k);
    cudaGetSymbolAddress((void**)&pv, g_v);
    cudaGetSymbolAddress((void**)&pa, g_ao);

    cudaFuncSetAttribute(attn_mma,
                         cudaFuncAttributeMaxDynamicSharedMemorySize, ATTN_SMEM);
    cudaFuncSetAttribute(gemm_qkv,
                         cudaFuncAttributeMaxDynamicSharedMemorySize, GEMM_SMEM);
    cudaFuncSetAttribute(gemm_mma,
                         cudaFuncAttributeMaxDynamicSharedMemorySize, GEMM_SMEM);

    // Fused Q/K/V projections: 8 x 32 x 3 = 768 CTAs
    dim3 gqkv(EMB / 128, MTOT / 128, 3);
    gemm_qkv<<<gqkv, 128, GEMM_SMEM>>>(query, keys, values,
                                       Wq, Wk, Wv, bq, bk, bv,
                                       pq, pk, pv);

    dim3 gattn(SEQ / 128, NHEAD, N_BATCH);  // 16 x 16 x 2 = 512 blocks
    attn_mma<<<gattn, 128, ATTN_SMEM>>>(pq, pk, pv, pa);

    dim3 gproj(EMB / 128, MTOT / 128);
    gemm_mma<<<gproj, 128, GEMM_SMEM>>>(pa, Wo, bo, out, MTOT, EMB, EMB, 1.0f);
}

// round 12
// speedup vs baseline: 3.6592x; 1.0092x over previous
#include <cuda_runtime.h>
#include <cstdint>

#define N_BATCH 2
#define SEQ     2048
#define EMB     1024
#define NHEAD   16
#define HDIM    64
#define MTOT    (N_BATCH*SEQ)   // 4096

// Scratch (allocation-free rule: __device__ globals)
__device__ float g_q[(size_t)MTOT*EMB];
__device__ float g_k[(size_t)MTOT*EMB];
__device__ float g_v[(size_t)MTOT*EMB];
__device__ float g_ao[(size_t)MTOT*EMB];

__device__ __forceinline__ uint32_t f2tf32(float f) {
    uint32_t u;
    asm("cvt.rna.tf32.f32 %0, %1;" : "=r"(u) : "f"(f));
    return u;
}

__device__ __forceinline__ void mma_tf32(
    float c[4], const uint32_t a[4], const uint32_t b[2])
{
    asm volatile(
        "mma.sync.aligned.m16n8k8.row.col.f32.tf32.tf32.f32 "
        "{%0,%1,%2,%3}, {%4,%5,%6,%7}, {%8,%9}, {%0,%1,%2,%3};"
        : "+f"(c[0]), "+f"(c[1]), "+f"(c[2]), "+f"(c[3])
        : "r"(a[0]), "r"(a[1]), "r"(a[2]), "r"(a[3]), "r"(b[0]), "r"(b[1]));
}

// ===========================================================================
// tf32 mma.sync GEMM (unchanged from R10)
// 128 threads / 4 warps, CTA 128x128, warp tile 64x64, BK=16, double-buffered.
// ===========================================================================
#define GEMM_SMEM (2 * 2 * 2048 * 4)   // 32768 B

__device__ __forceinline__ void gemm_body(
    const float* __restrict__ A, const float* __restrict__ B,
    const float* __restrict__ bias, float* __restrict__ C,
    int M, int N, int K, float alpha)
{
    extern __shared__ uint32_t gsm[];
    uint32_t* Asm = gsm;             // [2][2048]
    uint32_t* Bsm = gsm + 2 * 2048;  // [2][2048]

    const int tid  = threadIdx.x;
    const int lane = tid & 31;
    const int wid  = tid >> 5;
    const int wm   = (wid & 1) * 64;
    const int wn   = (wid >> 1) * 64;
    const int m0 = blockIdx.y * 128;
    const int n0 = blockIdx.x * 128;

    const int lr = lane >> 2;
    const int lc = lane & 3;

    const int srow = tid >> 2;
    const int sc4  = tid & 3;

    float acc[4][8][4];
    #pragma unroll
    for (int i = 0; i < 4; i++)
        #pragma unroll
        for (int j = 0; j < 8; j++)
            #pragma unroll
            for (int r = 0; r < 4; r++) acc[i][j][r] = 0.f;

    auto swoff = [](int row, int c4) -> uint32_t {
        return (uint32_t)(row * 16 + (((c4 ^ ((row >> 1) & 3)) & 3) << 2));
    };

    #pragma unroll
    for (int i = 0; i < 4; i++) {
        const int row = srow + i * 32;
        const uint32_t so = swoff(row, sc4);
        float4 a = *reinterpret_cast<const float4*>(&A[(size_t)(m0 + row) * K + sc4 * 4]);
        *reinterpret_cast<uint4*>(&Asm[so]) =
            make_uint4(f2tf32(a.x), f2tf32(a.y), f2tf32(a.z), f2tf32(a.w));
        float4 b = *reinterpret_cast<const float4*>(&B[(size_t)(n0 + row) * K + sc4 * 4]);
        *reinterpret_cast<uint4*>(&Bsm[so]) =
            make_uint4(f2tf32(b.x), f2tf32(b.y), f2tf32(b.z), f2tf32(b.w));
    }
    __syncthreads();

    const int nk = K / 16;
    for (int kc = 0; kc < nk; kc++) {
        const int buf = kc & 1;
        const uint32_t* Ab = Asm + buf * 2048;
        const uint32_t* Bb = Bsm + buf * 2048;

        float4 na[4], nb[4];
        const bool more = (kc + 1 < nk);
        if (more) {
            const int koff = (kc + 1) * 16 + sc4 * 4;
            #pragma unroll
            for (int i = 0; i < 4; i++) {
                const int row = srow + i * 32;
                na[i] = *reinterpret_cast<const float4*>(&A[(size_t)(m0 + row) * K + koff]);
                nb[i] = *reinterpret_cast<const float4*>(&B[(size_t)(n0 + row) * K + koff]);
            }
        }

        #pragma unroll
        for (int s = 0; s < 2; s++) {
            uint32_t af[4][4], bf[8][2];
            #pragma unroll
            for (int i = 0; i < 4; i++) {
                const int row = wm + i * 16 + lr;
                const uint32_t g = (uint32_t)((row >> 1) & 3);
                const uint32_t x0 = (((uint32_t)(2*s)     ^ g) & 3) << 2;
                const uint32_t x1 = (((uint32_t)(2*s + 1) ^ g) & 3) << 2;
                const uint32_t ra = (uint32_t)row * 16;
                af[i][0] = Ab[ra       + x0 + lc];
                af[i][1] = Ab[ra + 128 + x0 + lc];
                af[i][2] = Ab[ra       + x1 + lc];
                af[i][3] = Ab[ra + 128 + x1 + lc];
            }
            #pragma unroll
            for (int j = 0; j < 8; j++) {
                const int row = wn + j * 8 + lr;
                const uint32_t g = (uint32_t)((row >> 1) & 3);
                const uint32_t x0 = (((uint32_t)(2*s)     ^ g) & 3) << 2;
                const uint32_t x1 = (((uint32_t)(2*s + 1) ^ g) & 3) << 2;
                const uint32_t rb = (uint32_t)row * 16;
                bf[j][0] = Bb[rb + x0 + lc];
                bf[j][1] = Bb[rb + x1 + lc];
            }
            #pragma unroll
            for (int i = 0; i < 4; i++)
                #pragma unroll
                for (int j = 0; j < 8; j++)
                    mma_tf32(acc[i][j], af[i], bf[j]);
        }

        if (more) {
            uint32_t* An = Asm + (buf ^ 1) * 2048;
            uint32_t* Bn = Bsm + (buf ^ 1) * 2048;
            #pragma unroll
            for (int i = 0; i < 4; i++) {
                const int row = srow + i * 32;
                const uint32_t so = swoff(row, sc4);
                *reinterpret_cast<uint4*>(&An[so]) =
                    make_uint4(f2tf32(na[i].x), f2tf32(na[i].y), f2tf32(na[i].z), f2tf32(na[i].w));
                *reinterpret_cast<uint4*>(&Bn[so]) =
                    make_uint4(f2tf32(nb[i].x), f2tf32(nb[i].y), f2tf32(nb[i].z), f2tf32(nb[i].w));
            }
        }
        __syncthreads();
    }

    #pragma unroll
    for (int j = 0; j < 8; j++) {
        const int col = n0 + wn + j * 8 + lc * 2;
        const float b0 = bias[col], b1 = bias[col + 1];
        #pragma unroll
        for (int i = 0; i < 4; i++) {
            const int row = m0 + wm + i * 16 + lr;
            float2 o0, o1;
            o0.x = alpha * (acc[i][j][0] + b0);
            o0.y = alpha * (acc[i][j][1] + b1);
            o1.x = alpha * (acc[i][j][2] + b0);
            o1.y = alpha * (acc[i][j][3] + b1);
            *reinterpret_cast<float2*>(&C[(size_t)row * N + col])       = o0;
            *reinterpret_cast<float2*>(&C[(size_t)(row + 8) * N + col]) = o1;
        }
    }
}

__global__ __launch_bounds__(128, 2) void gemm_mma(
    const float* __restrict__ A, const float* __restrict__ B,
    const float* __restrict__ bias, float* __restrict__ C,
    int M, int N, int K, float alpha)
{
    gemm_body(A, B, bias, C, M, N, K, alpha);
}

__global__ __launch_bounds__(128, 2) void gemm_qkv(
    const float* __restrict__ Aq, const float* __restrict__ Ak, const float* __restrict__ Av,
    const float* __restrict__ Wq, const float* __restrict__ Wk, const float* __restrict__ Wv,
    const float* __restrict__ bq, const float* __restrict__ bk, const float* __restrict__ bv,
    float* __restrict__ Cq, float* __restrict__ Ck, float* __restrict__ Cv)
{
    const int z = blockIdx.z;
    const float* A = (z == 0) ? Aq : (z == 1) ? Ak : Av;
    const float* W = (z == 0) ? Wq : (z == 1) ? Wk : Wv;
    const float* b = (z == 0) ? bq : (z == 1) ? bk : bv;
    float*       C = (z == 0) ? Cq : (z == 1) ? Ck : Cv;
    const float alpha = (z == 0) ? 0.03125f : 1.0f;
    gemm_body(A, W, b, C, MTOT, EMB, EMB, alpha);
}

// ===========================================================================
// Tensor-core flash attention (tf32 mma.sync), causal.
// R12 = R11 with the staging bug fixed: K tile 32x64 = 512 uint4 needs 4
// iterations of 128 threads (rows 0..31); V likewise, loaded in the SAME
// loop iteration (one row index serves both).
// BQ=128, 4 warps, 32 q-rows/warp; BKT=32; smem 69.5KB -> 3 CTAs/SM.
// ===========================================================================
#define ASTR 68
#define VSTR 72
#define PSTR 36
#define BKT  32
#define ATTN_SMEM ((128*ASTR + BKT*ASTR + BKT*VSTR + 128*PSTR) * 4)   // 71168 B

__global__ __launch_bounds__(128, 3) void attn_mma(
    const float* __restrict__ Q, const float* __restrict__ K,
    const float* __restrict__ V, float* __restrict__ O)
{
    extern __shared__ uint32_t sm[];
    uint32_t (*Qs)[ASTR] = reinterpret_cast<uint32_t(*)[ASTR]>(sm);
    uint32_t (*Ks)[ASTR] = reinterpret_cast<uint32_t(*)[ASTR]>(sm + 128*ASTR);
    uint32_t (*Vs)[VSTR] = reinterpret_cast<uint32_t(*)[VSTR]>(sm + 128*ASTR + BKT*ASTR);
    uint32_t (*Ps)[PSTR] = reinterpret_cast<uint32_t(*)[PSTR]>(sm + 128*ASTR + BKT*ASTR + BKT*VSTR);

    const int tid  = threadIdx.x;
    const int lane = tid & 31;
    const int wid  = tid >> 5;
    const int lr   = lane >> 2;
    const int lc   = lane & 3;
    const int wq   = wid * 32;

    const int q0 = (gridDim.x - 1 - blockIdx.x) * 128;   // heavy tiles first
    const int h  = blockIdx.y;
    const int nb = blockIdx.z;

    const float* qbase = Q + (size_t)nb * SEQ * EMB + h * HDIM;
    const float* kbase = K + (size_t)nb * SEQ * EMB + h * HDIM;
    const float* vbase = V + (size_t)nb * SEQ * EMB + h * HDIM;

    // ---- load Q tile (128 x 64), coalesced ----
    #pragma unroll
    for (int i = 0; i < 16; i++) {
        const int idx = tid + i * 128;
        const int row = idx >> 4, c4 = idx & 15;
        float4 v = *reinterpret_cast<const float4*>(
            &qbase[(size_t)(q0 + row) * EMB + c4 * 4]);
        *reinterpret_cast<uint4*>(&Qs[row][c4 * 4]) =
            make_uint4(f2tf32(v.x), f2tf32(v.y), f2tf32(v.z), f2tf32(v.w));
    }

    float mrow[2][2], lsum[2][2];
    #pragma unroll
    for (int t = 0; t < 2; t++) {
        mrow[t][0] = -1e30f; mrow[t][1] = -1e30f;
        lsum[t][0] = 0.f;    lsum[t][1] = 0.f;
    }
    float oacc[2][8][4];
    #pragma unroll
    for (int t = 0; t < 2; t++)
        #pragma unroll
        for (int j = 0; j < 8; j++)
            #pragma unroll
            for (int r = 0; r < 4; r++) oacc[t][j][r] = 0.f;

    const int nkt = (q0 + 128) / BKT;
    for (int kt = 0; kt < nkt; kt++) {
        const int kb = kt * BKT;
        __syncthreads();   // Qs ready (1st); prev Ks/Vs/Ps consumed

        // stage K (32x64) and V (32x64): 512 uint4 each, 4 iterations,
        // each iteration loads one row-chunk for BOTH K and V.
        #pragma unroll
        for (int i = 0; i < 4; i++) {
            const int idx = tid + i * 128;
            const int row = idx >> 4, c4 = idx & 15;   // row 0..31
            float4 kv = *reinterpret_cast<const float4*>(
                &kbase[(size_t)(kb + row) * EMB + c4 * 4]);
            *reinterpret_cast<uint4*>(&Ks[row][c4 * 4]) =
                make_uint4(f2tf32(kv.x), f2tf32(kv.y), f2tf32(kv.z), f2tf32(kv.w));
            float4 vv = *reinterpret_cast<const float4*>(
                &vbase[(size_t)(kb + row) * EMB + c4 * 4]);
            *reinterpret_cast<uint4*>(&Vs[row][c4 * 4]) =
                make_uint4(f2tf32(vv.x), f2tf32(vv.y), f2tf32(vv.z), f2tf32(vv.w));
        }
        __syncthreads();

        // skip k-tiles entirely above this warp's rows
        if (kb > q0 + wq + 31) continue;

        // ---- S = Q . K^T : 2 m-tiles x 4 j-tiles, 8 k-steps ----
        float sacc[2][4][4];
        #pragma unroll
        for (int t = 0; t < 2; t++)
            #pragma unroll
            for (int j = 0; j < 4; j++)
                #pragma unroll
                for (int r = 0; r < 4; r++) sacc[t][j][r] = 0.f;

        #pragma unroll
        for (int s = 0; s < 8; s++) {
            uint32_t af[2][4];
            #pragma unroll
            for (int t = 0; t < 2; t++) {
                const int mr = wq + t * 16 + lr;
                af[t][0] = Qs[mr    ][s*8 + lc    ];
                af[t][1] = Qs[mr + 8][s*8 + lc    ];
                af[t][2] = Qs[mr    ][s*8 + lc + 4];
                af[t][3] = Qs[mr + 8][s*8 + lc + 4];
            }
            #pragma unroll
            for (int j = 0; j < 4; j++) {
                uint32_t bf[2];
                bf[0] = Ks[j*8 + lr][s*8 + lc    ];
                bf[1] = Ks[j*8 + lr][s*8 + lc + 4];
                mma_tf32(sacc[0][j], af[0], bf);
                mma_tf32(sacc[1][j], af[1], bf);
            }
        }

        // ---- causal mask (tile crosses this warp's diagonal) ----
        if (kb + BKT - 1 > q0 + wq) {
            #pragma unroll
            for (int t = 0; t < 2; t++) {
                const int r0 = q0 + wq + t*16 + lr, r1 = r0 + 8;
                #pragma unroll
                for (int j = 0; j < 4; j++) {
                    const int c0 = kb + j*8 + 2*lc, c1 = c0 + 1;
                    if (c0 > r0) sacc[t][j][0] = -1e30f;
                    if (c1 > r0) sacc[t][j][1] = -1e30f;
                    if (c0 > r1) sacc[t][j][2] = -1e30f;
                    if (c1 > r1) sacc[t][j][3] = -1e30f;
                }
            }
        }

        // ---- online softmax per m-tile ----
        #pragma unroll
        for (int t = 0; t < 2; t++) {
            float mt0 = -1e30f, mt1 = -1e30f;
            #pragma unroll
            for (int j = 0; j < 4; j++) {
                mt0 = fmaxf(mt0, fmaxf(sacc[t][j][0], sacc[t][j][1]));
                mt1 = fmaxf(mt1, fmaxf(sacc[t][j][2], sacc[t][j][3]));
            }
            mt0 = fmaxf(mt0, __shfl_xor_sync(0xffffffffu, mt0, 1));
            mt0 = fmaxf(mt0, __shfl_xor_sync(0xffffffffu, mt0, 2));
            mt1 = fmaxf(mt1, __shfl_xor_sync(0xffffffffu, mt1, 1));
            mt1 = fmaxf(mt1, __shfl_xor_sync(0xffffffffu, mt1, 2));

            const float mn0 = fmaxf(mrow[t][0], mt0);
            const float mn1 = fmaxf(mrow[t][1], mt1);
            const float cor0 = __expf(mrow[t][0] - mn0);
            const float cor1 = __expf(mrow[t][1] - mn1);
            mrow[t][0] = mn0; mrow[t][1] = mn1;

            float ls0 = 0.f, ls1 = 0.f;
            #pragma unroll
            for (int j = 0; j < 4; j++) {
                sacc[t][j][0] = __expf(sacc[t][j][0] - mn0);
                sacc[t][j][1] = __expf(sacc[t][j][1] - mn0);
                sacc[t][j][2] = __expf(sacc[t][j][2] - mn1);
                sacc[t][j][3] = __expf(sacc[t][j][3] - mn1);
                ls0 += sacc[t][j][0] + sacc[t][j][1];
                ls1 += sacc[t][j][2] + sacc[t][j][3];
            }
            ls0 += __shfl_xor_sync(0xffffffffu, ls0, 1);
            ls0 += __shfl_xor_sync(0xffffffffu, ls0, 2);
            ls1 += __shfl_xor_sync(0xffffffffu, ls1, 1);
            ls1 += __shfl_xor_sync(0xffffffffu, ls1, 2);
            lsum[t][0] = lsum[t][0] * cor0 + ls0;
            lsum[t][1] = lsum[t][1] * cor1 + ls1;

            #pragma unroll
            for (int j = 0; j < 8; j++) {
                oacc[t][j][0] *= cor0; oacc[t][j][1] *= cor0;
                oacc[t][j][2] *= cor1; oacc[t][j][3] *= cor1;
            }
        }

        // ---- stage P (per-warp private rows, tf32) ----
        #pragma unroll
        for (int t = 0; t < 2; t++) {
            const int mr = wq + t * 16 + lr;
            #pragma unroll
            for (int j = 0; j < 4; j++) {
                *reinterpret_cast<uint2*>(&Ps[mr    ][j*8 + 2*lc]) =
                    make_uint2(f2tf32(sacc[t][j][0]), f2tf32(sacc[t][j][1]));
                *reinterpret_cast<uint2*>(&Ps[mr + 8][j*8 + 2*lc]) =
                    make_uint2(f2tf32(sacc[t][j][2]), f2tf32(sacc[t][j][3]));
            }
        }
        __syncwarp();

        // ---- O += P . V  (4 k-steps over 32 keys, 8 d-tiles) ----
        #pragma unroll
        for (int s = 0; s < 4; s++) {
            uint32_t af[2][4];
            #pragma unroll
            for (int t = 0; t < 2; t++) {
                const int mr = wq + t * 16 + lr;
                af[t][0] = Ps[mr    ][s*8 + lc    ];
                af[t][1] = Ps[mr + 8][s*8 + lc    ];
                af[t][2] = Ps[mr    ][s*8 + lc + 4];
                af[t][3] = Ps[mr + 8][s*8 + lc + 4];
            }
            #pragma unroll
            for (int j = 0; j < 8; j++) {
                uint32_t bf[2];
                bf[0] = Vs[s*8 + lc    ][j*8 + lr];
                bf[1] = Vs[s*8 + lc + 4][j*8 + lr];
                mma_tf32(oacc[0][j], af[0], bf);
                mma_tf32(oacc[1][j], af[1], bf);
            }
        }
        __syncwarp();
    }

    // ---- epilogue ----
    #pragma unroll
    for (int t = 0; t < 2; t++) {
        const float inv0 = 1.f / lsum[t][0];
        const float inv1 = 1.f / lsum[t][1];
        const size_t row0 = (size_t)nb * SEQ + q0 + wq + t*16 + lr;
        const size_t row1 = row0 + 8;
        #pragma unroll
        for (int j = 0; j < 8; j++) {
            const int col = h * HDIM + j*8 + 2*lc;
            *reinterpret_cast<float2*>(&O[row0 * EMB + col]) =
                make_float2(oacc[t][j][0] * inv0, oacc[t][j][1] * inv0);
            *reinterpret_cast<float2*>(&O[row1 * EMB + col]) =
                make_float2(oacc[t][j][2] * inv1, oacc[t][j][3] * inv1);
        }
    }
}

// ---------------------------------------------------------------------------
// Inputs: 0 values, 1 keys, 2 query, 3 mask(unused), 4 Wv, 5 bv, 6 Wk, 7 bk,
//         8 Wq, 9 bq, 10 Wo, 11 bo
// ---------------------------------------------------------------------------
extern "C" void kernel_launch(void* const* d_in, const int* in_sizes, int n_in,
                              void* d_out, int out_size)
{
    const float* values = (const float*)d_in[0];
    const float* keys   = (const float*)d_in[1];
    const float* query  = (const float*)d_in[2];
    const float* Wv = (const float*)d_in[4];
    const float* bv = (const float*)d_in[5];
    const float* Wk = (const float*)d_in[6];
    const float* bk = (const float*)d_in[7];
    const float* Wq = (const float*)d_in[8];
    const float* bq = (const float*)d_in[9];
    const float* Wo = (const float*)d_in[10];
    const float* bo = (const float*)d_in[11];
    float* out = (float*)d_out;

    float *pq, *pk, *pv, *pa;
    cudaGetSymbolAddress((void**)&pq, g_q);
    cudaGetSymbolAddress((void**)&pk, g_k);
    cudaGetSymbolAddress((void**)&pv, g_v);
    cudaGetSymbolAddress((void**)&pa, g_ao);

    cudaFuncSetAttribute(attn_mma,
                         cudaFuncAttributeMaxDynamicSharedMemorySize, ATTN_SMEM);
    cudaFuncSetAttribute(gemm_qkv,
                         cudaFuncAttributeMaxDynamicSharedMemorySize, GEMM_SMEM);
    cudaFuncSetAttribute(gemm_mma,
                         cudaFuncAttributeMaxDynamicSharedMemorySize, GEMM_SMEM);

    // Fused Q/K/V projections: 8 x 32 x 3 = 768 CTAs
    dim3 gqkv(EMB / 128, MTOT / 128, 3);
    gemm_qkv<<<gqkv, 128, GEMM_SMEM>>>(query, keys, values,
                                       Wq, Wk, Wv, bq, bk, bv,
                                       pq, pk, pv);

    dim3 gattn(SEQ / 128, NHEAD, N_BATCH);  // 16 x 16 x 2 = 512 blocks
    attn_mma<<<gattn, 128, ATTN_SMEM>>>(pq, pk, pv, pa);

    dim3 gproj(EMB / 128, MTOT / 128);
    gemm_mma<<<gproj, 128, GEMM_SMEM>>>(pa, Wo, bo, out, MTOT, EMB, EMB, 1.0f);
}

// round 13
// speedup vs baseline: 4.1683x; 1.1391x over previous
#include <cuda_runtime.h>
#include <cuda_fp16.h>
#include <cstdint>

#define N_BATCH 2
#define SEQ     2048
#define EMB     1024
#define NHEAD   16
#define HDIM    64
#define MTOT    (N_BATCH*SEQ)   // 4096

// Scratch (allocation-free rule: __device__ globals)
__device__ float g_q[(size_t)MTOT*EMB];
__device__ float g_k[(size_t)MTOT*EMB];
__device__ float g_v[(size_t)MTOT*EMB];
__device__ float g_ao[(size_t)MTOT*EMB];

__device__ __forceinline__ uint32_t f2tf32(float f) {
    uint32_t u;
    asm("cvt.rna.tf32.f32 %0, %1;" : "=r"(u) : "f"(f));
    return u;
}
__device__ __forceinline__ uint32_t pack_h2(float lo, float hi) {
    __half2 h = __floats2half2_rn(lo, hi);   // .x = lo half
    return *reinterpret_cast<uint32_t*>(&h);
}

__device__ __forceinline__ void mma_tf32(
    float c[4], const uint32_t a[4], const uint32_t b[2])
{
    asm volatile(
        "mma.sync.aligned.m16n8k8.row.col.f32.tf32.tf32.f32 "
        "{%0,%1,%2,%3}, {%4,%5,%6,%7}, {%8,%9}, {%0,%1,%2,%3};"
        : "+f"(c[0]), "+f"(c[1]), "+f"(c[2]), "+f"(c[3])
        : "r"(a[0]), "r"(a[1]), "r"(a[2]), "r"(a[3]), "r"(b[0]), "r"(b[1]));
}
__device__ __forceinline__ void mma_f16(
    float c[4], const uint32_t a[4], const uint32_t b[2])
{
    asm volatile(
        "mma.sync.aligned.m16n8k16.row.col.f32.f16.f16.f32 "
        "{%0,%1,%2,%3}, {%4,%5,%6,%7}, {%8,%9}, {%0,%1,%2,%3};"
        : "+f"(c[0]), "+f"(c[1]), "+f"(c[2]), "+f"(c[3])
        : "r"(a[0]), "r"(a[1]), "r"(a[2]), "r"(a[3]), "r"(b[0]), "r"(b[1]));
}

// ===========================================================================
// fp16 mma.sync GEMM: C = alpha * (A[M,K] @ B[N,K]^T + bias[N])  fp32 accum.
// R13: 128 threads / 4 warps, CTA 128x128, warp tile 64x64, BK=32 halves
//      (= 16 words/row, same swizzled layout as R10), double-buffered.
//      m16n8k16 -> half the MMAs and half the barriers of the tf32 version.
// ===========================================================================
#define GEMM_SMEM (2 * 2 * 2048 * 4)   // 32768 B

__device__ __forceinline__ void gemm_body(
    const float* __restrict__ A, const float* __restrict__ B,
    const float* __restrict__ bias, float* __restrict__ C,
    int M, int N, int K, float alpha)
{
    extern __shared__ uint32_t gsm[];
    uint32_t* Asm = gsm;             // [2][2048] words (128 rows x 16 words)
    uint32_t* Bsm = gsm + 2 * 2048;

    const int tid  = threadIdx.x;
    const int lane = tid & 31;
    const int wid  = tid >> 5;
    const int wm   = (wid & 1) * 64;
    const int wn   = (wid >> 1) * 64;
    const int m0 = blockIdx.y * 128;
    const int n0 = blockIdx.x * 128;

    const int lr = lane >> 2;
    const int lc = lane & 3;

    // staging: row = (tid>>2) + 32*i, chunk (8 halves = uint4) = tid&3
    const int srow = tid >> 2;
    const int sch  = tid & 3;

    float acc[4][8][4];
    #pragma unroll
    for (int i = 0; i < 4; i++)
        #pragma unroll
        for (int j = 0; j < 8; j++)
            #pragma unroll
            for (int r = 0; r < 4; r++) acc[i][j][r] = 0.f;

    auto swoff = [](int row, int ch) -> uint32_t {
        return (uint32_t)(row * 16 + (((ch ^ ((row >> 1) & 3)) & 3) << 2));
    };

    // ---- preload chunk 0 into buffer 0 ----
    #pragma unroll
    for (int i = 0; i < 4; i++) {
        const int row = srow + i * 32;
        const uint32_t so = swoff(row, sch);
        const float* ap = &A[(size_t)(m0 + row) * K + sch * 8];
        float4 a0 = *reinterpret_cast<const float4*>(ap);
        float4 a1 = *reinterpret_cast<const float4*>(ap + 4);
        *reinterpret_cast<uint4*>(&Asm[so]) =
            make_uint4(pack_h2(a0.x,a0.y), pack_h2(a0.z,a0.w),
                       pack_h2(a1.x,a1.y), pack_h2(a1.z,a1.w));
        const float* bp = &B[(size_t)(n0 + row) * K + sch * 8];
        float4 b0 = *reinterpret_cast<const float4*>(bp);
        float4 b1 = *reinterpret_cast<const float4*>(bp + 4);
        *reinterpret_cast<uint4*>(&Bsm[so]) =
            make_uint4(pack_h2(b0.x,b0.y), pack_h2(b0.z,b0.w),
                       pack_h2(b1.x,b1.y), pack_h2(b1.z,b1.w));
    }
    __syncthreads();

    const int nk = K / 32;
    for (int kc = 0; kc < nk; kc++) {
        const int buf = kc & 1;
        const uint32_t* Ab = Asm + buf * 2048;
        const uint32_t* Bb = Bsm + buf * 2048;

        uint4 na_p[4], nb_p[4];
        const bool more = (kc + 1 < nk);
        if (more) {
            const int koff = (kc + 1) * 32 + sch * 8;
            #pragma unroll
            for (int i = 0; i < 4; i++) {
                const int row = srow + i * 32;
                const float* ap = &A[(size_t)(m0 + row) * K + koff];
                float4 a0 = *reinterpret_cast<const float4*>(ap);
                float4 a1 = *reinterpret_cast<const float4*>(ap + 4);
                na_p[i] = make_uint4(pack_h2(a0.x,a0.y), pack_h2(a0.z,a0.w),
                                     pack_h2(a1.x,a1.y), pack_h2(a1.z,a1.w));
                const float* bp = &B[(size_t)(n0 + row) * K + koff];
                float4 b0 = *reinterpret_cast<const float4*>(bp);
                float4 b1 = *reinterpret_cast<const float4*>(bp + 4);
                nb_p[i] = make_uint4(pack_h2(b0.x,b0.y), pack_h2(b0.z,b0.w),
                                     pack_h2(b1.x,b1.y), pack_h2(b1.z,b1.w));
            }
        }

        // 2 k16-steps per chunk; step s uses word-chunks 2s (a0/a1,b0) and
        // 2s+1 (a2/a3,b1) — same swizzled indexing as the tf32 version.
        #pragma unroll
        for (int s = 0; s < 2; s++) {
            uint32_t af[4][4], bf[8][2];
            #pragma unroll
            for (int i = 0; i < 4; i++) {
                const int row = wm + i * 16 + lr;
                const uint32_t g = (uint32_t)((row >> 1) & 3);
                const uint32_t x0 = (((uint32_t)(2*s)     ^ g) & 3) << 2;
                const uint32_t x1 = (((uint32_t)(2*s + 1) ^ g) & 3) << 2;
                const uint32_t ra = (uint32_t)row * 16;
                af[i][0] = Ab[ra       + x0 + lc];
                af[i][1] = Ab[ra + 128 + x0 + lc];
                af[i][2] = Ab[ra       + x1 + lc];
                af[i][3] = Ab[ra + 128 + x1 + lc];
            }
            #pragma unroll
            for (int j = 0; j < 8; j++) {
                const int row = wn + j * 8 + lr;
                const uint32_t g = (uint32_t)((row >> 1) & 3);
                const uint32_t x0 = (((uint32_t)(2*s)     ^ g) & 3) << 2;
                const uint32_t x1 = (((uint32_t)(2*s + 1) ^ g) & 3) << 2;
                const uint32_t rb = (uint32_t)row * 16;
                bf[j][0] = Bb[rb + x0 + lc];
                bf[j][1] = Bb[rb + x1 + lc];
            }
            #pragma unroll
            for (int i = 0; i < 4; i++)
                #pragma unroll
                for (int j = 0; j < 8; j++)
                    mma_f16(acc[i][j], af[i], bf[j]);
        }

        if (more) {
            uint32_t* An = Asm + (buf ^ 1) * 2048;
            uint32_t* Bn = Bsm + (buf ^ 1) * 2048;
            #pragma unroll
            for (int i = 0; i < 4; i++) {
                const int row = srow + i * 32;
                const uint32_t so = swoff(row, sch);
                *reinterpret_cast<uint4*>(&An[so]) = na_p[i];
                *reinterpret_cast<uint4*>(&Bn[so]) = nb_p[i];
            }
        }
        __syncthreads();
    }

    #pragma unroll
    for (int j = 0; j < 8; j++) {
        const int col = n0 + wn + j * 8 + lc * 2;
        const float b0 = bias[col], b1 = bias[col + 1];
        #pragma unroll
        for (int i = 0; i < 4; i++) {
            const int row = m0 + wm + i * 16 + lr;
            float2 o0, o1;
            o0.x = alpha * (acc[i][j][0] + b0);
            o0.y = alpha * (acc[i][j][1] + b1);
            o1.x = alpha * (acc[i][j][2] + b0);
            o1.y = alpha * (acc[i][j][3] + b1);
            *reinterpret_cast<float2*>(&C[(size_t)row * N + col])       = o0;
            *reinterpret_cast<float2*>(&C[(size_t)(row + 8) * N + col]) = o1;
        }
    }
}

__global__ __launch_bounds__(128, 2) void gemm_mma(
    const float* __restrict__ A, const float* __restrict__ B,
    const float* __restrict__ bias, float* __restrict__ C,
    int M, int N, int K, float alpha)
{
    gemm_body(A, B, bias, C, M, N, K, alpha);
}

__global__ __launch_bounds__(128, 2) void gemm_qkv(
    const float* __restrict__ Aq, const float* __restrict__ Ak, const float* __restrict__ Av,
    const float* __restrict__ Wq, const float* __restrict__ Wk, const float* __restrict__ Wv,
    const float* __restrict__ bq, const float* __restrict__ bk, const float* __restrict__ bv,
    float* __restrict__ Cq, float* __restrict__ Ck, float* __restrict__ Cv)
{
    const int z = blockIdx.z;
    const float* A = (z == 0) ? Aq : (z == 1) ? Ak : Av;
    const float* W = (z == 0) ? Wq : (z == 1) ? Wk : Wv;
    const float* b = (z == 0) ? bq : (z == 1) ? bk : bv;
    float*       C = (z == 0) ? Cq : (z == 1) ? Ck : Cv;
    const float alpha = (z == 0) ? 0.03125f : 1.0f;
    gemm_body(A, W, b, C, MTOT, EMB, EMB, alpha);
}

// ===========================================================================
// Flash attention, causal. R13: QK^T in fp16 (m16n8k16, Q/K staged as half2
// words, stride 36 -> fragment banks 4*lr+lc = lane, conflict-free), P.V
// kept tf32 (V row-major). BQ=128, 4 warps, 32 q-rows/warp; BKT=32.
// Smem: Qs 128x36 + Ks 32x36 + Vs 32x72 + Ps 128x36 words = 50688 B.
// ===========================================================================
#define QSTR 36
#define VSTR 72
#define PSTR 36
#define BKT  32
#define ATTN_SMEM ((128*QSTR + BKT*QSTR + BKT*VSTR + 128*PSTR) * 4)   // 50688 B

__global__ __launch_bounds__(128, 3) void attn_mma(
    const float* __restrict__ Q, const float* __restrict__ K,
    const float* __restrict__ V, float* __restrict__ O)
{
    extern __shared__ uint32_t sm[];
    uint32_t (*Qs)[QSTR] = reinterpret_cast<uint32_t(*)[QSTR]>(sm);
    uint32_t (*Ks)[QSTR] = reinterpret_cast<uint32_t(*)[QSTR]>(sm + 128*QSTR);
    uint32_t (*Vs)[VSTR] = reinterpret_cast<uint32_t(*)[VSTR]>(sm + 128*QSTR + BKT*QSTR);
    uint32_t (*Ps)[PSTR] = reinterpret_cast<uint32_t(*)[PSTR]>(sm + 128*QSTR + BKT*QSTR + BKT*VSTR);

    const int tid  = threadIdx.x;
    const int lane = tid & 31;
    const int wid  = tid >> 5;
    const int lr   = lane >> 2;
    const int lc   = lane & 3;
    const int wq   = wid * 32;

    const int q0 = (gridDim.x - 1 - blockIdx.x) * 128;   // heavy tiles first
    const int h  = blockIdx.y;
    const int nb = blockIdx.z;

    const float* qbase = Q + (size_t)nb * SEQ * EMB + h * HDIM;
    const float* kbase = K + (size_t)nb * SEQ * EMB + h * HDIM;
    const float* vbase = V + (size_t)nb * SEQ * EMB + h * HDIM;

    // ---- load Q tile (128 x 64 -> half2 words), coalesced ----
    #pragma unroll
    for (int i = 0; i < 8; i++) {
        const int idx = tid + i * 128;
        const int row = idx >> 3, cw = idx & 7;     // cw = uint4 chunk (8 halves)
        const float* qp = &qbase[(size_t)(q0 + row) * EMB + cw * 8];
        float4 v0 = *reinterpret_cast<const float4*>(qp);
        float4 v1 = *reinterpret_cast<const float4*>(qp + 4);
        *reinterpret_cast<uint4*>(&Qs[row][cw * 4]) =
            make_uint4(pack_h2(v0.x,v0.y), pack_h2(v0.z,v0.w),
                       pack_h2(v1.x,v1.y), pack_h2(v1.z,v1.w));
    }

    float mrow[2][2], lsum[2][2];
    #pragma unroll
    for (int t = 0; t < 2; t++) {
        mrow[t][0] = -1e30f; mrow[t][1] = -1e30f;
        lsum[t][0] = 0.f;    lsum[t][1] = 0.f;
    }
    float oacc[2][8][4];
    #pragma unroll
    for (int t = 0; t < 2; t++)
        #pragma unroll
        for (int j = 0; j < 8; j++)
            #pragma unroll
            for (int r = 0; r < 4; r++) oacc[t][j][r] = 0.f;

    const int nkt = (q0 + 128) / BKT;
    for (int kt = 0; kt < nkt; kt++) {
        const int kb = kt * BKT;
        __syncthreads();   // Qs ready (1st); prev Ks/Vs/Ps consumed

        // K tile (32 x 64 halves): 256 uint4, 2 iterations
        #pragma unroll
        for (int i = 0; i < 2; i++) {
            const int idx = tid + i * 128;
            const int row = idx >> 3, cw = idx & 7;
            const float* kp = &kbase[(size_t)(kb + row) * EMB + cw * 8];
            float4 v0 = *reinterpret_cast<const float4*>(kp);
            float4 v1 = *reinterpret_cast<const float4*>(kp + 4);
            *reinterpret_cast<uint4*>(&Ks[row][cw * 4]) =
                make_uint4(pack_h2(v0.x,v0.y), pack_h2(v0.z,v0.w),
                           pack_h2(v1.x,v1.y), pack_h2(v1.z,v1.w));
        }
        // V tile (32 x 64 tf32): 512 uint4, 4 iterations
        #pragma unroll
        for (int i = 0; i < 4; i++) {
            const int idx = tid + i * 128;
            const int row = idx >> 4, c4 = idx & 15;
            float4 vv = *reinterpret_cast<const float4*>(
                &vbase[(size_t)(kb + row) * EMB + c4 * 4]);
            *reinterpret_cast<uint4*>(&Vs[row][c4 * 4]) =
                make_uint4(f2tf32(vv.x), f2tf32(vv.y), f2tf32(vv.z), f2tf32(vv.w));
        }
        __syncthreads();

        if (kb > q0 + wq + 31) continue;

        // ---- S = Q . K^T : fp16, 4 k16-steps over d, 4 j-tiles ----
        float sacc[2][4][4];
        #pragma unroll
        for (int t = 0; t < 2; t++)
            #pragma unroll
            for (int j = 0; j < 4; j++)
                #pragma unroll
                for (int r = 0; r < 4; r++) sacc[t][j][r] = 0.f;

        #pragma unroll
        for (int s = 0; s < 4; s++) {
            uint32_t af[2][4];
            #pragma unroll
            for (int t = 0; t < 2; t++) {
                const int mr = wq + t * 16 + lr;
                af[t][0] = Qs[mr    ][s*8 + lc    ];
                af[t][1] = Qs[mr + 8][s*8 + lc    ];
                af[t][2] = Qs[mr    ][s*8 + lc + 4];
                af[t][3] = Qs[mr + 8][s*8 + lc + 4];
            }
            #pragma unroll
            for (int j = 0; j < 4; j++) {
                uint32_t bf[2];
                bf[0] = Ks[j*8 + lr][s*8 + lc    ];
                bf[1] = Ks[j*8 + lr][s*8 + lc + 4];
                mma_f16(sacc[0][j], af[0], bf);
                mma_f16(sacc[1][j], af[1], bf);
            }
        }

        // ---- causal mask ----
        if (kb + BKT - 1 > q0 + wq) {
            #pragma unroll
            for (int t = 0; t < 2; t++) {
                const int r0 = q0 + wq + t*16 + lr, r1 = r0 + 8;
                #pragma unroll
                for (int j = 0; j < 4; j++) {
                    const int c0 = kb + j*8 + 2*lc, c1 = c0 + 1;
                    if (c0 > r0) sacc[t][j][0] = -1e30f;
                    if (c1 > r0) sacc[t][j][1] = -1e30f;
                    if (c0 > r1) sacc[t][j][2] = -1e30f;
                    if (c1 > r1) sacc[t][j][3] = -1e30f;
                }
            }
        }

        // ---- online softmax per m-tile ----
        #pragma unroll
        for (int t = 0; t < 2; t++) {
            float mt0 = -1e30f, mt1 = -1e30f;
            #pragma unroll
            for (int j = 0; j < 4; j++) {
                mt0 = fmaxf(mt0, fmaxf(sacc[t][j][0], sacc[t][j][1]));
                mt1 = fmaxf(mt1, fmaxf(sacc[t][j][2], sacc[t][j][3]));
            }
            mt0 = fmaxf(mt0, __shfl_xor_sync(0xffffffffu, mt0, 1));
            mt0 = fmaxf(mt0, __shfl_xor_sync(0xffffffffu, mt0, 2));
            mt1 = fmaxf(mt1, __shfl_xor_sync(0xffffffffu, mt1, 1));
            mt1 = fmaxf(mt1, __shfl_xor_sync(0xffffffffu, mt1, 2));

            const float mn0 = fmaxf(mrow[t][0], mt0);
            const float mn1 = fmaxf(mrow[t][1], mt1);
            const float cor0 = __expf(mrow[t][0] - mn0);
            const float cor1 = __expf(mrow[t][1] - mn1);
            mrow[t][0] = mn0; mrow[t][1] = mn1;

            float ls0 = 0.f, ls1 = 0.f;
            #pragma unroll
            for (int j = 0; j < 4; j++) {
                sacc[t][j][0] = __expf(sacc[t][j][0] - mn0);
                sacc[t][j][1] = __expf(sacc[t][j][1] - mn0);
                sacc[t][j][2] = __expf(sacc[t][j][2] - mn1);
                sacc[t][j][3] = __expf(sacc[t][j][3] - mn1);
                ls0 += sacc[t][j][0] + sacc[t][j][1];
                ls1 += sacc[t][j][2] + sacc[t][j][3];
            }
            ls0 += __shfl_xor_sync(0xffffffffu, ls0, 1);
            ls0 += __shfl_xor_sync(0xffffffffu, ls0, 2);
            ls1 += __shfl_xor_sync(0xffffffffu, ls1, 1);
            ls1 += __shfl_xor_sync(0xffffffffu, ls1, 2);
            lsum[t][0] = lsum[t][0] * cor0 + ls0;
            lsum[t][1] = lsum[t][1] * cor1 + ls1;

            #pragma unroll
            for (int j = 0; j < 8; j++) {
                oacc[t][j][0] *= cor0; oacc[t][j][1] *= cor0;
                oacc[t][j][2] *= cor1; oacc[t][j][3] *= cor1;
            }
        }

        // ---- stage P (tf32, per-warp private rows) ----
        #pragma unroll
        for (int t = 0; t < 2; t++) {
            const int mr = wq + t * 16 + lr;
            #pragma unroll
            for (int j = 0; j < 4; j++) {
                *reinterpret_cast<uint2*>(&Ps[mr    ][j*8 + 2*lc]) =
                    make_uint2(f2tf32(sacc[t][j][0]), f2tf32(sacc[t][j][1]));
                *reinterpret_cast<uint2*>(&Ps[mr + 8][j*8 + 2*lc]) =
                    make_uint2(f2tf32(sacc[t][j][2]), f2tf32(sacc[t][j][3]));
            }
        }
        __syncwarp();

        // ---- O += P . V  (tf32: 4 k8-steps over 32 keys, 8 d-tiles) ----
        #pragma unroll
        for (int s = 0; s < 4; s++) {
            uint32_t af[2][4];
            #pragma unroll
            for (int t = 0; t < 2; t++) {
                const int mr = wq + t * 16 + lr;
                af[t][0] = Ps[mr    ][s*8 + lc    ];
                af[t][1] = Ps[mr + 8][s*8 + lc    ];
                af[t][2] = Ps[mr    ][s*8 + lc + 4];
                af[t][3] = Ps[mr + 8][s*8 + lc + 4];
            }
            #pragma unroll
            for (int j = 0; j < 8; j++) {
                uint32_t bf[2];
                bf[0] = Vs[s*8 + lc    ][j*8 + lr];
                bf[1] = Vs[s*8 + lc + 4][j*8 + lr];
                mma_tf32(oacc[0][j], af[0], bf);
                mma_tf32(oacc[1][j], af[1], bf);
            }
        }
        __syncwarp();
    }

    // ---- epilogue ----
    #pragma unroll
    for (int t = 0; t < 2; t++) {
        const float inv0 = 1.f / lsum[t][0];
        const float inv1 = 1.f / lsum[t][1];
        const size_t row0 = (size_t)nb * SEQ + q0 + wq + t*16 + lr;
        const size_t row1 = row0 + 8;
        #pragma unroll
        for (int j = 0; j < 8; j++) {
            const int col = h * HDIM + j*8 + 2*lc;
            *reinterpret_cast<float2*>(&O[row0 * EMB + col]) =
                make_float2(oacc[t][j][0] * inv0, oacc[t][j][1] * inv0);
            *reinterpret_cast<float2*>(&O[row1 * EMB + col]) =
                make_float2(oacc[t][j][2] * inv1, oacc[t][j][3] * inv1);
        }
    }
}

// ---------------------------------------------------------------------------
// Inputs: 0 values, 1 keys, 2 query, 3 mask(unused), 4 Wv, 5 bv, 6 Wk, 7 bk,
//         8 Wq, 9 bq, 10 Wo, 11 bo
// ---------------------------------------------------------------------------
extern "C" void kernel_launch(void* const* d_in, const int* in_sizes, int n_in,
                              void* d_out, int out_size)
{
    const float* values = (const float*)d_in[0];
    const float* keys   = (const float*)d_in[1];
    const float* query  = (const float*)d_in[2];
    const float* Wv = (const float*)d_in[4];
    const float* bv = (const float*)d_in[5];
    const float* Wk = (const float*)d_in[6];
    const float* bk = (const float*)d_in[7];
    const float* Wq = (const float*)d_in[8];
    const float* bq = (const float*)d_in[9];
    const float* Wo = (const float*)d_in[10];
    const float* bo = (const float*)d_in[11];
    float* out = (float*)d_out;

    float *pq, *pk, *pv, *pa;
    cudaGetSymbolAddress((void**)&pq, g_q);
    cudaGetSymbolAddress((void**)&pk, g_k);
    cudaGetSymbolAddress((void**)&pv, g_v);
    cudaGetSymbolAddress((void**)&pa, g_ao);

    cudaFuncSetAttribute(attn_mma,
                         cudaFuncAttributeMaxDynamicSharedMemorySize, ATTN_SMEM);
    cudaFuncSetAttribute(gemm_qkv,
                         cudaFuncAttributeMaxDynamicSharedMemorySize, GEMM_SMEM);
    cudaFuncSetAttribute(gemm_mma,
                         cudaFuncAttributeMaxDynamicSharedMemorySize, GEMM_SMEM);

    // Fused Q/K/V projections: 8 x 32 x 3 = 768 CTAs
    dim3 gqkv(EMB / 128, MTOT / 128, 3);
    gemm_qkv<<<gqkv, 128, GEMM_SMEM>>>(query, keys, values,
                                       Wq, Wk, Wv, bq, bk, bv,
                                       pq, pk, pv);

    dim3 gattn(SEQ / 128, NHEAD, N_BATCH);  // 16 x 16 x 2 = 512 blocks
    attn_mma<<<gattn, 128, ATTN_SMEM>>>(pq, pk, pv, pa);

    dim3 gproj(EMB / 128, MTOT / 128);
    gemm_mma<<<gproj, 128, GEMM_SMEM>>>(pa, Wo, bo, out, MTOT, EMB, EMB, 1.0f);
}

// round 14
// speedup vs baseline: 5.4804x; 1.3148x over previous
#include <cuda_runtime.h>
#include <cuda_fp16.h>
#include <cstdint>

#define N_BATCH 2
#define SEQ     2048
#define EMB     1024
#define NHEAD   16
#define HDIM    64
#define MTOT    (N_BATCH*SEQ)   // 4096

// Scratch (allocation-free rule: __device__ globals), all fp16
__device__ __half h_query[(size_t)MTOT*EMB];
__device__ __half h_keys [(size_t)MTOT*EMB];
__device__ __half h_vals [(size_t)MTOT*EMB];
__device__ __half h_wq[(size_t)EMB*EMB];
__device__ __half h_wk[(size_t)EMB*EMB];
__device__ __half h_wv[(size_t)EMB*EMB];
__device__ __half h_wo[(size_t)EMB*EMB];
__device__ __half g_qh[(size_t)MTOT*EMB];
__device__ __half g_kh[(size_t)MTOT*EMB];
__device__ __half g_vh[(size_t)MTOT*EMB];
__device__ __half g_aoh[(size_t)MTOT*EMB];

__device__ __forceinline__ uint32_t f2tf32(float f) {
    uint32_t u;
    asm("cvt.rna.tf32.f32 %0, %1;" : "=r"(u) : "f"(f));
    return u;
}
__device__ __forceinline__ uint32_t pack_h2(float lo, float hi) {
    __half2 h = __floats2half2_rn(lo, hi);
    return *reinterpret_cast<uint32_t*>(&h);
}
__device__ __forceinline__ uint32_t smem_u32(const void* p) {
    uint32_t a;
    asm("{ .reg .u64 t; cvta.to.shared.u64 t, %1; cvt.u32.u64 %0, t; }"
        : "=r"(a) : "l"(p));
    return a;
}
__device__ __forceinline__ void cp16(uint32_t sm_dst, const void* g_src) {
    asm volatile("cp.async.cg.shared.global [%0], [%1], 16;"
                 :: "r"(sm_dst), "l"(g_src) : "memory");
}
#define CP_COMMIT() asm volatile("cp.async.commit_group;" ::: "memory")
#define CP_WAIT0()  asm volatile("cp.async.wait_group 0;" ::: "memory")

__device__ __forceinline__ void mma_tf32(
    float c[4], const uint32_t a[4], const uint32_t b[2])
{
    asm volatile(
        "mma.sync.aligned.m16n8k8.row.col.f32.tf32.tf32.f32 "
        "{%0,%1,%2,%3}, {%4,%5,%6,%7}, {%8,%9}, {%0,%1,%2,%3};"
        : "+f"(c[0]), "+f"(c[1]), "+f"(c[2]), "+f"(c[3])
        : "r"(a[0]), "r"(a[1]), "r"(a[2]), "r"(a[3]), "r"(b[0]), "r"(b[1]));
}
__device__ __forceinline__ void mma_f16(
    float c[4], const uint32_t a[4], const uint32_t b[2])
{
    asm volatile(
        "mma.sync.aligned.m16n8k16.row.col.f32.f16.f16.f32 "
        "{%0,%1,%2,%3}, {%4,%5,%6,%7}, {%8,%9}, {%0,%1,%2,%3};"
        : "+f"(c[0]), "+f"(c[1]), "+f"(c[2]), "+f"(c[3])
        : "r"(a[0]), "r"(a[1]), "r"(a[2]), "r"(a[3]), "r"(b[0]), "r"(b[1]));
}

// ===========================================================================
// fp32 -> fp16 converter (8 floats / thread)
// ===========================================================================
__global__ __launch_bounds__(256) void cvt_f2h(
    const float* __restrict__ s, __half* __restrict__ d, int n8)
{
    const int i = blockIdx.x * 256 + threadIdx.x;
    if (i >= n8) return;
    const float4* sp = reinterpret_cast<const float4*>(s) + (size_t)i * 2;
    float4 a = sp[0], b = sp[1];
    reinterpret_cast<uint4*>(d)[i] =
        make_uint4(pack_h2(a.x,a.y), pack_h2(a.z,a.w),
                   pack_h2(b.x,b.y), pack_h2(b.z,b.w));
}

// ===========================================================================
// fp16 GEMM (fp32 accum): C = alpha * (A[M,K] @ B[N,K]^T + bias[N])
// R14: cp.async staging (no prefetch regs, no in-loop packing), BK=32 halves,
//      CTA 128x128, 4 warps, warp tile 64x64, double-buffered swizzled smem.
// HALF_OUT: C is __half (packed stores); else fp32.
// ===========================================================================
#define GEMM_SMEM (2 * 2 * 2048 * 4)   // 32768 B

template<bool HALF_OUT>
__device__ __forceinline__ void gemm_body_h(
    const __half* __restrict__ A, const __half* __restrict__ B,
    const float* __restrict__ bias, void* __restrict__ Cv,
    int M, int N, int K, float alpha)
{
    extern __shared__ uint32_t gsm[];
    // words: A buf0 [0,2048), A buf1 [2048,4096), B buf0 [4096,..), B buf1
    const uint32_t sbase = smem_u32(gsm);

    const int tid  = threadIdx.x;
    const int lane = tid & 31;
    const int wid  = tid >> 5;
    const int wm   = (wid & 1) * 64;
    const int wn   = (wid >> 1) * 64;
    const int m0 = blockIdx.y * 128;
    const int n0 = blockIdx.x * 128;

    const int lr = lane >> 2;
    const int lc = lane & 3;

    const int srow = tid >> 2;    // 0..31
    const int sch  = tid & 3;     // 16B chunk (8 halves)

    float acc[4][8][4];
    #pragma unroll
    for (int i = 0; i < 4; i++)
        #pragma unroll
        for (int j = 0; j < 8; j++)
            #pragma unroll
            for (int r = 0; r < 4; r++) acc[i][j][r] = 0.f;

    auto swoff = [](int row, int ch) -> uint32_t {
        return (uint32_t)(row * 16 + (((ch ^ ((row >> 1) & 3)) & 3) << 2));
    };

    auto stage = [&](int buf, int kc) {
        const int koff = kc * 32 + sch * 8;   // halves
        #pragma unroll
        for (int i = 0; i < 4; i++) {
            const int row = srow + i * 32;
            const uint32_t so = swoff(row, sch);
            cp16(sbase + (buf * 2048 + so) * 4,
                 A + (size_t)(m0 + row) * K + koff);
            cp16(sbase + (4096 + buf * 2048 + so) * 4,
                 B + (size_t)(n0 + row) * K + koff);
        }
        CP_COMMIT();
    };

    stage(0, 0);
    CP_WAIT0();
    __syncthreads();

    const int nk = K / 32;
    for (int kc = 0; kc < nk; kc++) {
        const int buf = kc & 1;
        const bool more = (kc + 1 < nk);
        if (more) stage(buf ^ 1, kc + 1);

        const uint32_t* Ab = gsm + buf * 2048;
        const uint32_t* Bb = gsm + 4096 + buf * 2048;

        #pragma unroll
        for (int s = 0; s < 2; s++) {
            uint32_t af[4][4], bf[8][2];
            #pragma unroll
            for (int i = 0; i < 4; i++) {
                const int row = wm + i * 16 + lr;
                const uint32_t g = (uint32_t)((row >> 1) & 3);
                const uint32_t x0 = (((uint32_t)(2*s)     ^ g) & 3) << 2;
                const uint32_t x1 = (((uint32_t)(2*s + 1) ^ g) & 3) << 2;
                const uint32_t ra = (uint32_t)row * 16;
                af[i][0] = Ab[ra       + x0 + lc];
                af[i][1] = Ab[ra + 128 + x0 + lc];
                af[i][2] = Ab[ra       + x1 + lc];
                af[i][3] = Ab[ra + 128 + x1 + lc];
            }
            #pragma unroll
            for (int j = 0; j < 8; j++) {
                const int row = wn + j * 8 + lr;
                const uint32_t g = (uint32_t)((row >> 1) & 3);
                const uint32_t x0 = (((uint32_t)(2*s)     ^ g) & 3) << 2;
                const uint32_t x1 = (((uint32_t)(2*s + 1) ^ g) & 3) << 2;
                const uint32_t rb = (uint32_t)row * 16;
                bf[j][0] = Bb[rb + x0 + lc];
                bf[j][1] = Bb[rb + x1 + lc];
            }
            #pragma unroll
            for (int i = 0; i < 4; i++)
                #pragma unroll
                for (int j = 0; j < 8; j++)
                    mma_f16(acc[i][j], af[i], bf[j]);
        }

        if (more) CP_WAIT0();
        __syncthreads();
    }

    // ---- epilogue ----
    #pragma unroll
    for (int j = 0; j < 8; j++) {
        const int col = n0 + wn + j * 8 + lc * 2;
        const float b0 = bias[col], b1 = bias[col + 1];
        #pragma unroll
        for (int i = 0; i < 4; i++) {
            const int row = m0 + wm + i * 16 + lr;
            const float o00 = alpha * (acc[i][j][0] + b0);
            const float o01 = alpha * (acc[i][j][1] + b1);
            const float o10 = alpha * (acc[i][j][2] + b0);
            const float o11 = alpha * (acc[i][j][3] + b1);
            if (HALF_OUT) {
                __half* C = reinterpret_cast<__half*>(Cv);
                *reinterpret_cast<uint32_t*>(&C[(size_t)row * N + col]) =
                    pack_h2(o00, o01);
                *reinterpret_cast<uint32_t*>(&C[(size_t)(row + 8) * N + col]) =
                    pack_h2(o10, o11);
            } else {
                float* C = reinterpret_cast<float*>(Cv);
                *reinterpret_cast<float2*>(&C[(size_t)row * N + col]) =
                    make_float2(o00, o01);
                *reinterpret_cast<float2*>(&C[(size_t)(row + 8) * N + col]) =
                    make_float2(o10, o11);
            }
        }
    }
}

// Fused QKV: one launch, blockIdx.z selects the projection. fp16 out.
__global__ __launch_bounds__(128, 2) void gemm_qkv_h(
    const __half* __restrict__ Aq, const __half* __restrict__ Ak, const __half* __restrict__ Av,
    const __half* __restrict__ Wq, const __half* __restrict__ Wk, const __half* __restrict__ Wv,
    const float* __restrict__ bq, const float* __restrict__ bk, const float* __restrict__ bv,
    __half* __restrict__ Cq, __half* __restrict__ Ck, __half* __restrict__ Cv)
{
    const int z = blockIdx.z;
    const __half* A = (z == 0) ? Aq : (z == 1) ? Ak : Av;
    const __half* W = (z == 0) ? Wq : (z == 1) ? Wk : Wv;
    const float*  b = (z == 0) ? bq : (z == 1) ? bk : bv;
    __half*       C = (z == 0) ? Cq : (z == 1) ? Ck : Cv;
    const float alpha = (z == 0) ? 0.03125f : 1.0f;   // softmax scale in Q
    gemm_body_h<true>(A, W, b, C, MTOT, EMB, EMB, alpha);
}

// Output GEMM: fp16 in, fp32 out.
__global__ __launch_bounds__(128, 2) void gemm_out_h(
    const __half* __restrict__ A, const __half* __restrict__ B,
    const float* __restrict__ bias, float* __restrict__ C)
{
    gemm_body_h<false>(A, B, bias, C, MTOT, EMB, EMB, 1.0f);
}

// ===========================================================================
// Flash attention, causal. fp16 Q/K (m16n8k16 QK^T), tf32 P.V.
// R14: inputs/outputs fp16 -> staging is plain copies (Q/K) and exact
// fp16->tf32 widen (V). Output written fp16 for the Wo GEMM.
// BQ=128, 4 warps, 32 q-rows/warp; BKT=32; smem 50688 B -> 3-4 CTAs/SM.
// ===========================================================================
#define QSTR 36
#define VSTR 72
#define PSTR 36
#define BKT  32
#define ATTN_SMEM ((128*QSTR + BKT*QSTR + BKT*VSTR + 128*PSTR) * 4)   // 50688 B

__global__ __launch_bounds__(128, 3) void attn_mma(
    const __half* __restrict__ Q, const __half* __restrict__ K,
    const __half* __restrict__ V, __half* __restrict__ O)
{
    extern __shared__ uint32_t sm[];
    uint32_t (*Qs)[QSTR] = reinterpret_cast<uint32_t(*)[QSTR]>(sm);
    uint32_t (*Ks)[QSTR] = reinterpret_cast<uint32_t(*)[QSTR]>(sm + 128*QSTR);
    uint32_t (*Vs)[VSTR] = reinterpret_cast<uint32_t(*)[VSTR]>(sm + 128*QSTR + BKT*QSTR);
    uint32_t (*Ps)[PSTR] = reinterpret_cast<uint32_t(*)[PSTR]>(sm + 128*QSTR + BKT*QSTR + BKT*VSTR);

    const int tid  = threadIdx.x;
    const int lane = tid & 31;
    const int wid  = tid >> 5;
    const int lr   = lane >> 2;
    const int lc   = lane & 3;
    const int wq   = wid * 32;

    const int q0 = (gridDim.x - 1 - blockIdx.x) * 128;   // heavy tiles first
    const int h  = blockIdx.y;
    const int nb = blockIdx.z;

    const __half* qbase = Q + (size_t)nb * SEQ * EMB + h * HDIM;
    const __half* kbase = K + (size_t)nb * SEQ * EMB + h * HDIM;
    const __half* vbase = V + (size_t)nb * SEQ * EMB + h * HDIM;

    // ---- load Q tile (128 x 64 halves = 128 x 32 words), plain copy ----
    #pragma unroll
    for (int i = 0; i < 8; i++) {
        const int idx = tid + i * 128;
        const int row = idx >> 3, cw = idx & 7;
        *reinterpret_cast<uint4*>(&Qs[row][cw * 4]) =
            *reinterpret_cast<const uint4*>(&qbase[(size_t)(q0 + row) * EMB + cw * 8]);
    }

    float mrow[2][2], lsum[2][2];
    #pragma unroll
    for (int t = 0; t < 2; t++) {
        mrow[t][0] = -1e30f; mrow[t][1] = -1e30f;
        lsum[t][0] = 0.f;    lsum[t][1] = 0.f;
    }
    float oacc[2][8][4];
    #pragma unroll
    for (int t = 0; t < 2; t++)
        #pragma unroll
        for (int j = 0; j < 8; j++)
            #pragma unroll
            for (int r = 0; r < 4; r++) oacc[t][j][r] = 0.f;

    const int nkt = (q0 + 128) / BKT;
    for (int kt = 0; kt < nkt; kt++) {
        const int kb = kt * BKT;
        __syncthreads();

        // K tile (32 x 32 words), plain copy: 256 uint4, 2 iterations
        #pragma unroll
        for (int i = 0; i < 2; i++) {
            const int idx = tid + i * 128;
            const int row = idx >> 3, cw = idx & 7;
            *reinterpret_cast<uint4*>(&Ks[row][cw * 4]) =
                *reinterpret_cast<const uint4*>(&kbase[(size_t)(kb + row) * EMB + cw * 8]);
        }
        // V tile (32 x 64): fp16 -> tf32 widen (exact), 4 iterations
        #pragma unroll
        for (int i = 0; i < 4; i++) {
            const int idx = tid + i * 128;
            const int row = idx >> 4, c4 = idx & 15;
            const uint2 hv = *reinterpret_cast<const uint2*>(
                &vbase[(size_t)(kb + row) * EMB + c4 * 4]);
            const __half2 p0 = *reinterpret_cast<const __half2*>(&hv.x);
            const __half2 p1 = *reinterpret_cast<const __half2*>(&hv.y);
            const float2 f0 = __half22float2(p0);
            const float2 f1 = __half22float2(p1);
            *reinterpret_cast<uint4*>(&Vs[row][c4 * 4]) =
                make_uint4(f2tf32(f0.x), f2tf32(f0.y), f2tf32(f1.x), f2tf32(f1.y));
        }
        __syncthreads();

        if (kb > q0 + wq + 31) continue;

        // ---- S = Q . K^T : fp16, 4 k16-steps over d, 4 j-tiles ----
        float sacc[2][4][4];
        #pragma unroll
        for (int t = 0; t < 2; t++)
            #pragma unroll
            for (int j = 0; j < 4; j++)
                #pragma unroll
                for (int r = 0; r < 4; r++) sacc[t][j][r] = 0.f;

        #pragma unroll
        for (int s = 0; s < 4; s++) {
            uint32_t af[2][4];
            #pragma unroll
            for (int t = 0; t < 2; t++) {
                const int mr = wq + t * 16 + lr;
                af[t][0] = Qs[mr    ][s*8 + lc    ];
                af[t][1] = Qs[mr + 8][s*8 + lc    ];
                af[t][2] = Qs[mr    ][s*8 + lc + 4];
                af[t][3] = Qs[mr + 8][s*8 + lc + 4];
            }
            #pragma unroll
            for (int j = 0; j < 4; j++) {
                uint32_t bf[2];
                bf[0] = Ks[j*8 + lr][s*8 + lc    ];
                bf[1] = Ks[j*8 + lr][s*8 + lc + 4];
                mma_f16(sacc[0][j], af[0], bf);
                mma_f16(sacc[1][j], af[1], bf);
            }
        }

        // ---- causal mask ----
        if (kb + BKT - 1 > q0 + wq) {
            #pragma unroll
            for (int t = 0; t < 2; t++) {
                const int r0 = q0 + wq + t*16 + lr, r1 = r0 + 8;
                #pragma unroll
                for (int j = 0; j < 4; j++) {
                    const int c0 = kb + j*8 + 2*lc, c1 = c0 + 1;
                    if (c0 > r0) sacc[t][j][0] = -1e30f;
                    if (c1 > r0) sacc[t][j][1] = -1e30f;
                    if (c0 > r1) sacc[t][j][2] = -1e30f;
                    if (c1 > r1) sacc[t][j][3] = -1e30f;
                }
            }
        }

        // ---- online softmax per m-tile ----
        #pragma unroll
        for (int t = 0; t < 2; t++) {
            float mt0 = -1e30f, mt1 = -1e30f;
            #pragma unroll
            for (int j = 0; j < 4; j++) {
                mt0 = fmaxf(mt0, fmaxf(sacc[t][j][0], sacc[t][j][1]));
                mt1 = fmaxf(mt1, fmaxf(sacc[t][j][2], sacc[t][j][3]));
            }
            mt0 = fmaxf(mt0, __shfl_xor_sync(0xffffffffu, mt0, 1));
            mt0 = fmaxf(mt0, __shfl_xor_sync(0xffffffffu, mt0, 2));
            mt1 = fmaxf(mt1, __shfl_xor_sync(0xffffffffu, mt1, 1));
            mt1 = fmaxf(mt1, __shfl_xor_sync(0xffffffffu, mt1, 2));

            const float mn0 = fmaxf(mrow[t][0], mt0);
            const float mn1 = fmaxf(mrow[t][1], mt1);
            const float cor0 = __expf(mrow[t][0] - mn0);
            const float cor1 = __expf(mrow[t][1] - mn1);
            mrow[t][0] = mn0; mrow[t][1] = mn1;

            float ls0 = 0.f, ls1 = 0.f;
            #pragma unroll
            for (int j = 0; j < 4; j++) {
                sacc[t][j][0] = __expf(sacc[t][j][0] - mn0);
                sacc[t][j][1] = __expf(sacc[t][j][1] - mn0);
                sacc[t][j][2] = __expf(sacc[t][j][2] - mn1);
                sacc[t][j][3] = __expf(sacc[t][j][3] - mn1);
                ls0 += sacc[t][j][0] + sacc[t][j][1];
                ls1 += sacc[t][j][2] + sacc[t][j][3];
            }
            ls0 += __shfl_xor_sync(0xffffffffu, ls0, 1);
            ls0 += __shfl_xor_sync(0xffffffffu, ls0, 2);
            ls1 += __shfl_xor_sync(0xffffffffu, ls1, 1);
            ls1 += __shfl_xor_sync(0xffffffffu, ls1, 2);
            lsum[t][0] = lsum[t][0] * cor0 + ls0;
            lsum[t][1] = lsum[t][1] * cor1 + ls1;

            #pragma unroll
            for (int j = 0; j < 8; j++) {
                oacc[t][j][0] *= cor0; oacc[t][j][1] *= cor0;
                oacc[t][j][2] *= cor1; oacc[t][j][3] *= cor1;
            }
        }

        // ---- stage P (tf32, per-warp private rows) ----
        #pragma unroll
        for (int t = 0; t < 2; t++) {
            const int mr = wq + t * 16 + lr;
            #pragma unroll
            for (int j = 0; j < 4; j++) {
                *reinterpret_cast<uint2*>(&Ps[mr    ][j*8 + 2*lc]) =
                    make_uint2(f2tf32(sacc[t][j][0]), f2tf32(sacc[t][j][1]));
                *reinterpret_cast<uint2*>(&Ps[mr + 8][j*8 + 2*lc]) =
                    make_uint2(f2tf32(sacc[t][j][2]), f2tf32(sacc[t][j][3]));
            }
        }
        __syncwarp();

        // ---- O += P . V  (tf32: 4 k8-steps over 32 keys, 8 d-tiles) ----
        #pragma unroll
        for (int s = 0; s < 4; s++) {
            uint32_t af[2][4];
            #pragma unroll
            for (int t = 0; t < 2; t++) {
                const int mr = wq + t * 16 + lr;
                af[t][0] = Ps[mr    ][s*8 + lc    ];
                af[t][1] = Ps[mr + 8][s*8 + lc    ];
                af[t][2] = Ps[mr    ][s*8 + lc + 4];
                af[t][3] = Ps[mr + 8][s*8 + lc + 4];
            }
            #pragma unroll
            for (int j = 0; j < 8; j++) {
                uint32_t bf[2];
                bf[0] = Vs[s*8 + lc    ][j*8 + lr];
                bf[1] = Vs[s*8 + lc + 4][j*8 + lr];
                mma_tf32(oacc[0][j], af[0], bf);
                mma_tf32(oacc[1][j], af[1], bf);
            }
        }
        __syncwarp();
    }

    // ---- epilogue: normalize, write fp16 [n, q, h*64 + d] ----
    #pragma unroll
    for (int t = 0; t < 2; t++) {
        const float inv0 = 1.f / lsum[t][0];
        const float inv1 = 1.f / lsum[t][1];
        const size_t row0 = (size_t)nb * SEQ + q0 + wq + t*16 + lr;
        const size_t row1 = row0 + 8;
        #pragma unroll
        for (int j = 0; j < 8; j++) {
            const int col = h * HDIM + j*8 + 2*lc;
            *reinterpret_cast<uint32_t*>(&O[row0 * EMB + col]) =
                pack_h2(oacc[t][j][0] * inv0, oacc[t][j][1] * inv0);
            *reinterpret_cast<uint32_t*>(&O[row1 * EMB + col]) =
                pack_h2(oacc[t][j][2] * inv1, oacc[t][j][3] * inv1);
        }
    }
}

// ---------------------------------------------------------------------------
// Inputs: 0 values, 1 keys, 2 query, 3 mask(unused), 4 Wv, 5 bv, 6 Wk, 7 bk,
//         8 Wq, 9 bq, 10 Wo, 11 bo
// ---------------------------------------------------------------------------
extern "C" void kernel_launch(void* const* d_in, const int* in_sizes, int n_in,
                              void* d_out, int out_size)
{
    const float* values = (const float*)d_in[0];
    const float* keys   = (const float*)d_in[1];
    const float* query  = (const float*)d_in[2];
    const float* Wv = (const float*)d_in[4];
    const float* bv = (const float*)d_in[5];
    const float* Wk = (const float*)d_in[6];
    const float* bk = (const float*)d_in[7];
    const float* Wq = (const float*)d_in[8];
    const float* bq = (const float*)d_in[9];
    const float* Wo = (const float*)d_in[10];
    const float* bo = (const float*)d_in[11];
    float* out = (float*)d_out;

    __half *pQ, *pK, *pV, *pWq, *pWk, *pWv, *pWo, *pqh, *pkh, *pvh, *pah;
    cudaGetSymbolAddress((void**)&pQ,  h_query);
    cudaGetSymbolAddress((void**)&pK,  h_keys);
    cudaGetSymbolAddress((void**)&pV,  h_vals);
    cudaGetSymbolAddress((void**)&pWq, h_wq);
    cudaGetSymbolAddress((void**)&pWk, h_wk);
    cudaGetSymbolAddress((void**)&pWv, h_wv);
    cudaGetSymbolAddress((void**)&pWo, h_wo);
    cudaGetSymbolAddress((void**)&pqh, g_qh);
    cudaGetSymbolAddress((void**)&pkh, g_kh);
    cudaGetSymbolAddress((void**)&pvh, g_vh);
    cudaGetSymbolAddress((void**)&pah, g_aoh);

    cudaFuncSetAttribute(attn_mma,
                         cudaFuncAttributeMaxDynamicSharedMemorySize, ATTN_SMEM);
    cudaFuncSetAttribute(gemm_qkv_h,
                         cudaFuncAttributeMaxDynamicSharedMemorySize, GEMM_SMEM);
    cudaFuncSetAttribute(gemm_out_h,
                         cudaFuncAttributeMaxDynamicSharedMemorySize, GEMM_SMEM);

    // fp32 -> fp16 conversions
    const int nact8 = (MTOT * EMB) / 8;   // 524288
    const int nw8   = (EMB * EMB) / 8;    // 131072
    cvt_f2h<<<nact8 / 256, 256>>>(query,  pQ,  nact8);
    cvt_f2h<<<nact8 / 256, 256>>>(keys,   pK,  nact8);
    cvt_f2h<<<nact8 / 256, 256>>>(values, pV,  nact8);
    cvt_f2h<<<nw8 / 256, 256>>>(Wq, pWq, nw8);
    cvt_f2h<<<nw8 / 256, 256>>>(Wk, pWk, nw8);
    cvt_f2h<<<nw8 / 256, 256>>>(Wv, pWv, nw8);
    cvt_f2h<<<nw8 / 256, 256>>>(Wo, pWo, nw8);

    // Fused Q/K/V projections: 8 x 32 x 3 = 768 CTAs
    dim3 gqkv(EMB / 128, MTOT / 128, 3);
    gemm_qkv_h<<<gqkv, 128, GEMM_SMEM>>>(pQ, pK, pV,
                                         pWq, pWk, pWv, bq, bk, bv,
                                         pqh, pkh, pvh);

    dim3 gattn(SEQ / 128, NHEAD, N_BATCH);  // 16 x 16 x 2 = 512 blocks
    attn_mma<<<gattn, 128, ATTN_SMEM>>>(pqh, pkh, pvh, pah);

    dim3 gproj(EMB / 128, MTOT / 128);
    gemm_out_h<<<gproj, 128, GEMM_SMEM>>>(pah, pWo, bo, out);
}

// round 15
// speedup vs baseline: 5.4880x; 1.0014x over previous
#include <cuda_runtime.h>
#include <cuda_fp16.h>
#include <cstdint>

#define N_BATCH 2
#define SEQ     2048
#define EMB     1024
#define NHEAD   16
#define HDIM    64
#define MTOT    (N_BATCH*SEQ)   // 4096

// Scratch (allocation-free rule: __device__ globals), all fp16
__device__ __half h_query[(size_t)MTOT*EMB];
__device__ __half h_keys [(size_t)MTOT*EMB];
__device__ __half h_vals [(size_t)MTOT*EMB];
__device__ __half h_wq[(size_t)EMB*EMB];
__device__ __half h_wk[(size_t)EMB*EMB];
__device__ __half h_wv[(size_t)EMB*EMB];
__device__ __half h_wo[(size_t)EMB*EMB];
__device__ __half g_qh[(size_t)MTOT*EMB];
__device__ __half g_kh[(size_t)MTOT*EMB];
__device__ __half g_vh[(size_t)MTOT*EMB];
__device__ __half g_aoh[(size_t)MTOT*EMB];

__device__ __forceinline__ uint32_t f2tf32(float f) {
    uint32_t u;
    asm("cvt.rna.tf32.f32 %0, %1;" : "=r"(u) : "f"(f));
    return u;
}
__device__ __forceinline__ uint32_t pack_h2(float lo, float hi) {
    __half2 h = __floats2half2_rn(lo, hi);
    return *reinterpret_cast<uint32_t*>(&h);
}
__device__ __forceinline__ uint32_t smem_u32(const void* p) {
    uint32_t a;
    asm("{ .reg .u64 t; cvta.to.shared.u64 t, %1; cvt.u32.u64 %0, t; }"
        : "=r"(a) : "l"(p));
    return a;
}
__device__ __forceinline__ void cp16(uint32_t sm_dst, const void* g_src) {
    asm volatile("cp.async.cg.shared.global [%0], [%1], 16;"
                 :: "r"(sm_dst), "l"(g_src) : "memory");
}
#define CP_COMMIT() asm volatile("cp.async.commit_group;" ::: "memory")
#define CP_WAIT0()  asm volatile("cp.async.wait_group 0;" ::: "memory")

__device__ __forceinline__ void mma_tf32(
    float c[4], const uint32_t a[4], const uint32_t b[2])
{
    asm volatile(
        "mma.sync.aligned.m16n8k8.row.col.f32.tf32.tf32.f32 "
        "{%0,%1,%2,%3}, {%4,%5,%6,%7}, {%8,%9}, {%0,%1,%2,%3};"
        : "+f"(c[0]), "+f"(c[1]), "+f"(c[2]), "+f"(c[3])
        : "r"(a[0]), "r"(a[1]), "r"(a[2]), "r"(a[3]), "r"(b[0]), "r"(b[1]));
}
__device__ __forceinline__ void mma_f16(
    float c[4], const uint32_t a[4], const uint32_t b[2])
{
    asm volatile(
        "mma.sync.aligned.m16n8k16.row.col.f32.f16.f16.f32 "
        "{%0,%1,%2,%3}, {%4,%5,%6,%7}, {%8,%9}, {%0,%1,%2,%3};"
        : "+f"(c[0]), "+f"(c[1]), "+f"(c[2]), "+f"(c[3])
        : "r"(a[0]), "r"(a[1]), "r"(a[2]), "r"(a[3]), "r"(b[0]), "r"(b[1]));
}

// ===========================================================================
// Fused fp32 -> fp16 converter: all 7 tensors in ONE launch.
// Index space in units of 8 elements (one uint4 of halves out).
// ===========================================================================
#define NA8 ((MTOT*EMB)/8)    // 524288 per activation
#define NW8 ((EMB*EMB)/8)     // 131072 per weight
#define NCVT (3*NA8 + 4*NW8)  // 2097152

__global__ __launch_bounds__(256) void cvt_all(
    const float* __restrict__ q, const float* __restrict__ k, const float* __restrict__ v,
    const float* __restrict__ wq, const float* __restrict__ wk,
    const float* __restrict__ wv, const float* __restrict__ wo,
    __half* __restrict__ dq, __half* __restrict__ dk, __half* __restrict__ dv,
    __half* __restrict__ dwq, __half* __restrict__ dwk,
    __half* __restrict__ dwv, __half* __restrict__ dwo)
{
    const int i = blockIdx.x * 256 + threadIdx.x;
    if (i >= NCVT) return;
    const float* s;
    __half* d;
    int off;
    if (i < 3 * NA8) {
        const int seg = i / NA8;
        off = i - seg * NA8;
        s = (seg == 0) ? q : (seg == 1) ? k : v;
        d = (seg == 0) ? dq : (seg == 1) ? dk : dv;
    } else {
        const int j = i - 3 * NA8;
        const int seg = j / NW8;
        off = j - seg * NW8;
        s = (seg == 0) ? wq : (seg == 1) ? wk : (seg == 2) ? wv : wo;
        d = (seg == 0) ? dwq : (seg == 1) ? dwk : (seg == 2) ? dwv : dwo;
    }
    const float4* sp = reinterpret_cast<const float4*>(s) + (size_t)off * 2;
    float4 a = sp[0], b = sp[1];
    reinterpret_cast<uint4*>(d)[off] =
        make_uint4(pack_h2(a.x,a.y), pack_h2(a.z,a.w),
                   pack_h2(b.x,b.y), pack_h2(b.z,b.w));
}

// ===========================================================================
// fp16 GEMM (fp32 accum): C = alpha * (A[M,K] @ B[N,K]^T + bias[N])
// R15: 256 threads / 8 warps, warp tile 64x32 (acc 64 regs -> no spills,
//      16 warps/SM at 2 CTAs), cp.async staging, BK=32 halves, swizzled smem.
// ===========================================================================
#define GEMM_SMEM (2 * 2 * 2048 * 4)   // 32768 B

template<bool HALF_OUT>
__device__ __forceinline__ void gemm_body_h(
    const __half* __restrict__ A, const __half* __restrict__ B,
    const float* __restrict__ bias, void* __restrict__ Cv,
    int M, int N, int K, float alpha)
{
    extern __shared__ uint32_t gsm[];
    const uint32_t sbase = smem_u32(gsm);

    const int tid  = threadIdx.x;
    const int lane = tid & 31;
    const int wid  = tid >> 5;          // 0..7
    const int wm   = (wid & 1) * 64;
    const int wn   = (wid >> 1) * 32;
    const int m0 = blockIdx.y * 128;
    const int n0 = blockIdx.x * 128;

    const int lr = lane >> 2;
    const int lc = lane & 3;

    const int srow = tid >> 2;          // 0..63
    const int sch  = tid & 3;           // 16B chunk (8 halves)

    float acc[4][4][4];
    #pragma unroll
    for (int i = 0; i < 4; i++)
        #pragma unroll
        for (int j = 0; j < 4; j++)
            #pragma unroll
            for (int r = 0; r < 4; r++) acc[i][j][r] = 0.f;

    auto swoff = [](int row, int ch) -> uint32_t {
        return (uint32_t)(row * 16 + (((ch ^ ((row >> 1) & 3)) & 3) << 2));
    };

    auto stage = [&](int buf, int kc) {
        const int koff = kc * 32 + sch * 8;   // halves
        #pragma unroll
        for (int i = 0; i < 2; i++) {
            const int row = srow + i * 64;
            const uint32_t so = swoff(row, sch);
            cp16(sbase + (buf * 2048 + so) * 4,
                 A + (size_t)(m0 + row) * K + koff);
            cp16(sbase + (4096 + buf * 2048 + so) * 4,
                 B + (size_t)(n0 + row) * K + koff);
        }
        CP_COMMIT();
    };

    stage(0, 0);
    CP_WAIT0();
    __syncthreads();

    const int nk = K / 32;
    for (int kc = 0; kc < nk; kc++) {
        const int buf = kc & 1;
        const bool more = (kc + 1 < nk);
        if (more) stage(buf ^ 1, kc + 1);

        const uint32_t* Ab = gsm + buf * 2048;
        const uint32_t* Bb = gsm + 4096 + buf * 2048;

        #pragma unroll
        for (int s = 0; s < 2; s++) {
            uint32_t af[4][4], bf[4][2];
            #pragma unroll
            for (int i = 0; i < 4; i++) {
                const int row = wm + i * 16 + lr;
                const uint32_t g = (uint32_t)((row >> 1) & 3);
                const uint32_t x0 = (((uint32_t)(2*s)     ^ g) & 3) << 2;
                const uint32_t x1 = (((uint32_t)(2*s + 1) ^ g) & 3) << 2;
                const uint32_t ra = (uint32_t)row * 16;
                af[i][0] = Ab[ra       + x0 + lc];
                af[i][1] = Ab[ra + 128 + x0 + lc];
                af[i][2] = Ab[ra       + x1 + lc];
                af[i][3] = Ab[ra + 128 + x1 + lc];
            }
            #pragma unroll
            for (int j = 0; j < 4; j++) {
                const int row = wn + j * 8 + lr;
                const uint32_t g = (uint32_t)((row >> 1) & 3);
                const uint32_t x0 = (((uint32_t)(2*s)     ^ g) & 3) << 2;
                const uint32_t x1 = (((uint32_t)(2*s + 1) ^ g) & 3) << 2;
                const uint32_t rb = (uint32_t)row * 16;
                bf[j][0] = Bb[rb + x0 + lc];
                bf[j][1] = Bb[rb + x1 + lc];
            }
            #pragma unroll
            for (int i = 0; i < 4; i++)
                #pragma unroll
                for (int j = 0; j < 4; j++)
                    mma_f16(acc[i][j], af[i], bf[j]);
        }

        if (more) CP_WAIT0();
        __syncthreads();
    }

    // ---- epilogue ----
    #pragma unroll
    for (int j = 0; j < 4; j++) {
        const int col = n0 + wn + j * 8 + lc * 2;
        const float b0 = bias[col], b1 = bias[col + 1];
        #pragma unroll
        for (int i = 0; i < 4; i++) {
            const int row = m0 + wm + i * 16 + lr;
            const float o00 = alpha * (acc[i][j][0] + b0);
            const float o01 = alpha * (acc[i][j][1] + b1);
            const float o10 = alpha * (acc[i][j][2] + b0);
            const float o11 = alpha * (acc[i][j][3] + b1);
            if (HALF_OUT) {
                __half* C = reinterpret_cast<__half*>(Cv);
                *reinterpret_cast<uint32_t*>(&C[(size_t)row * N + col]) =
                    pack_h2(o00, o01);
                *reinterpret_cast<uint32_t*>(&C[(size_t)(row + 8) * N + col]) =
                    pack_h2(o10, o11);
            } else {
                float* C = reinterpret_cast<float*>(Cv);
                *reinterpret_cast<float2*>(&C[(size_t)row * N + col]) =
                    make_float2(o00, o01);
                *reinterpret_cast<float2*>(&C[(size_t)(row + 8) * N + col]) =
                    make_float2(o10, o11);
            }
        }
    }
}

// Fused QKV: one launch, blockIdx.z selects the projection. fp16 out.
__global__ __launch_bounds__(256, 2) void gemm_qkv_h(
    const __half* __restrict__ Aq, const __half* __restrict__ Ak, const __half* __restrict__ Av,
    const __half* __restrict__ Wq, const __half* __restrict__ Wk, const __half* __restrict__ Wv,
    const float* __restrict__ bq, const float* __restrict__ bk, const float* __restrict__ bv,
    __half* __restrict__ Cq, __half* __restrict__ Ck, __half* __restrict__ Cv)
{
    const int z = blockIdx.z;
    const __half* A = (z == 0) ? Aq : (z == 1) ? Ak : Av;
    const __half* W = (z == 0) ? Wq : (z == 1) ? Wk : Wv;
    const float*  b = (z == 0) ? bq : (z == 1) ? bk : bv;
    __half*       C = (z == 0) ? Cq : (z == 1) ? Ck : Cv;
    const float alpha = (z == 0) ? 0.03125f : 1.0f;   // softmax scale in Q
    gemm_body_h<true>(A, W, b, C, MTOT, EMB, EMB, alpha);
}

// Output GEMM: fp16 in, fp32 out.
__global__ __launch_bounds__(256, 2) void gemm_out_h(
    const __half* __restrict__ A, const __half* __restrict__ B,
    const float* __restrict__ bias, float* __restrict__ C)
{
    gemm_body_h<false>(A, B, bias, C, MTOT, EMB, EMB, 1.0f);
}

// ===========================================================================
// Flash attention, causal. fp16 Q/K (m16n8k16 QK^T), tf32 P.V.
// (unchanged from R14 — proven, rel_err 3.688e-4)
// ===========================================================================
#define QSTR 36
#define VSTR 72
#define PSTR 36
#define BKT  32
#define ATTN_SMEM ((128*QSTR + BKT*QSTR + BKT*VSTR + 128*PSTR) * 4)   // 50688 B

__global__ __launch_bounds__(128, 3) void attn_mma(
    const __half* __restrict__ Q, const __half* __restrict__ K,
    const __half* __restrict__ V, __half* __restrict__ O)
{
    extern __shared__ uint32_t sm[];
    uint32_t (*Qs)[QSTR] = reinterpret_cast<uint32_t(*)[QSTR]>(sm);
    uint32_t (*Ks)[QSTR] = reinterpret_cast<uint32_t(*)[QSTR]>(sm + 128*QSTR);
    uint32_t (*Vs)[VSTR] = reinterpret_cast<uint32_t(*)[VSTR]>(sm + 128*QSTR + BKT*QSTR);
    uint32_t (*Ps)[PSTR] = reinterpret_cast<uint32_t(*)[PSTR]>(sm + 128*QSTR + BKT*QSTR + BKT*VSTR);

    const int tid  = threadIdx.x;
    const int lane = tid & 31;
    const int wid  = tid >> 5;
    const int lr   = lane >> 2;
    const int lc   = lane & 3;
    const int wq   = wid * 32;

    const int q0 = (gridDim.x - 1 - blockIdx.x) * 128;   // heavy tiles first
    const int h  = blockIdx.y;
    const int nb = blockIdx.z;

    const __half* qbase = Q + (size_t)nb * SEQ * EMB + h * HDIM;
    const __half* kbase = K + (size_t)nb * SEQ * EMB + h * HDIM;
    const __half* vbase = V + (size_t)nb * SEQ * EMB + h * HDIM;

    #pragma unroll
    for (int i = 0; i < 8; i++) {
        const int idx = tid + i * 128;
        const int row = idx >> 3, cw = idx & 7;
        *reinterpret_cast<uint4*>(&Qs[row][cw * 4]) =
            *reinterpret_cast<const uint4*>(&qbase[(size_t)(q0 + row) * EMB + cw * 8]);
    }

    float mrow[2][2], lsum[2][2];
    #pragma unroll
    for (int t = 0; t < 2; t++) {
        mrow[t][0] = -1e30f; mrow[t][1] = -1e30f;
        lsum[t][0] = 0.f;    lsum[t][1] = 0.f;
    }
    float oacc[2][8][4];
    #pragma unroll
    for (int t = 0; t < 2; t++)
        #pragma unroll
        for (int j = 0; j < 8; j++)
            #pragma unroll
            for (int r = 0; r < 4; r++) oacc[t][j][r] = 0.f;

    const int nkt = (q0 + 128) / BKT;
    for (int kt = 0; kt < nkt; kt++) {
        const int kb = kt * BKT;
        __syncthreads();

        #pragma unroll
        for (int i = 0; i < 2; i++) {
            const int idx = tid + i * 128;
            const int row = idx >> 3, cw = idx & 7;
            *reinterpret_cast<uint4*>(&Ks[row][cw * 4]) =
                *reinterpret_cast<const uint4*>(&kbase[(size_t)(kb + row) * EMB + cw * 8]);
        }
        #pragma unroll
        for (int i = 0; i < 4; i++) {
            const int idx = tid + i * 128;
            const int row = idx >> 4, c4 = idx & 15;
            const uint2 hv = *reinterpret_cast<const uint2*>(
                &vbase[(size_t)(kb + row) * EMB + c4 * 4]);
            const __half2 p0 = *reinterpret_cast<const __half2*>(&hv.x);
            const __half2 p1 = *reinterpret_cast<const __half2*>(&hv.y);
            const float2 f0 = __half22float2(p0);
            const float2 f1 = __half22float2(p1);
            *reinterpret_cast<uint4*>(&Vs[row][c4 * 4]) =
                make_uint4(f2tf32(f0.x), f2tf32(f0.y), f2tf32(f1.x), f2tf32(f1.y));
        }
        __syncthreads();

        if (kb > q0 + wq + 31) continue;

        float sacc[2][4][4];
        #pragma unroll
        for (int t = 0; t < 2; t++)
            #pragma unroll
            for (int j = 0; j < 4; j++)
                #pragma unroll
                for (int r = 0; r < 4; r++) sacc[t][j][r] = 0.f;

        #pragma unroll
        for (int s = 0; s < 4; s++) {
            uint32_t af[2][4];
            #pragma unroll
            for (int t = 0; t < 2; t++) {
                const int mr = wq + t * 16 + lr;
                af[t][0] = Qs[mr    ][s*8 + lc    ];
                af[t][1] = Qs[mr + 8][s*8 + lc    ];
                af[t][2] = Qs[mr    ][s*8 + lc + 4];
                af[t][3] = Qs[mr + 8][s*8 + lc + 4];
            }
            #pragma unroll
            for (int j = 0; j < 4; j++) {
                uint32_t bf[2];
                bf[0] = Ks[j*8 + lr][s*8 + lc    ];
                bf[1] = Ks[j*8 + lr][s*8 + lc + 4];
                mma_f16(sacc[0][j], af[0], bf);
                mma_f16(sacc[1][j], af[1], bf);
            }
        }

        if (kb + BKT - 1 > q0 + wq) {
            #pragma unroll
            for (int t = 0; t < 2; t++) {
                const int r0 = q0 + wq + t*16 + lr, r1 = r0 + 8;
                #pragma unroll
                for (int j = 0; j < 4; j++) {
                    const int c0 = kb + j*8 + 2*lc, c1 = c0 + 1;
                    if (c0 > r0) sacc[t][j][0] = -1e30f;
                    if (c1 > r0) sacc[t][j][1] = -1e30f;
                    if (c0 > r1) sacc[t][j][2] = -1e30f;
                    if (c1 > r1) sacc[t][j][3] = -1e30f;
                }
            }
        }

        #pragma unroll
        for (int t = 0; t < 2; t++) {
            float mt0 = -1e30f, mt1 = -1e30f;
            #pragma unroll
            for (int j = 0; j < 4; j++) {
                mt0 = fmaxf(mt0, fmaxf(sacc[t][j][0], sacc[t][j][1]));
                mt1 = fmaxf(mt1, fmaxf(sacc[t][j][2], sacc[t][j][3]));
            }
            mt0 = fmaxf(mt0, __shfl_xor_sync(0xffffffffu, mt0, 1));
            mt0 = fmaxf(mt0, __shfl_xor_sync(0xffffffffu, mt0, 2));
            mt1 = fmaxf(mt1, __shfl_xor_sync(0xffffffffu, mt1, 1));
            mt1 = fmaxf(mt1, __shfl_xor_sync(0xffffffffu, mt1, 2));

            const float mn0 = fmaxf(mrow[t][0], mt0);
            const float mn1 = fmaxf(mrow[t][1], mt1);
            const float cor0 = __expf(mrow[t][0] - mn0);
            const float cor1 = __expf(mrow[t][1] - mn1);
            mrow[t][0] = mn0; mrow[t][1] = mn1;

            float ls0 = 0.f, ls1 = 0.f;
            #pragma unroll
            for (int j = 0; j < 4; j++) {
                sacc[t][j][0] = __expf(sacc[t][j][0] - mn0);
                sacc[t][j][1] = __expf(sacc[t][j][1] - mn0);
                sacc[t][j][2] = __expf(sacc[t][j][2] - mn1);
                sacc[t][j][3] = __expf(sacc[t][j][3] - mn1);
                ls0 += sacc[t][j][0] + sacc[t][j][1];
                ls1 += sacc[t][j][2] + sacc[t][j][3];
            }
            ls0 += __shfl_xor_sync(0xffffffffu, ls0, 1);
            ls0 += __shfl_xor_sync(0xffffffffu, ls0, 2);
            ls1 += __shfl_xor_sync(0xffffffffu, ls1, 1);
            ls1 += __shfl_xor_sync(0xffffffffu, ls1, 2);
            lsum[t][0] = lsum[t][0] * cor0 + ls0;
            lsum[t][1] = lsum[t][1] * cor1 + ls1;

            #pragma unroll
            for (int j = 0; j < 8; j++) {
                oacc[t][j][0] *= cor0; oacc[t][j][1] *= cor0;
                oacc[t][j][2] *= cor1; oacc[t][j][3] *= cor1;
            }
        }

        #pragma unroll
        for (int t = 0; t < 2; t++) {
            const int mr = wq + t * 16 + lr;
            #pragma unroll
            for (int j = 0; j < 4; j++) {
                *reinterpret_cast<uint2*>(&Ps[mr    ][j*8 + 2*lc]) =
                    make_uint2(f2tf32(sacc[t][j][0]), f2tf32(sacc[t][j][1]));
                *reinterpret_cast<uint2*>(&Ps[mr + 8][j*8 + 2*lc]) =
                    make_uint2(f2tf32(sacc[t][j][2]), f2tf32(sacc[t][j][3]));
            }
        }
        __syncwarp();

        #pragma unroll
        for (int s = 0; s < 4; s++) {
            uint32_t af[2][4];
            #pragma unroll
            for (int t = 0; t < 2; t++) {
                const int mr = wq + t * 16 + lr;
                af[t][0] = Ps[mr    ][s*8 + lc    ];
                af[t][1] = Ps[mr + 8][s*8 + lc    ];
                af[t][2] = Ps[mr    ][s*8 + lc + 4];
                af[t][3] = Ps[mr + 8][s*8 + lc + 4];
            }
            #pragma unroll
            for (int j = 0; j < 8; j++) {
                uint32_t bf[2];
                bf[0] = Vs[s*8 + lc    ][j*8 + lr];
                bf[1] = Vs[s*8 + lc + 4][j*8 + lr];
                mma_tf32(oacc[0][j], af[0], bf);
                mma_tf32(oacc[1][j], af[1], bf);
            }
        }
        __syncwarp();
    }

    #pragma unroll
    for (int t = 0; t < 2; t++) {
        const float inv0 = 1.f / lsum[t][0];
        const float inv1 = 1.f / lsum[t][1];
        const size_t row0 = (size_t)nb * SEQ + q0 + wq + t*16 + lr;
        const size_t row1 = row0 + 8;
        #pragma unroll
        for (int j = 0; j < 8; j++) {
            const int col = h * HDIM + j*8 + 2*lc;
            *reinterpret_cast<uint32_t*>(&O[row0 * EMB + col]) =
                pack_h2(oacc[t][j][0] * inv0, oacc[t][j][1] * inv0);
            *reinterpret_cast<uint32_t*>(&O[row1 * EMB + col]) =
                pack_h2(oacc[t][j][2] * inv1, oacc[t][j][3] * inv1);
        }
    }
}

// ---------------------------------------------------------------------------
// Inputs: 0 values, 1 keys, 2 query, 3 mask(unused), 4 Wv, 5 bv, 6 Wk, 7 bk,
//         8 Wq, 9 bq, 10 Wo, 11 bo
// ---------------------------------------------------------------------------
extern "C" void kernel_launch(void* const* d_in, const int* in_sizes, int n_in,
                              void* d_out, int out_size)
{
    const float* values = (const float*)d_in[0];
    const float* keys   = (const float*)d_in[1];
    const float* query  = (const float*)d_in[2];
    const float* Wv = (const float*)d_in[4];
    const float* bv = (const float*)d_in[5];
    const float* Wk = (const float*)d_in[6];
    const float* bk = (const float*)d_in[7];
    const float* Wq = (const float*)d_in[8];
    const float* bq = (const float*)d_in[9];
    const float* Wo = (const float*)d_in[10];
    const float* bo = (const float*)d_in[11];
    float* out = (float*)d_out;

    __half *pQ, *pK, *pV, *pWq, *pWk, *pWv, *pWo, *pqh, *pkh, *pvh, *pah;
    cudaGetSymbolAddress((void**)&pQ,  h_query);
    cudaGetSymbolAddress((void**)&pK,  h_keys);
    cudaGetSymbolAddress((void**)&pV,  h_vals);
    cudaGetSymbolAddress((void**)&pWq, h_wq);
    cudaGetSymbolAddress((void**)&pWk, h_wk);
    cudaGetSymbolAddress((void**)&pWv, h_wv);
    cudaGetSymbolAddress((void**)&pWo, h_wo);
    cudaGetSymbolAddress((void**)&pqh, g_qh);
    cudaGetSymbolAddress((void**)&pkh, g_kh);
    cudaGetSymbolAddress((void**)&pvh, g_vh);
    cudaGetSymbolAddress((void**)&pah, g_aoh);

    cudaFuncSetAttribute(attn_mma,
                         cudaFuncAttributeMaxDynamicSharedMemorySize, ATTN_SMEM);
    cudaFuncSetAttribute(gemm_qkv_h,
                         cudaFuncAttributeMaxDynamicSharedMemorySize, GEMM_SMEM);
    cudaFuncSetAttribute(gemm_out_h,
                         cudaFuncAttributeMaxDynamicSharedMemorySize, GEMM_SMEM);

    // Fused fp32 -> fp16 conversion: one launch for all 7 tensors
    cvt_all<<<(NCVT + 255) / 256, 256>>>(query, keys, values,
                                         Wq, Wk, Wv, Wo,
                                         pQ, pK, pV, pWq, pWk, pWv, pWo);

    // Fused Q/K/V projections: 8 x 32 x 3 = 768 CTAs
    dim3 gqkv(EMB / 128, MTOT / 128, 3);
    gemm_qkv_h<<<gqkv, 256, GEMM_SMEM>>>(pQ, pK, pV,
                                         pWq, pWk, pWv, bq, bk, bv,
                                         pqh, pkh, pvh);

    dim3 gattn(SEQ / 128, NHEAD, N_BATCH);  // 16 x 16 x 2 = 512 blocks
    attn_mma<<<gattn, 128, ATTN_SMEM>>>(pqh, pkh, pvh, pah);

    dim3 gproj(EMB / 128, MTOT / 128);
    gemm_out_h<<<gproj, 256, GEMM_SMEM>>>(pah, pWo, bo, out);
}

// round 16
// speedup vs baseline: 6.3268x; 1.1528x over previous
#include <cuda_runtime.h>
#include <cuda_fp16.h>
#include <cstdint>

#define N_BATCH 2
#define SEQ     2048
#define EMB     1024
#define NHEAD   16
#define HDIM    64
#define MTOT    (N_BATCH*SEQ)   // 4096

// Scratch (allocation-free rule: __device__ globals), all fp16
__device__ __half h_query[(size_t)MTOT*EMB];
__device__ __half h_keys [(size_t)MTOT*EMB];
__device__ __half h_vals [(size_t)MTOT*EMB];
__device__ __half h_wq[(size_t)EMB*EMB];
__device__ __half h_wk[(size_t)EMB*EMB];
__device__ __half h_wv[(size_t)EMB*EMB];
__device__ __half h_wo[(size_t)EMB*EMB];
__device__ __half g_qh[(size_t)MTOT*EMB];
__device__ __half g_kh[(size_t)MTOT*EMB];
__device__ __half g_vh[(size_t)MTOT*EMB];
__device__ __half g_aoh[(size_t)MTOT*EMB];

__device__ __forceinline__ uint32_t pack_h2(float lo, float hi) {
    __half2 h = __floats2half2_rn(lo, hi);
    return *reinterpret_cast<uint32_t*>(&h);
}
__device__ __forceinline__ uint32_t smem_u32(const void* p) {
    uint32_t a;
    asm("{ .reg .u64 t; cvta.to.shared.u64 t, %1; cvt.u32.u64 %0, t; }"
        : "=r"(a) : "l"(p));
    return a;
}
__device__ __forceinline__ void cp16(uint32_t sm_dst, const void* g_src) {
    asm volatile("cp.async.cg.shared.global [%0], [%1], 16;"
                 :: "r"(sm_dst), "l"(g_src) : "memory");
}
#define CP_COMMIT() asm volatile("cp.async.commit_group;" ::: "memory")
#define CP_WAIT0()  asm volatile("cp.async.wait_group 0;" ::: "memory")
#define CP_WAIT1()  asm volatile("cp.async.wait_group 1;" ::: "memory")

__device__ __forceinline__ void mma_f16(
    float c[4], const uint32_t a[4], const uint32_t b[2])
{
    asm volatile(
        "mma.sync.aligned.m16n8k16.row.col.f32.f16.f16.f32 "
        "{%0,%1,%2,%3}, {%4,%5,%6,%7}, {%8,%9}, {%0,%1,%2,%3};"
        : "+f"(c[0]), "+f"(c[1]), "+f"(c[2]), "+f"(c[3])
        : "r"(a[0]), "r"(a[1]), "r"(a[2]), "r"(a[3]), "r"(b[0]), "r"(b[1]));
}

// ===========================================================================
// Fused fp32 -> fp16 converter: all 7 tensors in ONE launch.
// ===========================================================================
#define NA8 ((MTOT*EMB)/8)
#define NW8 ((EMB*EMB)/8)
#define NCVT (3*NA8 + 4*NW8)

__global__ __launch_bounds__(256) void cvt_all(
    const float* __restrict__ q, const float* __restrict__ k, const float* __restrict__ v,
    const float* __restrict__ wq, const float* __restrict__ wk,
    const float* __restrict__ wv, const float* __restrict__ wo,
    __half* __restrict__ dq, __half* __restrict__ dk, __half* __restrict__ dv,
    __half* __restrict__ dwq, __half* __restrict__ dwk,
    __half* __restrict__ dwv, __half* __restrict__ dwo)
{
    const int i = blockIdx.x * 256 + threadIdx.x;
    if (i >= NCVT) return;
    const float* s;
    __half* d;
    int off;
    if (i < 3 * NA8) {
        const int seg = i / NA8;
        off = i - seg * NA8;
        s = (seg == 0) ? q : (seg == 1) ? k : v;
        d = (seg == 0) ? dq : (seg == 1) ? dk : dv;
    } else {
        const int j = i - 3 * NA8;
        const int seg = j / NW8;
        off = j - seg * NW8;
        s = (seg == 0) ? wq : (seg == 1) ? wk : (seg == 2) ? wv : wo;
        d = (seg == 0) ? dwq : (seg == 1) ? dwk : (seg == 2) ? dwv : dwo;
    }
    const float4* sp = reinterpret_cast<const float4*>(s) + (size_t)off * 2;
    float4 a = sp[0], b = sp[1];
    reinterpret_cast<uint4*>(d)[off] =
        make_uint4(pack_h2(a.x,a.y), pack_h2(a.z,a.w),
                   pack_h2(b.x,b.y), pack_h2(b.z,b.w));
}

// ===========================================================================
// fp16 GEMM (fp32 accum): C = alpha * (A[M,K] @ B[N,K]^T + bias[N])
// R16: 3-stage cp.async pipeline (wait_group 1), 256 threads / 8 warps,
//      warp tile 64x32, BK=32 halves, swizzled smem.
// ===========================================================================
#define GEMM_SMEM (3 * 2 * 2048 * 4)   // 49152 B

template<bool HALF_OUT>
__device__ __forceinline__ void gemm_body_h(
    const __half* __restrict__ A, const __half* __restrict__ B,
    const float* __restrict__ bias, void* __restrict__ Cv,
    int M, int N, int K, float alpha)
{
    extern __shared__ uint32_t gsm[];
    const uint32_t sbase = smem_u32(gsm);

    const int tid  = threadIdx.x;
    const int lane = tid & 31;
    const int wid  = tid >> 5;          // 0..7
    const int wm   = (wid & 1) * 64;
    const int wn   = (wid >> 1) * 32;
    const int m0 = blockIdx.y * 128;
    const int n0 = blockIdx.x * 128;

    const int lr = lane >> 2;
    const int lc = lane & 3;

    const int srow = tid >> 2;          // 0..63
    const int sch  = tid & 3;           // 16B chunk (8 halves)

    float acc[4][4][4];
    #pragma unroll
    for (int i = 0; i < 4; i++)
        #pragma unroll
        for (int j = 0; j < 4; j++)
            #pragma unroll
            for (int r = 0; r < 4; r++) acc[i][j][r] = 0.f;

    auto swoff = [](int row, int ch) -> uint32_t {
        return (uint32_t)(row * 16 + (((ch ^ ((row >> 1) & 3)) & 3) << 2));
    };

    auto stage = [&](int buf, int kc) {
        const int koff = kc * 32 + sch * 8;   // halves
        #pragma unroll
        for (int i = 0; i < 2; i++) {
            const int row = srow + i * 64;
            const uint32_t so = swoff(row, sch);
            cp16(sbase + (buf * 2048 + so) * 4,
                 A + (size_t)(m0 + row) * K + koff);
            cp16(sbase + (6144 + buf * 2048 + so) * 4,
                 B + (size_t)(n0 + row) * K + koff);
        }
        CP_COMMIT();
    };

    const int nk = K / 32;
    stage(0, 0);
    if (nk > 1) stage(1, 1);
    CP_WAIT1();              // buffer 0 landed
    __syncthreads();

    for (int kc = 0; kc < nk; kc++) {
        const int buf = kc % 3;
        if (kc + 2 < nk) stage((kc + 2) % 3, kc + 2);

        const uint32_t* Ab = gsm + buf * 2048;
        const uint32_t* Bb = gsm + 6144 + buf * 2048;

        #pragma unroll
        for (int s = 0; s < 2; s++) {
            uint32_t af[4][4], bf[4][2];
            #pragma unroll
            for (int i = 0; i < 4; i++) {
                const int row = wm + i * 16 + lr;
                const uint32_t g = (uint32_t)((row >> 1) & 3);
                const uint32_t x0 = (((uint32_t)(2*s)     ^ g) & 3) << 2;
                const uint32_t x1 = (((uint32_t)(2*s + 1) ^ g) & 3) << 2;
                const uint32_t ra = (uint32_t)row * 16;
                af[i][0] = Ab[ra       + x0 + lc];
                af[i][1] = Ab[ra + 128 + x0 + lc];
                af[i][2] = Ab[ra       + x1 + lc];
                af[i][3] = Ab[ra + 128 + x1 + lc];
            }
            #pragma unroll
            for (int j = 0; j < 4; j++) {
                const int row = wn + j * 8 + lr;
                const uint32_t g = (uint32_t)((row >> 1) & 3);
                const uint32_t x0 = (((uint32_t)(2*s)     ^ g) & 3) << 2;
                const uint32_t x1 = (((uint32_t)(2*s + 1) ^ g) & 3) << 2;
                const uint32_t rb = (uint32_t)row * 16;
                bf[j][0] = Bb[rb + x0 + lc];
                bf[j][1] = Bb[rb + x1 + lc];
            }
            #pragma unroll
            for (int i = 0; i < 4; i++)
                #pragma unroll
                for (int j = 0; j < 4; j++)
                    mma_f16(acc[i][j], af[i], bf[j]);
        }

        // next buffer must be landed before compute; keep ≤1 group in flight
        if (kc + 1 < nk) CP_WAIT1();
        __syncthreads();
    }

    // ---- epilogue ----
    #pragma unroll
    for (int j = 0; j < 4; j++) {
        const int col = n0 + wn + j * 8 + lc * 2;
        const float b0 = bias[col], b1 = bias[col + 1];
        #pragma unroll
        for (int i = 0; i < 4; i++) {
            const int row = m0 + wm + i * 16 + lr;
            const float o00 = alpha * (acc[i][j][0] + b0);
            const float o01 = alpha * (acc[i][j][1] + b1);
            const float o10 = alpha * (acc[i][j][2] + b0);
            const float o11 = alpha * (acc[i][j][3] + b1);
            if (HALF_OUT) {
                __half* C = reinterpret_cast<__half*>(Cv);
                *reinterpret_cast<uint32_t*>(&C[(size_t)row * N + col]) =
                    pack_h2(o00, o01);
                *reinterpret_cast<uint32_t*>(&C[(size_t)(row + 8) * N + col]) =
                    pack_h2(o10, o11);
            } else {
                float* C = reinterpret_cast<float*>(Cv);
                *reinterpret_cast<float2*>(&C[(size_t)row * N + col]) =
                    make_float2(o00, o01);
                *reinterpret_cast<float2*>(&C[(size_t)(row + 8) * N + col]) =
                    make_float2(o10, o11);
            }
        }
    }
}

__global__ __launch_bounds__(256, 2) void gemm_qkv_h(
    const __half* __restrict__ Aq, const __half* __restrict__ Ak, const __half* __restrict__ Av,
    const __half* __restrict__ Wq, const __half* __restrict__ Wk, const __half* __restrict__ Wv,
    const float* __restrict__ bq, const float* __restrict__ bk, const float* __restrict__ bv,
    __half* __restrict__ Cq, __half* __restrict__ Ck, __half* __restrict__ Cv)
{
    const int z = blockIdx.z;
    const __half* A = (z == 0) ? Aq : (z == 1) ? Ak : Av;
    const __half* W = (z == 0) ? Wq : (z == 1) ? Wk : Wv;
    const float*  b = (z == 0) ? bq : (z == 1) ? bk : bv;
    __half*       C = (z == 0) ? Cq : (z == 1) ? Ck : Cv;
    const float alpha = (z == 0) ? 0.03125f : 1.0f;
    gemm_body_h<true>(A, W, b, C, MTOT, EMB, EMB, alpha);
}

__global__ __launch_bounds__(256, 2) void gemm_out_h(
    const __half* __restrict__ A, const __half* __restrict__ B,
    const float* __restrict__ bias, float* __restrict__ C)
{
    gemm_body_h<false>(A, B, bias, C, MTOT, EMB, EMB, 1.0f);
}

// ===========================================================================
// Flash attention, causal — R16: ALL fp16 MMAs.
// QK^T fp16 as before. P.V now fp16: V staged as packed key-pairs
//   Vp[kp][d] = (V[2kp][d], V[2kp+1][d])  (exact col-major B fragment layout),
// P stored as fp16 pair-words Ps[q][k/2] (stride 20 -> banks 20*lr+lc all
// distinct). No tf32 anywhere. Smem 37888 B -> 3 CTAs/SM.
// ===========================================================================
#define QSTR 36
#define VPSTR 72
#define PSTR 20
#define BKT  32
#define ATTN_SMEM ((128*QSTR + BKT*QSTR + 16*VPSTR + 128*PSTR) * 4)   // 37888 B

__global__ __launch_bounds__(128, 3) void attn_mma(
    const __half* __restrict__ Q, const __half* __restrict__ K,
    const __half* __restrict__ V, __half* __restrict__ O)
{
    extern __shared__ uint32_t sm[];
    uint32_t (*Qs)[QSTR]  = reinterpret_cast<uint32_t(*)[QSTR]>(sm);
    uint32_t (*Ks)[QSTR]  = reinterpret_cast<uint32_t(*)[QSTR]>(sm + 128*QSTR);
    uint32_t (*Vp)[VPSTR] = reinterpret_cast<uint32_t(*)[VPSTR]>(sm + 128*QSTR + BKT*QSTR);
    uint32_t (*Ps)[PSTR]  = reinterpret_cast<uint32_t(*)[PSTR]>(sm + 128*QSTR + BKT*QSTR + 16*VPSTR);

    const int tid  = threadIdx.x;
    const int lane = tid & 31;
    const int wid  = tid >> 5;
    const int lr   = lane >> 2;
    const int lc   = lane & 3;
    const int wq   = wid * 32;

    const int q0 = (gridDim.x - 1 - blockIdx.x) * 128;   // heavy tiles first
    const int h  = blockIdx.y;
    const int nb = blockIdx.z;

    const __half* qbase = Q + (size_t)nb * SEQ * EMB + h * HDIM;
    const __half* kbase = K + (size_t)nb * SEQ * EMB + h * HDIM;
    const __half* vbase = V + (size_t)nb * SEQ * EMB + h * HDIM;

    // ---- load Q tile (128 x 64 halves), plain copy ----
    #pragma unroll
    for (int i = 0; i < 8; i++) {
        const int idx = tid + i * 128;
        const int row = idx >> 3, cw = idx & 7;
        *reinterpret_cast<uint4*>(&Qs[row][cw * 4]) =
            *reinterpret_cast<const uint4*>(&qbase[(size_t)(q0 + row) * EMB + cw * 8]);
    }

    float mrow[2][2], lsum[2][2];
    #pragma unroll
    for (int t = 0; t < 2; t++) {
        mrow[t][0] = -1e30f; mrow[t][1] = -1e30f;
        lsum[t][0] = 0.f;    lsum[t][1] = 0.f;
    }
    float oacc[2][8][4];
    #pragma unroll
    for (int t = 0; t < 2; t++)
        #pragma unroll
        for (int j = 0; j < 8; j++)
            #pragma unroll
            for (int r = 0; r < 4; r++) oacc[t][j][r] = 0.f;

    const int nkt = (q0 + 128) / BKT;
    for (int kt = 0; kt < nkt; kt++) {
        const int kb = kt * BKT;
        __syncthreads();

        // K tile (32 rows x 32 words), plain copy
        #pragma unroll
        for (int i = 0; i < 2; i++) {
            const int idx = tid + i * 128;
            const int row = idx >> 3, cw = idx & 7;
            *reinterpret_cast<uint4*>(&Ks[row][cw * 4]) =
                *reinterpret_cast<const uint4*>(&kbase[(size_t)(kb + row) * EMB + cw * 8]);
        }
        // V tile packed key-pairs: thread -> (kp = tid>>3, dc = tid&7)
        {
            const int kp = tid >> 3, dc = tid & 7;
            const uint4 a = *reinterpret_cast<const uint4*>(
                &vbase[(size_t)(kb + 2*kp)     * EMB + dc * 8]);
            const uint4 b = *reinterpret_cast<const uint4*>(
                &vbase[(size_t)(kb + 2*kp + 1) * EMB + dc * 8]);
            *reinterpret_cast<uint4*>(&Vp[kp][dc * 8]) = make_uint4(
                __byte_perm(a.x, b.x, 0x5410), __byte_perm(a.x, b.x, 0x7632),
                __byte_perm(a.y, b.y, 0x5410), __byte_perm(a.y, b.y, 0x7632));
            *reinterpret_cast<uint4*>(&Vp[kp][dc * 8 + 4]) = make_uint4(
                __byte_perm(a.z, b.z, 0x5410), __byte_perm(a.z, b.z, 0x7632),
                __byte_perm(a.w, b.w, 0x5410), __byte_perm(a.w, b.w, 0x7632));
        }
        __syncthreads();

        if (kb > q0 + wq + 31) continue;

        // ---- S = Q . K^T : fp16, 4 k16-steps over d, 4 j-tiles ----
        float sacc[2][4][4];
        #pragma unroll
        for (int t = 0; t < 2; t++)
            #pragma unroll
            for (int j = 0; j < 4; j++)
                #pragma unroll
                for (int r = 0; r < 4; r++) sacc[t][j][r] = 0.f;

        #pragma unroll
        for (int s = 0; s < 4; s++) {
            uint32_t af[2][4];
            #pragma unroll
            for (int t = 0; t < 2; t++) {
                const int mr = wq + t * 16 + lr;
                af[t][0] = Qs[mr    ][s*8 + lc    ];
                af[t][1] = Qs[mr + 8][s*8 + lc    ];
                af[t][2] = Qs[mr    ][s*8 + lc + 4];
                af[t][3] = Qs[mr + 8][s*8 + lc + 4];
            }
            #pragma unroll
            for (int j = 0; j < 4; j++) {
                uint32_t bf[2];
                bf[0] = Ks[j*8 + lr][s*8 + lc    ];
                bf[1] = Ks[j*8 + lr][s*8 + lc + 4];
                mma_f16(sacc[0][j], af[0], bf);
                mma_f16(sacc[1][j], af[1], bf);
            }
        }

        // ---- causal mask ----
        if (kb + BKT - 1 > q0 + wq) {
            #pragma unroll
            for (int t = 0; t < 2; t++) {
                const int r0 = q0 + wq + t*16 + lr, r1 = r0 + 8;
                #pragma unroll
                for (int j = 0; j < 4; j++) {
                    const int c0 = kb + j*8 + 2*lc, c1 = c0 + 1;
                    if (c0 > r0) sacc[t][j][0] = -1e30f;
                    if (c1 > r0) sacc[t][j][1] = -1e30f;
                    if (c0 > r1) sacc[t][j][2] = -1e30f;
                    if (c1 > r1) sacc[t][j][3] = -1e30f;
                }
            }
        }

        // ---- online softmax per m-tile ----
        #pragma unroll
        for (int t = 0; t < 2; t++) {
            float mt0 = -1e30f, mt1 = -1e30f;
            #pragma unroll
            for (int j = 0; j < 4; j++) {
                mt0 = fmaxf(mt0, fmaxf(sacc[t][j][0], sacc[t][j][1]));
                mt1 = fmaxf(mt1, fmaxf(sacc[t][j][2], sacc[t][j][3]));
            }
            mt0 = fmaxf(mt0, __shfl_xor_sync(0xffffffffu, mt0, 1));
            mt0 = fmaxf(mt0, __shfl_xor_sync(0xffffffffu, mt0, 2));
            mt1 = fmaxf(mt1, __shfl_xor_sync(0xffffffffu, mt1, 1));
            mt1 = fmaxf(mt1, __shfl_xor_sync(0xffffffffu, mt1, 2));

            const float mn0 = fmaxf(mrow[t][0], mt0);
            const float mn1 = fmaxf(mrow[t][1], mt1);
            const float cor0 = __expf(mrow[t][0] - mn0);
            const float cor1 = __expf(mrow[t][1] - mn1);
            mrow[t][0] = mn0; mrow[t][1] = mn1;

            float ls0 = 0.f, ls1 = 0.f;
            #pragma unroll
            for (int j = 0; j < 4; j++) {
                sacc[t][j][0] = __expf(sacc[t][j][0] - mn0);
                sacc[t][j][1] = __expf(sacc[t][j][1] - mn0);
                sacc[t][j][2] = __expf(sacc[t][j][2] - mn1);
                sacc[t][j][3] = __expf(sacc[t][j][3] - mn1);
                ls0 += sacc[t][j][0] + sacc[t][j][1];
                ls1 += sacc[t][j][2] + sacc[t][j][3];
            }
            ls0 += __shfl_xor_sync(0xffffffffu, ls0, 1);
            ls0 += __shfl_xor_sync(0xffffffffu, ls0, 2);
            ls1 += __shfl_xor_sync(0xffffffffu, ls1, 1);
            ls1 += __shfl_xor_sync(0xffffffffu, ls1, 2);
            lsum[t][0] = lsum[t][0] * cor0 + ls0;
            lsum[t][1] = lsum[t][1] * cor1 + ls1;

            #pragma unroll
            for (int j = 0; j < 8; j++) {
                oacc[t][j][0] *= cor0; oacc[t][j][1] *= cor0;
                oacc[t][j][2] *= cor1; oacc[t][j][3] *= cor1;
            }
        }

        // ---- stage P as fp16 pair-words: Ps[q][k/2] ----
        #pragma unroll
        for (int t = 0; t < 2; t++) {
            const int mr = wq + t * 16 + lr;
            #pragma unroll
            for (int j = 0; j < 4; j++) {
                Ps[mr    ][j*4 + lc] = pack_h2(sacc[t][j][0], sacc[t][j][1]);
                Ps[mr + 8][j*4 + lc] = pack_h2(sacc[t][j][2], sacc[t][j][3]);
            }
        }
        __syncwarp();

        // ---- O += P . V  (fp16: 2 k16-steps over 32 keys, 8 d-tiles) ----
        #pragma unroll
        for (int s = 0; s < 2; s++) {
            uint32_t af[2][4];
            #pragma unroll
            for (int t = 0; t < 2; t++) {
                const int mr = wq + t * 16 + lr;
                af[t][0] = Ps[mr    ][s*8 + lc    ];
                af[t][1] = Ps[mr + 8][s*8 + lc    ];
                af[t][2] = Ps[mr    ][s*8 + lc + 4];
                af[t][3] = Ps[mr + 8][s*8 + lc + 4];
            }
            #pragma unroll
            for (int j = 0; j < 8; j++) {
                uint32_t bf[2];
                bf[0] = Vp[s*8 + lc    ][j*8 + lr];
                bf[1] = Vp[s*8 + lc + 4][j*8 + lr];
                mma_f16(oacc[0][j], af[0], bf);
                mma_f16(oacc[1][j], af[1], bf);
            }
        }
        __syncwarp();
    }

    // ---- epilogue: normalize, write fp16 [n, q, h*64 + d] ----
    #pragma unroll
    for (int t = 0; t < 2; t++) {
        const float inv0 = 1.f / lsum[t][0];
        const float inv1 = 1.f / lsum[t][1];
        const size_t row0 = (size_t)nb * SEQ + q0 + wq + t*16 + lr;
        const size_t row1 = row0 + 8;
        #pragma unroll
        for (int j = 0; j < 8; j++) {
            const int col = h * HDIM + j*8 + 2*lc;
            *reinterpret_cast<uint32_t*>(&O[row0 * EMB + col]) =
                pack_h2(oacc[t][j][0] * inv0, oacc[t][j][1] * inv0);
            *reinterpret_cast<uint32_t*>(&O[row1 * EMB + col]) =
                pack_h2(oacc[t][j][2] * inv1, oacc[t][j][3] * inv1);
        }
    }
}

// ---------------------------------------------------------------------------
// Inputs: 0 values, 1 keys, 2 query, 3 mask(unused), 4 Wv, 5 bv, 6 Wk, 7 bk,
//         8 Wq, 9 bq, 10 Wo, 11 bo
// ---------------------------------------------------------------------------
extern "C" void kernel_launch(void* const* d_in, const int* in_sizes, int n_in,
                              void* d_out, int out_size)
{
    const float* values = (const float*)d_in[0];
    const float* keys   = (const float*)d_in[1];
    const float* query  = (const float*)d_in[2];
    const float* Wv = (const float*)d_in[4];
    const float* bv = (const float*)d_in[5];
    const float* Wk = (const float*)d_in[6];
    const float* bk = (const float*)d_in[7];
    const float* Wq = (const float*)d_in[8];
    const float* bq = (const float*)d_in[9];
    const float* Wo = (const float*)d_in[10];
    const float* bo = (const float*)d_in[11];
    float* out = (float*)d_out;

    __half *pQ, *pK, *pV, *pWq, *pWk, *pWv, *pWo, *pqh, *pkh, *pvh, *pah;
    cudaGetSymbolAddress((void**)&pQ,  h_query);
    cudaGetSymbolAddress((void**)&pK,  h_keys);
    cudaGetSymbolAddress((void**)&pV,  h_vals);
    cudaGetSymbolAddress((void**)&pWq, h_wq);
    cudaGetSymbolAddress((void**)&pWk, h_wk);
    cudaGetSymbolAddress((void**)&pWv, h_wv);
    cudaGetSymbolAddress((void**)&pWo, h_wo);
    cudaGetSymbolAddress((void**)&pqh, g_qh);
    cudaGetSymbolAddress((void**)&pkh, g_kh);
    cudaGetSymbolAddress((void**)&pvh, g_vh);
    cudaGetSymbolAddress((void**)&pah, g_aoh);

    cudaFuncSetAttribute(attn_mma,
                         cudaFuncAttributeMaxDynamicSharedMemorySize, ATTN_SMEM);
    cudaFuncSetAttribute(gemm_qkv_h,
                         cudaFuncAttributeMaxDynamicSharedMemorySize, GEMM_SMEM);
    cudaFuncSetAttribute(gemm_out_h,
                         cudaFuncAttributeMaxDynamicSharedMemorySize, GEMM_SMEM);

    // Fused fp32 -> fp16 conversion: one launch for all 7 tensors
    cvt_all<<<(NCVT + 255) / 256, 256>>>(query, keys, values,
                                         Wq, Wk, Wv, Wo,
                                         pQ, pK, pV, pWq, pWk, pWv, pWo);

    // Fused Q/K/V projections: 8 x 32 x 3 = 768 CTAs
    dim3 gqkv(EMB / 128, MTOT / 128, 3);
    gemm_qkv_h<<<gqkv, 256, GEMM_SMEM>>>(pQ, pK, pV,
                                         pWq, pWk, pWv, bq, bk, bv,
                                         pqh, pkh, pvh);

    dim3 gattn(SEQ / 128, NHEAD, N_BATCH);  // 16 x 16 x 2 = 512 blocks
    attn_mma<<<gattn, 128, ATTN_SMEM>>>(pqh, pkh, pvh, pah);

    dim3 gproj(EMB / 128, MTOT / 128);
    gemm_out_h<<<gproj, 256, GEMM_SMEM>>>(pah, pWo, bo, out);
}

// round 17
// speedup vs baseline: 6.5944x; 1.0423x over previous
#include <cuda_runtime.h>
#include <cuda_fp16.h>
#include <cstdint>

#define N_BATCH 2
#define SEQ     2048
#define EMB     1024
#define NHEAD   16
#define HDIM    64
#define MTOT    (N_BATCH*SEQ)   // 4096

// Scratch (allocation-free rule: __device__ globals), all fp16
__device__ __half h_query[(size_t)MTOT*EMB];
__device__ __half h_keys [(size_t)MTOT*EMB];
__device__ __half h_vals [(size_t)MTOT*EMB];
__device__ __half h_wq[(size_t)EMB*EMB];
__device__ __half h_wk[(size_t)EMB*EMB];
__device__ __half h_wv[(size_t)EMB*EMB];
__device__ __half h_wo[(size_t)EMB*EMB];
__device__ __half g_qh[(size_t)MTOT*EMB];
__device__ __half g_kh[(size_t)MTOT*EMB];
__device__ __half g_vh[(size_t)MTOT*EMB];
__device__ __half g_aoh[(size_t)MTOT*EMB];

__device__ __forceinline__ uint32_t pack_h2(float lo, float hi) {
    __half2 h = __floats2half2_rn(lo, hi);
    return *reinterpret_cast<uint32_t*>(&h);
}
__device__ __forceinline__ uint32_t smem_u32(const void* p) {
    uint32_t a;
    asm("{ .reg .u64 t; cvta.to.shared.u64 t, %1; cvt.u32.u64 %0, t; }"
        : "=r"(a) : "l"(p));
    return a;
}
__device__ __forceinline__ void cp16(uint32_t sm_dst, const void* g_src) {
    asm volatile("cp.async.cg.shared.global [%0], [%1], 16;"
                 :: "r"(sm_dst), "l"(g_src) : "memory");
}
#define CP_COMMIT() asm volatile("cp.async.commit_group;" ::: "memory")
#define CP_WAIT0()  asm volatile("cp.async.wait_group 0;" ::: "memory")
#define CP_WAIT1()  asm volatile("cp.async.wait_group 1;" ::: "memory")

__device__ __forceinline__ void mma_f16(
    float c[4], const uint32_t a[4], const uint32_t b[2])
{
    asm volatile(
        "mma.sync.aligned.m16n8k16.row.col.f32.f16.f16.f32 "
        "{%0,%1,%2,%3}, {%4,%5,%6,%7}, {%8,%9}, {%0,%1,%2,%3};"
        : "+f"(c[0]), "+f"(c[1]), "+f"(c[2]), "+f"(c[3])
        : "r"(a[0]), "r"(a[1]), "r"(a[2]), "r"(a[3]), "r"(b[0]), "r"(b[1]));
}

// ===========================================================================
// Fused fp32 -> fp16 converter: all 7 tensors in ONE launch.
// ===========================================================================
#define NA8 ((MTOT*EMB)/8)
#define NW8 ((EMB*EMB)/8)
#define NCVT (3*NA8 + 4*NW8)

__global__ __launch_bounds__(256) void cvt_all(
    const float* __restrict__ q, const float* __restrict__ k, const float* __restrict__ v,
    const float* __restrict__ wq, const float* __restrict__ wk,
    const float* __restrict__ wv, const float* __restrict__ wo,
    __half* __restrict__ dq, __half* __restrict__ dk, __half* __restrict__ dv,
    __half* __restrict__ dwq, __half* __restrict__ dwk,
    __half* __restrict__ dwv, __half* __restrict__ dwo)
{
    const int i = blockIdx.x * 256 + threadIdx.x;
    if (i >= NCVT) return;
    const float* s;
    __half* d;
    int off;
    if (i < 3 * NA8) {
        const int seg = i / NA8;
        off = i - seg * NA8;
        s = (seg == 0) ? q : (seg == 1) ? k : v;
        d = (seg == 0) ? dq : (seg == 1) ? dk : dv;
    } else {
        const int j = i - 3 * NA8;
        const int seg = j / NW8;
        off = j - seg * NW8;
        s = (seg == 0) ? wq : (seg == 1) ? wk : (seg == 2) ? wv : wo;
        d = (seg == 0) ? dwq : (seg == 1) ? dwk : (seg == 2) ? dwv : dwo;
    }
    const float4* sp = reinterpret_cast<const float4*>(s) + (size_t)off * 2;
    float4 a = sp[0], b = sp[1];
    reinterpret_cast<uint4*>(d)[off] =
        make_uint4(pack_h2(a.x,a.y), pack_h2(a.z,a.w),
                   pack_h2(b.x,b.y), pack_h2(b.z,b.w));
}

// ===========================================================================
// fp16 GEMM (fp32 accum): C = alpha * (A[M,K] @ B[N,K]^T + bias[N])
// (unchanged from R16: 3-stage cp.async, 256 thr / 8 warps, warp tile 64x32)
// ===========================================================================
#define GEMM_SMEM (3 * 2 * 2048 * 4)   // 49152 B

template<bool HALF_OUT>
__device__ __forceinline__ void gemm_body_h(
    const __half* __restrict__ A, const __half* __restrict__ B,
    const float* __restrict__ bias, void* __restrict__ Cv,
    int M, int N, int K, float alpha)
{
    extern __shared__ uint32_t gsm[];
    const uint32_t sbase = smem_u32(gsm);

    const int tid  = threadIdx.x;
    const int lane = tid & 31;
    const int wid  = tid >> 5;
    const int wm   = (wid & 1) * 64;
    const int wn   = (wid >> 1) * 32;
    const int m0 = blockIdx.y * 128;
    const int n0 = blockIdx.x * 128;

    const int lr = lane >> 2;
    const int lc = lane & 3;

    const int srow = tid >> 2;
    const int sch  = tid & 3;

    float acc[4][4][4];
    #pragma unroll
    for (int i = 0; i < 4; i++)
        #pragma unroll
        for (int j = 0; j < 4; j++)
            #pragma unroll
            for (int r = 0; r < 4; r++) acc[i][j][r] = 0.f;

    auto swoff = [](int row, int ch) -> uint32_t {
        return (uint32_t)(row * 16 + (((ch ^ ((row >> 1) & 3)) & 3) << 2));
    };

    auto stage = [&](int buf, int kc) {
        const int koff = kc * 32 + sch * 8;
        #pragma unroll
        for (int i = 0; i < 2; i++) {
            const int row = srow + i * 64;
            const uint32_t so = swoff(row, sch);
            cp16(sbase + (buf * 2048 + so) * 4,
                 A + (size_t)(m0 + row) * K + koff);
            cp16(sbase + (6144 + buf * 2048 + so) * 4,
                 B + (size_t)(n0 + row) * K + koff);
        }
        CP_COMMIT();
    };

    const int nk = K / 32;
    stage(0, 0);
    if (nk > 1) stage(1, 1);
    CP_WAIT1();
    __syncthreads();

    for (int kc = 0; kc < nk; kc++) {
        const int buf = kc % 3;
        if (kc + 2 < nk) stage((kc + 2) % 3, kc + 2);

        const uint32_t* Ab = gsm + buf * 2048;
        const uint32_t* Bb = gsm + 6144 + buf * 2048;

        #pragma unroll
        for (int s = 0; s < 2; s++) {
            uint32_t af[4][4], bf[4][2];
            #pragma unroll
            for (int i = 0; i < 4; i++) {
                const int row = wm + i * 16 + lr;
                const uint32_t g = (uint32_t)((row >> 1) & 3);
                const uint32_t x0 = (((uint32_t)(2*s)     ^ g) & 3) << 2;
                const uint32_t x1 = (((uint32_t)(2*s + 1) ^ g) & 3) << 2;
                const uint32_t ra = (uint32_t)row * 16;
                af[i][0] = Ab[ra       + x0 + lc];
                af[i][1] = Ab[ra + 128 + x0 + lc];
                af[i][2] = Ab[ra       + x1 + lc];
                af[i][3] = Ab[ra + 128 + x1 + lc];
            }
            #pragma unroll
            for (int j = 0; j < 4; j++) {
                const int row = wn + j * 8 + lr;
                const uint32_t g = (uint32_t)((row >> 1) & 3);
                const uint32_t x0 = (((uint32_t)(2*s)     ^ g) & 3) << 2;
                const uint32_t x1 = (((uint32_t)(2*s + 1) ^ g) & 3) << 2;
                const uint32_t rb = (uint32_t)row * 16;
                bf[j][0] = Bb[rb + x0 + lc];
                bf[j][1] = Bb[rb + x1 + lc];
            }
            #pragma unroll
            for (int i = 0; i < 4; i++)
                #pragma unroll
                for (int j = 0; j < 4; j++)
                    mma_f16(acc[i][j], af[i], bf[j]);
        }

        if (kc + 1 < nk) CP_WAIT1();
        __syncthreads();
    }

    #pragma unroll
    for (int j = 0; j < 4; j++) {
        const int col = n0 + wn + j * 8 + lc * 2;
        const float b0 = bias[col], b1 = bias[col + 1];
        #pragma unroll
        for (int i = 0; i < 4; i++) {
            const int row = m0 + wm + i * 16 + lr;
            const float o00 = alpha * (acc[i][j][0] + b0);
            const float o01 = alpha * (acc[i][j][1] + b1);
            const float o10 = alpha * (acc[i][j][2] + b0);
            const float o11 = alpha * (acc[i][j][3] + b1);
            if (HALF_OUT) {
                __half* C = reinterpret_cast<__half*>(Cv);
                *reinterpret_cast<uint32_t*>(&C[(size_t)row * N + col]) =
                    pack_h2(o00, o01);
                *reinterpret_cast<uint32_t*>(&C[(size_t)(row + 8) * N + col]) =
                    pack_h2(o10, o11);
            } else {
                float* C = reinterpret_cast<float*>(Cv);
                *reinterpret_cast<float2*>(&C[(size_t)row * N + col]) =
                    make_float2(o00, o01);
                *reinterpret_cast<float2*>(&C[(size_t)(row + 8) * N + col]) =
                    make_float2(o10, o11);
            }
        }
    }
}

__global__ __launch_bounds__(256, 2) void gemm_qkv_h(
    const __half* __restrict__ Aq, const __half* __restrict__ Ak, const __half* __restrict__ Av,
    const __half* __restrict__ Wq, const __half* __restrict__ Wk, const __half* __restrict__ Wv,
    const float* __restrict__ bq, const float* __restrict__ bk, const float* __restrict__ bv,
    __half* __restrict__ Cq, __half* __restrict__ Ck, __half* __restrict__ Cv)
{
    const int z = blockIdx.z;
    const __half* A = (z == 0) ? Aq : (z == 1) ? Ak : Av;
    const __half* W = (z == 0) ? Wq : (z == 1) ? Wk : Wv;
    const float*  b = (z == 0) ? bq : (z == 1) ? bk : bv;
    __half*       C = (z == 0) ? Cq : (z == 1) ? Ck : Cv;
    const float alpha = (z == 0) ? 0.03125f : 1.0f;
    gemm_body_h<true>(A, W, b, C, MTOT, EMB, EMB, alpha);
}

__global__ __launch_bounds__(256, 2) void gemm_out_h(
    const __half* __restrict__ A, const __half* __restrict__ B,
    const float* __restrict__ bias, float* __restrict__ C)
{
    gemm_body_h<false>(A, B, bias, C, MTOT, EMB, EMB, 1.0f);
}

// ===========================================================================
// Flash attention, causal — R17: software-pipelined staging.
// K tile: cp.async double-buffer. V tile: register prefetch (LDG before
// compute), byte_perm pack + STS after compute. ONE barrier per k-tile.
// All-fp16 MMAs as in R16. Smem 47104 B -> 3 CTAs/SM.
// ===========================================================================
#define QSTR 36
#define VPSTR 72
#define PSTR 20
#define BKT  32
#define ATTN_SMEM ((128*QSTR + 2*BKT*QSTR + 2*16*VPSTR + 128*PSTR) * 4)  // 47104

__global__ __launch_bounds__(128, 3) void attn_mma(
    const __half* __restrict__ Q, const __half* __restrict__ K,
    const __half* __restrict__ V, __half* __restrict__ O)
{
    extern __shared__ uint32_t sm[];
    uint32_t (*Qs)[QSTR]  = reinterpret_cast<uint32_t(*)[QSTR]>(sm);
    uint32_t (*Ks)[QSTR]  = reinterpret_cast<uint32_t(*)[QSTR]>(sm + 128*QSTR);          // [2*32][36]
    uint32_t (*Vp)[VPSTR] = reinterpret_cast<uint32_t(*)[VPSTR]>(sm + 128*QSTR + 2*BKT*QSTR); // [2*16][72]
    uint32_t (*Ps)[PSTR]  = reinterpret_cast<uint32_t(*)[PSTR]>(sm + 128*QSTR + 2*BKT*QSTR + 2*16*VPSTR);

    const int tid  = threadIdx.x;
    const int lane = tid & 31;
    const int wid  = tid >> 5;
    const int lr   = lane >> 2;
    const int lc   = lane & 3;
    const int wq   = wid * 32;

    const int q0 = (gridDim.x - 1 - blockIdx.x) * 128;   // heavy tiles first
    const int h  = blockIdx.y;
    const int nb = blockIdx.z;

    const __half* qbase = Q + (size_t)nb * SEQ * EMB + h * HDIM;
    const __half* kbase = K + (size_t)nb * SEQ * EMB + h * HDIM;
    const __half* vbase = V + (size_t)nb * SEQ * EMB + h * HDIM;

    const uint32_t ksb = smem_u32(&Ks[0][0]);

    // per-thread staging coords
    const int krow = tid >> 3, kcw = tid & 7;      // K: row 0..15 (+16), chunk
    const int vkp  = tid >> 3, vdc = tid & 7;      // V: key-pair 0..15, d-chunk

    auto stageK = [&](int buf, int kb) {
        #pragma unroll
        for (int i = 0; i < 2; i++) {
            const int row = krow + i * 16;
            cp16(ksb + ((buf * 32 + row) * QSTR + kcw * 4) * 4,
                 &kbase[(size_t)(kb + row) * EMB + kcw * 8]);
        }
        CP_COMMIT();
    };
    uint4 va, vb;
    auto vload = [&](int kb) {
        va = *reinterpret_cast<const uint4*>(&vbase[(size_t)(kb + 2*vkp)     * EMB + vdc * 8]);
        vb = *reinterpret_cast<const uint4*>(&vbase[(size_t)(kb + 2*vkp + 1) * EMB + vdc * 8]);
    };
    auto vstore = [&](int buf) {
        uint32_t* d = &Vp[buf * 16 + vkp][vdc * 8];
        *reinterpret_cast<uint4*>(d) = make_uint4(
            __byte_perm(va.x, vb.x, 0x5410), __byte_perm(va.x, vb.x, 0x7632),
            __byte_perm(va.y, vb.y, 0x5410), __byte_perm(va.y, vb.y, 0x7632));
        *reinterpret_cast<uint4*>(d + 4) = make_uint4(
            __byte_perm(va.z, vb.z, 0x5410), __byte_perm(va.z, vb.z, 0x7632),
            __byte_perm(va.w, vb.w, 0x5410), __byte_perm(va.w, vb.w, 0x7632));
    };

    // ---- load Q tile (plain copies) + prologue staging of tile 0 ----
    stageK(0, 0);
    vload(0);
    #pragma unroll
    for (int i = 0; i < 8; i++) {
        const int idx = tid + i * 128;
        const int row = idx >> 3, cw = idx & 7;
        *reinterpret_cast<uint4*>(&Qs[row][cw * 4]) =
            *reinterpret_cast<const uint4*>(&qbase[(size_t)(q0 + row) * EMB + cw * 8]);
    }
    CP_WAIT0();
    vstore(0);
    __syncthreads();

    float mrow[2][2], lsum[2][2];
    #pragma unroll
    for (int t = 0; t < 2; t++) {
        mrow[t][0] = -1e30f; mrow[t][1] = -1e30f;
        lsum[t][0] = 0.f;    lsum[t][1] = 0.f;
    }
    float oacc[2][8][4];
    #pragma unroll
    for (int t = 0; t < 2; t++)
        #pragma unroll
        for (int j = 0; j < 8; j++)
            #pragma unroll
            for (int r = 0; r < 4; r++) oacc[t][j][r] = 0.f;

    const int nkt = (q0 + 128) / BKT;
    for (int kt = 0; kt < nkt; kt++) {
        const int kb = kt * BKT;
        const int buf = kt & 1;
        const bool more = (kt + 1 < nkt);

        if (more) {               // prefetch tile kt+1 (into the dead buffer)
            stageK(buf ^ 1, kb + BKT);
            vload(kb + BKT);
        }

        if (kb <= q0 + wq + 31) {
            // ---- S = Q . K^T ----
            float sacc[2][4][4];
            #pragma unroll
            for (int t = 0; t < 2; t++)
                #pragma unroll
                for (int j = 0; j < 4; j++)
                    #pragma unroll
                    for (int r = 0; r < 4; r++) sacc[t][j][r] = 0.f;

            #pragma unroll
            for (int s = 0; s < 4; s++) {
                uint32_t af[2][4];
                #pragma unroll
                for (int t = 0; t < 2; t++) {
                    const int mr = wq + t * 16 + lr;
                    af[t][0] = Qs[mr    ][s*8 + lc    ];
                    af[t][1] = Qs[mr + 8][s*8 + lc    ];
                    af[t][2] = Qs[mr    ][s*8 + lc + 4];
                    af[t][3] = Qs[mr + 8][s*8 + lc + 4];
                }
                #pragma unroll
                for (int j = 0; j < 4; j++) {
                    uint32_t bf[2];
                    bf[0] = Ks[buf*32 + j*8 + lr][s*8 + lc    ];
                    bf[1] = Ks[buf*32 + j*8 + lr][s*8 + lc + 4];
                    mma_f16(sacc[0][j], af[0], bf);
                    mma_f16(sacc[1][j], af[1], bf);
                }
            }

            // ---- causal mask ----
            if (kb + BKT - 1 > q0 + wq) {
                #pragma unroll
                for (int t = 0; t < 2; t++) {
                    const int r0 = q0 + wq + t*16 + lr, r1 = r0 + 8;
                    #pragma unroll
                    for (int j = 0; j < 4; j++) {
                        const int c0 = kb + j*8 + 2*lc, c1 = c0 + 1;
                        if (c0 > r0) sacc[t][j][0] = -1e30f;
                        if (c1 > r0) sacc[t][j][1] = -1e30f;
                        if (c0 > r1) sacc[t][j][2] = -1e30f;
                        if (c1 > r1) sacc[t][j][3] = -1e30f;
                    }
                }
            }

            // ---- online softmax ----
            #pragma unroll
            for (int t = 0; t < 2; t++) {
                float mt0 = -1e30f, mt1 = -1e30f;
                #pragma unroll
                for (int j = 0; j < 4; j++) {
                    mt0 = fmaxf(mt0, fmaxf(sacc[t][j][0], sacc[t][j][1]));
                    mt1 = fmaxf(mt1, fmaxf(sacc[t][j][2], sacc[t][j][3]));
                }
                mt0 = fmaxf(mt0, __shfl_xor_sync(0xffffffffu, mt0, 1));
                mt0 = fmaxf(mt0, __shfl_xor_sync(0xffffffffu, mt0, 2));
                mt1 = fmaxf(mt1, __shfl_xor_sync(0xffffffffu, mt1, 1));
                mt1 = fmaxf(mt1, __shfl_xor_sync(0xffffffffu, mt1, 2));

                const float mn0 = fmaxf(mrow[t][0], mt0);
                const float mn1 = fmaxf(mrow[t][1], mt1);
                const float cor0 = __expf(mrow[t][0] - mn0);
                const float cor1 = __expf(mrow[t][1] - mn1);
                mrow[t][0] = mn0; mrow[t][1] = mn1;

                float ls0 = 0.f, ls1 = 0.f;
                #pragma unroll
                for (int j = 0; j < 4; j++) {
                    sacc[t][j][0] = __expf(sacc[t][j][0] - mn0);
                    sacc[t][j][1] = __expf(sacc[t][j][1] - mn0);
                    sacc[t][j][2] = __expf(sacc[t][j][2] - mn1);
                    sacc[t][j][3] = __expf(sacc[t][j][3] - mn1);
                    ls0 += sacc[t][j][0] + sacc[t][j][1];
                    ls1 += sacc[t][j][2] + sacc[t][j][3];
                }
                ls0 += __shfl_xor_sync(0xffffffffu, ls0, 1);
                ls0 += __shfl_xor_sync(0xffffffffu, ls0, 2);
                ls1 += __shfl_xor_sync(0xffffffffu, ls1, 1);
                ls1 += __shfl_xor_sync(0xffffffffu, ls1, 2);
                lsum[t][0] = lsum[t][0] * cor0 + ls0;
                lsum[t][1] = lsum[t][1] * cor1 + ls1;

                #pragma unroll
                for (int j = 0; j < 8; j++) {
                    oacc[t][j][0] *= cor0; oacc[t][j][1] *= cor0;
                    oacc[t][j][2] *= cor1; oacc[t][j][3] *= cor1;
                }
            }

            // ---- stage P as fp16 pair-words (warp-private rows) ----
            #pragma unroll
            for (int t = 0; t < 2; t++) {
                const int mr = wq + t * 16 + lr;
                #pragma unroll
                for (int j = 0; j < 4; j++) {
                    Ps[mr    ][j*4 + lc] = pack_h2(sacc[t][j][0], sacc[t][j][1]);
                    Ps[mr + 8][j*4 + lc] = pack_h2(sacc[t][j][2], sacc[t][j][3]);
                }
            }
            __syncwarp();

            // ---- O += P . V ----
            #pragma unroll
            for (int s = 0; s < 2; s++) {
                uint32_t af[2][4];
                #pragma unroll
                for (int t = 0; t < 2; t++) {
                    const int mr = wq + t * 16 + lr;
                    af[t][0] = Ps[mr    ][s*8 + lc    ];
                    af[t][1] = Ps[mr + 8][s*8 + lc    ];
                    af[t][2] = Ps[mr    ][s*8 + lc + 4];
                    af[t][3] = Ps[mr + 8][s*8 + lc + 4];
                }
                #pragma unroll
                for (int j = 0; j < 8; j++) {
                    uint32_t bf[2];
                    bf[0] = Vp[buf*16 + s*8 + lc    ][j*8 + lr];
                    bf[1] = Vp[buf*16 + s*8 + lc + 4][j*8 + lr];
                    mma_f16(oacc[0][j], af[0], bf);
                    mma_f16(oacc[1][j], af[1], bf);
                }
            }
            __syncwarp();
        }

        if (more) {
            CP_WAIT0();           // K tile kt+1 landed
            vstore(buf ^ 1);      // V tile kt+1 packed into smem
        }
        __syncthreads();          // one barrier per tile
    }

    // ---- epilogue: normalize, write fp16 [n, q, h*64 + d] ----
    #pragma unroll
    for (int t = 0; t < 2; t++) {
        const float inv0 = 1.f / lsum[t][0];
        const float inv1 = 1.f / lsum[t][1];
        const size_t row0 = (size_t)nb * SEQ + q0 + wq + t*16 + lr;
        const size_t row1 = row0 + 8;
        #pragma unroll
        for (int j = 0; j < 8; j++) {
            const int col = h * HDIM + j*8 + 2*lc;
            *reinterpret_cast<uint32_t*>(&O[row0 * EMB + col]) =
                pack_h2(oacc[t][j][0] * inv0, oacc[t][j][1] * inv0);
            *reinterpret_cast<uint32_t*>(&O[row1 * EMB + col]) =
                pack_h2(oacc[t][j][2] * inv1, oacc[t][j][3] * inv1);
        }
    }
}

// ---------------------------------------------------------------------------
// Inputs: 0 values, 1 keys, 2 query, 3 mask(unused), 4 Wv, 5 bv, 6 Wk, 7 bk,
//         8 Wq, 9 bq, 10 Wo, 11 bo
// ---------------------------------------------------------------------------
extern "C" void kernel_launch(void* const* d_in, const int* in_sizes, int n_in,
                              void* d_out, int out_size)
{
    const float* values = (const float*)d_in[0];
    const float* keys   = (const float*)d_in[1];
    const float* query  = (const float*)d_in[2];
    const float* Wv = (const float*)d_in[4];
    const float* bv = (const float*)d_in[5];
    const float* Wk = (const float*)d_in[6];
    const float* bk = (const float*)d_in[7];
    const float* Wq = (const float*)d_in[8];
    const float* bq = (const float*)d_in[9];
    const float* Wo = (const float*)d_in[10];
    const float* bo = (const float*)d_in[11];
    float* out = (float*)d_out;

    __half *pQ, *pK, *pV, *pWq, *pWk, *pWv, *pWo, *pqh, *pkh, *pvh, *pah;
    cudaGetSymbolAddress((void**)&pQ,  h_query);
    cudaGetSymbolAddress((void**)&pK,  h_keys);
    cudaGetSymbolAddress((void**)&pV,  h_vals);
    cudaGetSymbolAddress((void**)&pWq, h_wq);
    cudaGetSymbolAddress((void**)&pWk, h_wk);
    cudaGetSymbolAddress((void**)&pWv, h_wv);
    cudaGetSymbolAddress((void**)&pWo, h_wo);
    cudaGetSymbolAddress((void**)&pqh, g_qh);
    cudaGetSymbolAddress((void**)&pkh, g_kh);
    cudaGetSymbolAddress((void**)&pvh, g_vh);
    cudaGetSymbolAddress((void**)&pah, g_aoh);

    cudaFuncSetAttribute(attn_mma,
                         cudaFuncAttributeMaxDynamicSharedMemorySize, ATTN_SMEM);
    cudaFuncSetAttribute(gemm_qkv_h,
                         cudaFuncAttributeMaxDynamicSharedMemorySize, GEMM_SMEM);
    cudaFuncSetAttribute(gemm_out_h,
                         cudaFuncAttributeMaxDynamicSharedMemorySize, GEMM_SMEM);

    // Fused fp32 -> fp16 conversion: one launch for all 7 tensors
    cvt_all<<<(NCVT + 255) / 256, 256>>>(query, keys, values,
                                         Wq, Wk, Wv, Wo,
                                         pQ, pK, pV, pWq, pWk, pWv, pWo);

    // Fused Q/K/V projections: 8 x 32 x 3 = 768 CTAs
    dim3 gqkv(EMB / 128, MTOT / 128, 3);
    gemm_qkv_h<<<gqkv, 256, GEMM_SMEM>>>(pQ, pK, pV,
                                         pWq, pWk, pWv, bq, bk, bv,
                                         pqh, pkh, pvh);

    dim3 gattn(SEQ / 128, NHEAD, N_BATCH);  // 16 x 16 x 2 = 512 blocks
    attn_mma<<<gattn, 128, ATTN_SMEM>>>(pqh, pkh, pvh, pah);

    dim3 gproj(EMB / 128, MTOT / 128);
    gemm_out_h<<<gproj, 256, GEMM_SMEM>>>(pah, pWo, bo, out);
}